// round 1
// baseline (speedup 1.0000x reference)
#include <cuda_runtime.h>
#include <math.h>

#define T_TOK 2048
#define SEQ   1024
#define BATCH 2
#define HID   768
#define NHEAD 12
#define HDIM  64
#define NLAYER 12
#define FFI   3072
#define VOCAB 50257

// ---------------- scratch (device globals: allocation-free) ----------------
__device__ float g_x[T_TOK * HID];
__device__ float g_h[T_TOK * HID];
__device__ float g_q[T_TOK * HID];
__device__ float g_k[T_TOK * HID];
__device__ float g_v[T_TOK * HID];
__device__ float g_a[T_TOK * HID];
__device__ float g_ff[T_TOK * FFI];

// ---------------- embeddings ----------------
__global__ void embed_kernel(const int* __restrict__ ids,
                             const float* __restrict__ tok,
                             const float* __restrict__ pos,
                             float* __restrict__ x) {
    int idx = blockIdx.x * blockDim.x + threadIdx.x;
    if (idx >= T_TOK * HID) return;
    int t = idx / HID;
    int hh = idx - t * HID;
    int s = t % SEQ;
    int id = ids[t];
    x[idx] = tok[(size_t)id * HID + hh] + pos[(size_t)s * HID + hh];
}

// ---------------- layernorm (one block per row) ----------------
__global__ void layernorm_kernel(const float* __restrict__ x,
                                 const float* __restrict__ w,
                                 const float* __restrict__ b,
                                 float* __restrict__ out) {
    int row = blockIdx.x;
    const float* xr = x + (size_t)row * HID;
    float* orow = out + (size_t)row * HID;
    __shared__ float red[32];
    int tid = threadIdx.x, lane = tid & 31, wid = tid >> 5;
    int nwarp = blockDim.x >> 5;

    float s = 0.f;
    for (int i = tid; i < HID; i += blockDim.x) s += xr[i];
    #pragma unroll
    for (int o = 16; o > 0; o >>= 1) s += __shfl_xor_sync(0xffffffffu, s, o);
    if (lane == 0) red[wid] = s;
    __syncthreads();
    float tot = 0.f;
    if (tid < nwarp) tot = red[tid];
    if (wid == 0) {
        #pragma unroll
        for (int o = 16; o > 0; o >>= 1) tot += __shfl_xor_sync(0xffffffffu, tot, o);
        if (lane == 0) red[0] = tot;
    }
    __syncthreads();
    float mean = red[0] / (float)HID;
    __syncthreads();

    float vs = 0.f;
    for (int i = tid; i < HID; i += blockDim.x) {
        float d = xr[i] - mean;
        vs += d * d;
    }
    #pragma unroll
    for (int o = 16; o > 0; o >>= 1) vs += __shfl_xor_sync(0xffffffffu, vs, o);
    if (lane == 0) red[wid] = vs;
    __syncthreads();
    float vt = 0.f;
    if (tid < nwarp) vt = red[tid];
    if (wid == 0) {
        #pragma unroll
        for (int o = 16; o > 0; o >>= 1) vt += __shfl_xor_sync(0xffffffffu, vt, o);
        if (lane == 0) red[0] = vt;
    }
    __syncthreads();
    float inv = rsqrtf(red[0] / (float)HID + 1e-5f);

    for (int i = tid; i < HID; i += blockDim.x)
        orow[i] = (xr[i] - mean) * inv * w[i] + b[i];
}

// ---------------- GEMM: C[M,N] = A[M,K] * W[N,K]^T (+bias)(+res) ----------------
// 64x64 tile, 256 threads, 4x4 per thread, K-tile 16. K % 16 == 0 required.
__global__ void gemm_tn(const float* __restrict__ A,
                        const float* __restrict__ W,
                        const float* __restrict__ bias,
                        const float* __restrict__ res,
                        float* __restrict__ C,
                        int M, int N, int K) {
    __shared__ float As[16][68];
    __shared__ float Bs[16][68];
    int m0 = blockIdx.y * 64;
    int n0 = blockIdx.x * 64;
    int tid = threadIdx.x;
    int tx = tid & 15, ty = tid >> 4;
    int lrow = tid >> 2;          // 0..63
    int lcol = (tid & 3) << 2;    // 0,4,8,12

    float acc[4][4];
    #pragma unroll
    for (int i = 0; i < 4; i++)
        #pragma unroll
        for (int j = 0; j < 4; j++) acc[i][j] = 0.f;

    for (int k0 = 0; k0 < K; k0 += 16) {
        int m = m0 + lrow;
        float4 va = make_float4(0.f, 0.f, 0.f, 0.f);
        if (m < M) va = *reinterpret_cast<const float4*>(&A[(size_t)m * K + k0 + lcol]);
        As[lcol + 0][lrow] = va.x;
        As[lcol + 1][lrow] = va.y;
        As[lcol + 2][lrow] = va.z;
        As[lcol + 3][lrow] = va.w;

        int n = n0 + lrow;
        float4 vb = make_float4(0.f, 0.f, 0.f, 0.f);
        if (n < N) vb = *reinterpret_cast<const float4*>(&W[(size_t)n * K + k0 + lcol]);
        Bs[lcol + 0][lrow] = vb.x;
        Bs[lcol + 1][lrow] = vb.y;
        Bs[lcol + 2][lrow] = vb.z;
        Bs[lcol + 3][lrow] = vb.w;
        __syncthreads();

        #pragma unroll
        for (int kk = 0; kk < 16; kk++) {
            float a[4], bb[4];
            #pragma unroll
            for (int i = 0; i < 4; i++) a[i] = As[kk][ty + 16 * i];
            #pragma unroll
            for (int j = 0; j < 4; j++) bb[j] = Bs[kk][tx + 16 * j];
            #pragma unroll
            for (int i = 0; i < 4; i++)
                #pragma unroll
                for (int j = 0; j < 4; j++) acc[i][j] += a[i] * bb[j];
        }
        __syncthreads();
    }

    #pragma unroll
    for (int i = 0; i < 4; i++) {
        int m = m0 + ty + 16 * i;
        if (m >= M) continue;
        #pragma unroll
        for (int j = 0; j < 4; j++) {
            int n = n0 + tx + 16 * j;
            if (n >= N) continue;
            float val = acc[i][j];
            if (bias) val += bias[n];
            if (res) val += res[(size_t)m * N + n];
            C[(size_t)m * N + n] = val;
        }
    }
}

// ---------------- GELU (exact erf) ----------------
__global__ void gelu_kernel(float* __restrict__ x, int n) {
    int idx = blockIdx.x * blockDim.x + threadIdx.x;
    if (idx >= n) return;
    float v = x[idx];
    x[idx] = 0.5f * v * (1.0f + erff(v * 0.70710678118654752f));
}

// ---------------- fused attention: one block per (query i, head, batch) ----------------
__global__ void attn_kernel(const float* __restrict__ q,
                            const float* __restrict__ k,
                            const float* __restrict__ v,
                            const int* __restrict__ amask,
                            float* __restrict__ out) {
    int i = blockIdx.x;
    int hh = blockIdx.y;
    int b = blockIdx.z;
    int tid = threadIdx.x; // 256 threads
    const float scale = 0.125f; // 1/sqrt(64)

    __shared__ float sc[SEQ];
    __shared__ float qv[HDIM];
    __shared__ float red[32];
    __shared__ float av[4][HDIM];

    size_t qoff = ((size_t)(b * SEQ + i)) * HID + hh * HDIM;
    if (tid < HDIM) qv[tid] = q[qoff + tid] * scale;
    __syncthreads();

    // scores over j in [0, i]
    for (int j = tid; j <= i; j += blockDim.x) {
        const float* kr = k + ((size_t)(b * SEQ + j)) * HID + hh * HDIM;
        float s = 0.f;
        #pragma unroll
        for (int d = 0; d < HDIM; d += 4) {
            float4 kk4 = *reinterpret_cast<const float4*>(&kr[d]);
            s += qv[d] * kk4.x + qv[d + 1] * kk4.y + qv[d + 2] * kk4.z + qv[d + 3] * kk4.w;
        }
        if (amask[b * SEQ + j] == 0) s = -1e9f;
        sc[j] = s;
    }
    __syncthreads();

    // max reduce
    int lane = tid & 31, wid = tid >> 5;
    float mx = -1e30f;
    for (int j = tid; j <= i; j += blockDim.x) mx = fmaxf(mx, sc[j]);
    #pragma unroll
    for (int o = 16; o > 0; o >>= 1) mx = fmaxf(mx, __shfl_xor_sync(0xffffffffu, mx, o));
    if (lane == 0) red[wid] = mx;
    __syncthreads();
    float m2 = (tid < 8) ? red[tid] : -1e30f;
    if (wid == 0) {
        #pragma unroll
        for (int o = 4; o > 0; o >>= 1) m2 = fmaxf(m2, __shfl_xor_sync(0xffffffffu, m2, o));
        if (lane == 0) red[0] = m2;
    }
    __syncthreads();
    float rowmax = red[0];
    __syncthreads();

    // exp + sum
    float sum = 0.f;
    for (int j = tid; j <= i; j += blockDim.x) {
        float e = expf(sc[j] - rowmax);
        sc[j] = e;
        sum += e;
    }
    #pragma unroll
    for (int o = 16; o > 0; o >>= 1) sum += __shfl_xor_sync(0xffffffffu, sum, o);
    if (lane == 0) red[wid] = sum;
    __syncthreads();
    float s2 = (tid < 8) ? red[tid] : 0.f;
    if (wid == 0) {
        #pragma unroll
        for (int o = 4; o > 0; o >>= 1) s2 += __shfl_xor_sync(0xffffffffu, s2, o);
        if (lane == 0) red[0] = s2;
    }
    __syncthreads();
    float inv = 1.0f / red[0];

    // AV: 256 threads = 64 dims x 4 j-groups
    int d = tid & 63, grp = tid >> 6;
    float acc = 0.f;
    for (int j = grp; j <= i; j += 4)
        acc += sc[j] * v[((size_t)(b * SEQ + j)) * HID + hh * HDIM + d];
    av[grp][d] = acc;
    __syncthreads();
    if (grp == 0) {
        float r = av[0][d] + av[1][d] + av[2][d] + av[3][d];
        out[qoff + d] = r * inv;
    }
}

// ---------------- launcher ----------------
extern "C" void kernel_launch(void* const* d_in, const int* in_sizes, int n_in,
                              void* d_out, int out_size) {
    const int*   input_ids = (const int*)d_in[0];
    const int*   attn_mask = (const int*)d_in[1];
    const float* tok_emb   = (const float*)d_in[2];
    const float* pos_emb   = (const float*)d_in[3];
    const float* ln1_w     = (const float*)d_in[4];
    const float* ln1_b     = (const float*)d_in[5];
    const float* qw        = (const float*)d_in[6];
    const float* kw        = (const float*)d_in[7];
    const float* vw        = (const float*)d_in[8];
    const float* ow        = (const float*)d_in[9];
    const float* ob        = (const float*)d_in[10];
    const float* ln2_w     = (const float*)d_in[11];
    const float* ln2_b     = (const float*)d_in[12];
    const float* w1        = (const float*)d_in[13];
    const float* b1        = (const float*)d_in[14];
    const float* w2        = (const float*)d_in[15];
    const float* b2        = (const float*)d_in[16];
    const float* lnf_w     = (const float*)d_in[17];
    const float* lnf_b     = (const float*)d_in[18];
    const float* lm_w      = (const float*)d_in[19];
    float* out = (float*)d_out;

    float *x, *h, *q, *k, *v, *a, *ff;
    cudaGetSymbolAddress((void**)&x,  g_x);
    cudaGetSymbolAddress((void**)&h,  g_h);
    cudaGetSymbolAddress((void**)&q,  g_q);
    cudaGetSymbolAddress((void**)&k,  g_k);
    cudaGetSymbolAddress((void**)&v,  g_v);
    cudaGetSymbolAddress((void**)&a,  g_a);
    cudaGetSymbolAddress((void**)&ff, g_ff);

    // embeddings
    {
        int n = T_TOK * HID;
        embed_kernel<<<(n + 255) / 256, 256>>>(input_ids, tok_emb, pos_emb, x);
    }

    dim3 gqkv((HID + 63) / 64, (T_TOK + 63) / 64);
    dim3 gff1((FFI + 63) / 64, (T_TOK + 63) / 64);
    dim3 gff2((HID + 63) / 64, (T_TOK + 63) / 64);
    dim3 gattn(SEQ, NHEAD, BATCH);

    for (int l = 0; l < NLAYER; l++) {
        const float* l1w = ln1_w + (size_t)l * HID;
        const float* l1b = ln1_b + (size_t)l * HID;
        const float* qwl = qw + (size_t)l * HID * HID;
        const float* kwl = kw + (size_t)l * HID * HID;
        const float* vwl = vw + (size_t)l * HID * HID;
        const float* owl = ow + (size_t)l * HID * HID;
        const float* obl = ob + (size_t)l * HID;
        const float* l2w = ln2_w + (size_t)l * HID;
        const float* l2b = ln2_b + (size_t)l * HID;
        const float* w1l = w1 + (size_t)l * FFI * HID;
        const float* b1l = b1 + (size_t)l * FFI;
        const float* w2l = w2 + (size_t)l * HID * FFI;
        const float* b2l = b2 + (size_t)l * HID;

        layernorm_kernel<<<T_TOK, 256>>>(x, l1w, l1b, h);
        gemm_tn<<<gqkv, 256>>>(h, qwl, nullptr, nullptr, q, T_TOK, HID, HID);
        gemm_tn<<<gqkv, 256>>>(h, kwl, nullptr, nullptr, k, T_TOK, HID, HID);
        gemm_tn<<<gqkv, 256>>>(h, vwl, nullptr, nullptr, v, T_TOK, HID, HID);
        attn_kernel<<<gattn, 256>>>(q, k, v, attn_mask, a);
        gemm_tn<<<gqkv, 256>>>(a, owl, obl, x, x, T_TOK, HID, HID);

        layernorm_kernel<<<T_TOK, 256>>>(x, l2w, l2b, h);
        gemm_tn<<<gff1, 256>>>(h, w1l, b1l, nullptr, ff, T_TOK, FFI, HID);
        {
            int n = T_TOK * FFI;
            gelu_kernel<<<(n + 255) / 256, 256>>>(ff, n);
        }
        gemm_tn<<<gff2, 256>>>(ff, w2l, b2l, x, x, T_TOK, HID, FFI);
    }

    // final LN + lm_head
    layernorm_kernel<<<T_TOK, 256>>>(x, lnf_w, lnf_b, h);
    dim3 glm((VOCAB + 63) / 64, (T_TOK + 63) / 64);
    gemm_tn<<<glm, 256>>>(h, lm_w, nullptr, nullptr, out, T_TOK, VOCAB, HID);
}

// round 3
// speedup vs baseline: 1.1523x; 1.1523x over previous
#include <cuda_runtime.h>
#include <math.h>

#define T_TOK 2048
#define SEQ   1024
#define BATCH 2
#define HID   768
#define NHEAD 12
#define HDIM  64
#define NLAYER 12
#define FFI   3072
#define VOCAB 50257

// ---------------- scratch (device globals: allocation-free) ----------------
__device__ float g_x[T_TOK * HID];
__device__ float g_h[T_TOK * HID];
__device__ float g_q[T_TOK * HID];
__device__ float g_k[T_TOK * HID];
__device__ float g_v[T_TOK * HID];
__device__ float g_a[T_TOK * HID];
__device__ float g_ff[T_TOK * FFI];

// ---------------- embeddings ----------------
__global__ void embed_kernel(const int* __restrict__ ids,
                             const float* __restrict__ tok,
                             const float* __restrict__ pos,
                             float* __restrict__ x) {
    int idx = blockIdx.x * blockDim.x + threadIdx.x;
    if (idx >= T_TOK * HID) return;
    int t = idx / HID;
    int hh = idx - t * HID;
    int s = t % SEQ;
    int id = ids[t];
    x[idx] = tok[(size_t)id * HID + hh] + pos[(size_t)s * HID + hh];
}

// ---------------- layernorm (one block per row) ----------------
__global__ void layernorm_kernel(const float* __restrict__ x,
                                 const float* __restrict__ w,
                                 const float* __restrict__ b,
                                 float* __restrict__ out) {
    int row = blockIdx.x;
    const float* xr = x + (size_t)row * HID;
    float* orow = out + (size_t)row * HID;
    __shared__ float red[32];
    int tid = threadIdx.x, lane = tid & 31, wid = tid >> 5;
    int nwarp = blockDim.x >> 5;

    float s = 0.f;
    for (int i = tid; i < HID; i += blockDim.x) s += xr[i];
    #pragma unroll
    for (int o = 16; o > 0; o >>= 1) s += __shfl_xor_sync(0xffffffffu, s, o);
    if (lane == 0) red[wid] = s;
    __syncthreads();
    float tot = 0.f;
    if (tid < nwarp) tot = red[tid];
    if (wid == 0) {
        #pragma unroll
        for (int o = 16; o > 0; o >>= 1) tot += __shfl_xor_sync(0xffffffffu, tot, o);
        if (lane == 0) red[0] = tot;
    }
    __syncthreads();
    float mean = red[0] / (float)HID;
    __syncthreads();

    float vs = 0.f;
    for (int i = tid; i < HID; i += blockDim.x) {
        float d = xr[i] - mean;
        vs += d * d;
    }
    #pragma unroll
    for (int o = 16; o > 0; o >>= 1) vs += __shfl_xor_sync(0xffffffffu, vs, o);
    if (lane == 0) red[wid] = vs;
    __syncthreads();
    float vt = 0.f;
    if (tid < nwarp) vt = red[tid];
    if (wid == 0) {
        #pragma unroll
        for (int o = 16; o > 0; o >>= 1) vt += __shfl_xor_sync(0xffffffffu, vt, o);
        if (lane == 0) red[0] = vt;
    }
    __syncthreads();
    float inv = rsqrtf(red[0] / (float)HID + 1e-5f);

    for (int i = tid; i < HID; i += blockDim.x)
        orow[i] = (xr[i] - mean) * inv * w[i] + b[i];
}

// ---------------- GELU helper ----------------
__device__ __forceinline__ float gelu1(float x) {
    return 0.5f * x * (1.0f + erff(x * 0.70710678118654752f));
}

// ---------------- SGEMM: C[M,N] = A[M,K] * W[N,K]^T (+bias)(+res)(+gelu) ----
// 128x128 tile, BK=8, 256 threads, 8x8 per thread, double-buffered smem.
// Requires: M % 128 == 0, K % 8 == 0. N arbitrary (guarded, scalar path if N%4!=0).
#define BM 128
#define BN 128
#define BK8 8

template<bool GELU>
__device__ __forceinline__ void gemm_dev(
    const float* __restrict__ A, const float* __restrict__ W,
    const float* __restrict__ bias, const float* __restrict__ res,
    float* __restrict__ C, int M, int N, int K)
{
    __shared__ float As[2][BK8][BM + 4];
    __shared__ float Bs[2][BK8][BN + 4];

    const int m0 = blockIdx.y * BM;
    const int n0 = blockIdx.x * BN;
    const int tid = threadIdx.x;
    const int tx = tid & 15;       // n direction
    const int ty = tid >> 4;       // m direction
    const int lr = tid >> 1;       // 0..127: row within tile for global loads
    const int lk = (tid & 1) << 2; // 0 or 4: k-chunk

    const int arow = m0 + lr;
    const int brow = n0 + lr;
    const bool bok = brow < N;
    const float4 f0 = make_float4(0.f, 0.f, 0.f, 0.f);

    float acc[8][8];
    #pragma unroll
    for (int i = 0; i < 8; i++)
        #pragma unroll
        for (int j = 0; j < 8; j++) acc[i][j] = 0.f;

    // preload tile 0
    float4 va = *reinterpret_cast<const float4*>(&A[(size_t)arow * K + lk]);
    float4 vb = bok ? *reinterpret_cast<const float4*>(&W[(size_t)brow * K + lk]) : f0;
    As[0][lk + 0][lr] = va.x; As[0][lk + 1][lr] = va.y;
    As[0][lk + 2][lr] = va.z; As[0][lk + 3][lr] = va.w;
    Bs[0][lk + 0][lr] = vb.x; Bs[0][lk + 1][lr] = vb.y;
    Bs[0][lk + 2][lr] = vb.z; Bs[0][lk + 3][lr] = vb.w;
    __syncthreads();

    const int nk = K >> 3;
    for (int t = 0; t < nk; t++) {
        const int buf = t & 1;
        const bool more = (t + 1) < nk;
        if (more) {
            const int ko = ((t + 1) << 3) + lk;
            va = *reinterpret_cast<const float4*>(&A[(size_t)arow * K + ko]);
            vb = bok ? *reinterpret_cast<const float4*>(&W[(size_t)brow * K + ko]) : f0;
        }
        #pragma unroll
        for (int kk = 0; kk < BK8; kk++) {
            float4 a0 = *reinterpret_cast<const float4*>(&As[buf][kk][ty * 4]);
            float4 a1 = *reinterpret_cast<const float4*>(&As[buf][kk][64 + ty * 4]);
            float4 b0 = *reinterpret_cast<const float4*>(&Bs[buf][kk][tx * 4]);
            float4 b1 = *reinterpret_cast<const float4*>(&Bs[buf][kk][64 + tx * 4]);
            float a[8] = {a0.x, a0.y, a0.z, a0.w, a1.x, a1.y, a1.z, a1.w};
            float b[8] = {b0.x, b0.y, b0.z, b0.w, b1.x, b1.y, b1.z, b1.w};
            #pragma unroll
            for (int i = 0; i < 8; i++)
                #pragma unroll
                for (int j = 0; j < 8; j++)
                    acc[i][j] = fmaf(a[i], b[j], acc[i][j]);
        }
        if (more) {
            const int nb2 = buf ^ 1;
            As[nb2][lk + 0][lr] = va.x; As[nb2][lk + 1][lr] = va.y;
            As[nb2][lk + 2][lr] = va.z; As[nb2][lk + 3][lr] = va.w;
            Bs[nb2][lk + 0][lr] = vb.x; Bs[nb2][lk + 1][lr] = vb.y;
            Bs[nb2][lk + 2][lr] = vb.z; Bs[nb2][lk + 3][lr] = vb.w;
            __syncthreads();
        }
    }

    // epilogue — vector path only if row stride keeps 16B alignment (N % 4 == 0)
    const bool vec_ok = ((N & 3) == 0);
    #pragma unroll
    for (int ig = 0; ig < 2; ig++) {
        #pragma unroll
        for (int ii = 0; ii < 4; ii++) {
            const int i = ig * 4 + ii;
            const int m = m0 + ig * 64 + ty * 4 + ii;
            #pragma unroll
            for (int jg = 0; jg < 2; jg++) {
                const int nb = n0 + jg * 64 + tx * 4;
                float v[4] = {acc[i][jg * 4 + 0], acc[i][jg * 4 + 1],
                              acc[i][jg * 4 + 2], acc[i][jg * 4 + 3]};
                if (vec_ok && (nb + 3 < N)) {
                    if (bias) {
                        float4 bv = *reinterpret_cast<const float4*>(&bias[nb]);
                        v[0] += bv.x; v[1] += bv.y; v[2] += bv.z; v[3] += bv.w;
                    }
                    if (res) {
                        float4 rv = *reinterpret_cast<const float4*>(&res[(size_t)m * N + nb]);
                        v[0] += rv.x; v[1] += rv.y; v[2] += rv.z; v[3] += rv.w;
                    }
                    if (GELU) {
                        v[0] = gelu1(v[0]); v[1] = gelu1(v[1]);
                        v[2] = gelu1(v[2]); v[3] = gelu1(v[3]);
                    }
                    float4 ov = make_float4(v[0], v[1], v[2], v[3]);
                    *reinterpret_cast<float4*>(&C[(size_t)m * N + nb]) = ov;
                } else {
                    #pragma unroll
                    for (int c = 0; c < 4; c++) {
                        int n = nb + c;
                        if (n < N) {
                            float val = v[c];
                            if (bias) val += bias[n];
                            if (res) val += res[(size_t)m * N + n];
                            if (GELU) val = gelu1(val);
                            C[(size_t)m * N + n] = val;
                        }
                    }
                }
            }
        }
    }
}

template<bool GELU>
__global__ __launch_bounds__(256, 2) void sgemm_k(
    const float* __restrict__ A, const float* __restrict__ W,
    const float* __restrict__ bias, const float* __restrict__ res,
    float* __restrict__ C, int M, int N, int K)
{
    gemm_dev<GELU>(A, W, bias, res, C, M, N, K);
}

__global__ __launch_bounds__(256, 2) void sgemm_qkv_k(
    const float* __restrict__ A,
    const float* __restrict__ w0, const float* __restrict__ w1, const float* __restrict__ w2,
    float* __restrict__ o0, float* __restrict__ o1, float* __restrict__ o2,
    int M, int N, int K)
{
    const float* W = (blockIdx.z == 0) ? w0 : ((blockIdx.z == 1) ? w1 : w2);
    float* C = (blockIdx.z == 0) ? o0 : ((blockIdx.z == 1) ? o1 : o2);
    gemm_dev<false>(A, W, nullptr, nullptr, C, M, N, K);
}

// ---------------- fused attention: one block per (query i, head, batch) ----------------
__global__ void attn_kernel(const float* __restrict__ q,
                            const float* __restrict__ k,
                            const float* __restrict__ v,
                            const int* __restrict__ amask,
                            float* __restrict__ out) {
    int i = blockIdx.x;
    int hh = blockIdx.y;
    int b = blockIdx.z;
    int tid = threadIdx.x; // 256 threads
    const float scale = 0.125f; // 1/sqrt(64)

    __shared__ float sc[SEQ];
    __shared__ float qv[HDIM];
    __shared__ float red[32];
    __shared__ float av[4][HDIM];

    size_t qoff = ((size_t)(b * SEQ + i)) * HID + hh * HDIM;
    if (tid < HDIM) qv[tid] = q[qoff + tid] * scale;
    __syncthreads();

    for (int j = tid; j <= i; j += blockDim.x) {
        const float* kr = k + ((size_t)(b * SEQ + j)) * HID + hh * HDIM;
        float s = 0.f;
        #pragma unroll
        for (int d = 0; d < HDIM; d += 4) {
            float4 kk4 = *reinterpret_cast<const float4*>(&kr[d]);
            s += qv[d] * kk4.x + qv[d + 1] * kk4.y + qv[d + 2] * kk4.z + qv[d + 3] * kk4.w;
        }
        if (amask[b * SEQ + j] == 0) s = -1e9f;
        sc[j] = s;
    }
    __syncthreads();

    int lane = tid & 31, wid = tid >> 5;
    float mx = -1e30f;
    for (int j = tid; j <= i; j += blockDim.x) mx = fmaxf(mx, sc[j]);
    #pragma unroll
    for (int o = 16; o > 0; o >>= 1) mx = fmaxf(mx, __shfl_xor_sync(0xffffffffu, mx, o));
    if (lane == 0) red[wid] = mx;
    __syncthreads();
    float m2 = (tid < 8) ? red[tid] : -1e30f;
    if (wid == 0) {
        #pragma unroll
        for (int o = 4; o > 0; o >>= 1) m2 = fmaxf(m2, __shfl_xor_sync(0xffffffffu, m2, o));
        if (lane == 0) red[0] = m2;
    }
    __syncthreads();
    float rowmax = red[0];
    __syncthreads();

    float sum = 0.f;
    for (int j = tid; j <= i; j += blockDim.x) {
        float e = expf(sc[j] - rowmax);
        sc[j] = e;
        sum += e;
    }
    #pragma unroll
    for (int o = 16; o > 0; o >>= 1) sum += __shfl_xor_sync(0xffffffffu, sum, o);
    if (lane == 0) red[wid] = sum;
    __syncthreads();
    float s2 = (tid < 8) ? red[tid] : 0.f;
    if (wid == 0) {
        #pragma unroll
        for (int o = 4; o > 0; o >>= 1) s2 += __shfl_xor_sync(0xffffffffu, s2, o);
        if (lane == 0) red[0] = s2;
    }
    __syncthreads();
    float inv = 1.0f / red[0];

    int d = tid & 63, grp = tid >> 6;
    float acc = 0.f;
    for (int j = grp; j <= i; j += 4)
        acc += sc[j] * v[((size_t)(b * SEQ + j)) * HID + hh * HDIM + d];
    av[grp][d] = acc;
    __syncthreads();
    if (grp == 0) {
        float r = av[0][d] + av[1][d] + av[2][d] + av[3][d];
        out[qoff + d] = r * inv;
    }
}

// ---------------- launcher ----------------
extern "C" void kernel_launch(void* const* d_in, const int* in_sizes, int n_in,
                              void* d_out, int out_size) {
    const int*   input_ids = (const int*)d_in[0];
    const int*   attn_mask = (const int*)d_in[1];
    const float* tok_emb   = (const float*)d_in[2];
    const float* pos_emb   = (const float*)d_in[3];
    const float* ln1_w     = (const float*)d_in[4];
    const float* ln1_b     = (const float*)d_in[5];
    const float* qw        = (const float*)d_in[6];
    const float* kw        = (const float*)d_in[7];
    const float* vw        = (const float*)d_in[8];
    const float* ow        = (const float*)d_in[9];
    const float* ob        = (const float*)d_in[10];
    const float* ln2_w     = (const float*)d_in[11];
    const float* ln2_b     = (const float*)d_in[12];
    const float* w1        = (const float*)d_in[13];
    const float* b1        = (const float*)d_in[14];
    const float* w2        = (const float*)d_in[15];
    const float* b2        = (const float*)d_in[16];
    const float* lnf_w     = (const float*)d_in[17];
    const float* lnf_b     = (const float*)d_in[18];
    const float* lm_w      = (const float*)d_in[19];
    float* out = (float*)d_out;

    float *x, *h, *q, *k, *v, *a, *ff;
    cudaGetSymbolAddress((void**)&x,  g_x);
    cudaGetSymbolAddress((void**)&h,  g_h);
    cudaGetSymbolAddress((void**)&q,  g_q);
    cudaGetSymbolAddress((void**)&k,  g_k);
    cudaGetSymbolAddress((void**)&v,  g_v);
    cudaGetSymbolAddress((void**)&a,  g_a);
    cudaGetSymbolAddress((void**)&ff, g_ff);

    {
        int n = T_TOK * HID;
        embed_kernel<<<(n + 255) / 256, 256>>>(input_ids, tok_emb, pos_emb, x);
    }

    dim3 gqkv(HID / BN, T_TOK / BM, 3);   // 6 x 16 x 3
    dim3 gproj(HID / BN, T_TOK / BM);     // 6 x 16
    dim3 gff1(FFI / BN, T_TOK / BM);      // 24 x 16
    dim3 gff2(HID / BN, T_TOK / BM);      // 6 x 16
    dim3 gattn(SEQ, NHEAD, BATCH);
    dim3 glm((VOCAB + BN - 1) / BN, T_TOK / BM); // 393 x 16

    for (int l = 0; l < NLAYER; l++) {
        const float* l1w = ln1_w + (size_t)l * HID;
        const float* l1b = ln1_b + (size_t)l * HID;
        const float* qwl = qw + (size_t)l * HID * HID;
        const float* kwl = kw + (size_t)l * HID * HID;
        const float* vwl = vw + (size_t)l * HID * HID;
        const float* owl = ow + (size_t)l * HID * HID;
        const float* obl = ob + (size_t)l * HID;
        const float* l2w = ln2_w + (size_t)l * HID;
        const float* l2b = ln2_b + (size_t)l * HID;
        const float* w1l = w1 + (size_t)l * FFI * HID;
        const float* b1l = b1 + (size_t)l * FFI;
        const float* w2l = w2 + (size_t)l * HID * FFI;
        const float* b2l = b2 + (size_t)l * HID;

        layernorm_kernel<<<T_TOK, 256>>>(x, l1w, l1b, h);
        sgemm_qkv_k<<<gqkv, 256>>>(h, qwl, kwl, vwl, q, k, v, T_TOK, HID, HID);
        attn_kernel<<<gattn, 256>>>(q, k, v, attn_mask, a);
        sgemm_k<false><<<gproj, 256>>>(a, owl, obl, x, x, T_TOK, HID, HID);

        layernorm_kernel<<<T_TOK, 256>>>(x, l2w, l2b, h);
        sgemm_k<true><<<gff1, 256>>>(h, w1l, b1l, nullptr, ff, T_TOK, FFI, HID);
        sgemm_k<false><<<gff2, 256>>>(ff, w2l, b2l, x, x, T_TOK, HID, FFI);
    }

    layernorm_kernel<<<T_TOK, 256>>>(x, lnf_w, lnf_b, h);
    sgemm_k<false><<<glm, 256>>>(h, lm_w, nullptr, nullptr, out, T_TOK, VOCAB, HID);
}

// round 4
// speedup vs baseline: 1.6706x; 1.4497x over previous
#include <cuda_runtime.h>
#include <math.h>
#include <stdint.h>

#define T_TOK 2048
#define SEQ   1024
#define BATCH 2
#define HID   768
#define NHEAD 12
#define HDIM  64
#define NLAYER 12
#define FFI   3072
#define VOCAB 50257

// ---------------- scratch (device globals: allocation-free) ----------------
__device__ float g_x[T_TOK * HID];
__device__ float g_h[T_TOK * HID];
__device__ float g_q[T_TOK * HID];
__device__ float g_k[T_TOK * HID];
__device__ float g_v[T_TOK * HID];
__device__ float g_a[T_TOK * HID];
__device__ float g_ff[T_TOK * FFI];

// ---------------- embeddings ----------------
__global__ void embed_kernel(const int* __restrict__ ids,
                             const float* __restrict__ tok,
                             const float* __restrict__ pos,
                             float* __restrict__ x) {
    int idx = blockIdx.x * blockDim.x + threadIdx.x;
    if (idx >= T_TOK * HID) return;
    int t = idx / HID;
    int hh = idx - t * HID;
    int s = t % SEQ;
    int id = ids[t];
    x[idx] = tok[(size_t)id * HID + hh] + pos[(size_t)s * HID + hh];
}

// ---------------- layernorm ----------------
__global__ void layernorm_kernel(const float* __restrict__ x,
                                 const float* __restrict__ w,
                                 const float* __restrict__ b,
                                 float* __restrict__ out) {
    int row = blockIdx.x;
    const float* xr = x + (size_t)row * HID;
    float* orow = out + (size_t)row * HID;
    __shared__ float red[32];
    int tid = threadIdx.x, lane = tid & 31, wid = tid >> 5;
    int nwarp = blockDim.x >> 5;

    float s = 0.f;
    for (int i = tid; i < HID; i += blockDim.x) s += xr[i];
    #pragma unroll
    for (int o = 16; o > 0; o >>= 1) s += __shfl_xor_sync(0xffffffffu, s, o);
    if (lane == 0) red[wid] = s;
    __syncthreads();
    float tot = 0.f;
    if (tid < nwarp) tot = red[tid];
    if (wid == 0) {
        #pragma unroll
        for (int o = 16; o > 0; o >>= 1) tot += __shfl_xor_sync(0xffffffffu, tot, o);
        if (lane == 0) red[0] = tot;
    }
    __syncthreads();
    float mean = red[0] / (float)HID;
    __syncthreads();

    float vs = 0.f;
    for (int i = tid; i < HID; i += blockDim.x) {
        float d = xr[i] - mean;
        vs += d * d;
    }
    #pragma unroll
    for (int o = 16; o > 0; o >>= 1) vs += __shfl_xor_sync(0xffffffffu, vs, o);
    if (lane == 0) red[wid] = vs;
    __syncthreads();
    float vt = 0.f;
    if (tid < nwarp) vt = red[tid];
    if (wid == 0) {
        #pragma unroll
        for (int o = 16; o > 0; o >>= 1) vt += __shfl_xor_sync(0xffffffffu, vt, o);
        if (lane == 0) red[0] = vt;
    }
    __syncthreads();
    float inv = rsqrtf(red[0] / (float)HID + 1e-5f);

    for (int i = tid; i < HID; i += blockDim.x)
        orow[i] = (xr[i] - mean) * inv * w[i] + b[i];
}

// ---------------- helpers ----------------
__device__ __forceinline__ float gelu1(float x) {
    return 0.5f * x * (1.0f + erff(x * 0.70710678118654752f));
}
__device__ __forceinline__ uint32_t f2tf32(float f) {
    uint32_t u;
    asm("cvt.rna.tf32.f32 %0, %1;" : "=r"(u) : "f"(f));
    return u;
}
__device__ __forceinline__ void mma_tf32(float d[4], const uint32_t a[4], const uint32_t b[2]) {
    asm volatile(
        "mma.sync.aligned.m16n8k8.row.col.f32.tf32.tf32.f32 "
        "{%0,%1,%2,%3}, {%4,%5,%6,%7}, {%8,%9}, {%0,%1,%2,%3};\n"
        : "+f"(d[0]), "+f"(d[1]), "+f"(d[2]), "+f"(d[3])
        : "r"(a[0]), "r"(a[1]), "r"(a[2]), "r"(a[3]), "r"(b[0]), "r"(b[1]));
}

// ---------------- TF32 tensor-core GEMM ----------------
// C[M,N] = A[M,K] * W[N,K]^T (+bias)(+res)(+gelu)
// Block tile 128x128, BK=16, 256 threads (8 warps, warp tile 64x32).
// Requires M % 128 == 0, K % 16 == 0. N arbitrary.
#define ASTRIDE 20
#define BSTRIDE 136

template<bool GELU>
__device__ __forceinline__ void gemm_mma_dev(
    const float* __restrict__ A, const float* __restrict__ W,
    const float* __restrict__ bias, const float* __restrict__ res,
    float* __restrict__ C, int M, int N, int K)
{
    __shared__ uint32_t As[2][128 * ASTRIDE];  // [m][k], stride 20
    __shared__ uint32_t Bs[2][16 * BSTRIDE];   // [k][n], stride 136

    const int tid  = threadIdx.x;
    const int warp = tid >> 5;
    const int lane = tid & 31;
    const int g    = lane >> 2;   // group id 0..7
    const int tig  = lane & 3;    // thread-in-group 0..3
    const int wm   = warp & 1;    // 0..1 : 64-row slice
    const int wn   = warp >> 1;   // 0..3 : 32-col slice

    const int m0 = blockIdx.y * 128;
    const int n0 = blockIdx.x * 128;

    // global load mapping: 2 float4 per thread per operand
    const int lrow = tid >> 2;          // 0..63
    const int lcol = (tid & 3) << 2;    // 0,4,8,12

    float acc[4][4][4];
    #pragma unroll
    for (int i = 0; i < 4; i++)
        #pragma unroll
        for (int j = 0; j < 4; j++)
            #pragma unroll
            for (int r = 0; r < 4; r++) acc[i][j][r] = 0.f;

    const int NIT = K >> 4;
    float4 aR[2], bR[2];

    // ---- load tile 0 ----
    {
        const int kb = 0;
        #pragma unroll
        for (int i = 0; i < 2; i++) {
            int ar = lrow + i * 64;
            aR[i] = *reinterpret_cast<const float4*>(&A[(size_t)(m0 + ar) * K + kb + lcol]);
            int brn = n0 + lrow + i * 64;
            bR[i] = (brn < N) ? *reinterpret_cast<const float4*>(&W[(size_t)brn * K + kb + lcol])
                              : make_float4(0.f, 0.f, 0.f, 0.f);
        }
        #pragma unroll
        for (int i = 0; i < 2; i++) {
            int ar = lrow + i * 64;
            uint4 u = make_uint4(f2tf32(aR[i].x), f2tf32(aR[i].y), f2tf32(aR[i].z), f2tf32(aR[i].w));
            *reinterpret_cast<uint4*>(&As[0][ar * ASTRIDE + lcol]) = u;
            int bn = lrow + i * 64;
            Bs[0][(lcol + 0) * BSTRIDE + bn] = f2tf32(bR[i].x);
            Bs[0][(lcol + 1) * BSTRIDE + bn] = f2tf32(bR[i].y);
            Bs[0][(lcol + 2) * BSTRIDE + bn] = f2tf32(bR[i].z);
            Bs[0][(lcol + 3) * BSTRIDE + bn] = f2tf32(bR[i].w);
        }
    }
    __syncthreads();

    for (int it = 0; it < NIT; it++) {
        const int buf = it & 1;
        const bool more = (it + 1) < NIT;
        if (more) {
            const int kb = (it + 1) << 4;
            #pragma unroll
            for (int i = 0; i < 2; i++) {
                int ar = lrow + i * 64;
                aR[i] = *reinterpret_cast<const float4*>(&A[(size_t)(m0 + ar) * K + kb + lcol]);
                int brn = n0 + lrow + i * 64;
                bR[i] = (brn < N) ? *reinterpret_cast<const float4*>(&W[(size_t)brn * K + kb + lcol])
                                  : make_float4(0.f, 0.f, 0.f, 0.f);
            }
        }

        // ---- compute: 2 ksteps of 8 ----
        #pragma unroll
        for (int s = 0; s < 2; s++) {
            uint32_t af[4][4];
            #pragma unroll
            for (int mt = 0; mt < 4; mt++) {
                int r0 = wm * 64 + mt * 16 + g;
                int c0 = s * 8 + tig;
                af[mt][0] = As[buf][r0 * ASTRIDE + c0];
                af[mt][1] = As[buf][(r0 + 8) * ASTRIDE + c0];
                af[mt][2] = As[buf][r0 * ASTRIDE + c0 + 4];
                af[mt][3] = As[buf][(r0 + 8) * ASTRIDE + c0 + 4];
            }
            uint32_t bf[4][2];
            #pragma unroll
            for (int nt = 0; nt < 4; nt++) {
                int n = wn * 32 + nt * 8 + g;
                int k0 = s * 8 + tig;
                bf[nt][0] = Bs[buf][k0 * BSTRIDE + n];
                bf[nt][1] = Bs[buf][(k0 + 4) * BSTRIDE + n];
            }
            #pragma unroll
            for (int mt = 0; mt < 4; mt++)
                #pragma unroll
                for (int nt = 0; nt < 4; nt++)
                    mma_tf32(acc[mt][nt], af[mt], bf[nt]);
        }

        if (more) {
            const int nb = buf ^ 1;
            #pragma unroll
            for (int i = 0; i < 2; i++) {
                int ar = lrow + i * 64;
                uint4 u = make_uint4(f2tf32(aR[i].x), f2tf32(aR[i].y), f2tf32(aR[i].z), f2tf32(aR[i].w));
                *reinterpret_cast<uint4*>(&As[nb][ar * ASTRIDE + lcol]) = u;
                int bn = lrow + i * 64;
                Bs[nb][(lcol + 0) * BSTRIDE + bn] = f2tf32(bR[i].x);
                Bs[nb][(lcol + 1) * BSTRIDE + bn] = f2tf32(bR[i].y);
                Bs[nb][(lcol + 2) * BSTRIDE + bn] = f2tf32(bR[i].z);
                Bs[nb][(lcol + 3) * BSTRIDE + bn] = f2tf32(bR[i].w);
            }
        }
        __syncthreads();
    }

    // ---- epilogue ----
    const bool n_even = ((N & 1) == 0);
    #pragma unroll
    for (int mt = 0; mt < 4; mt++) {
        const int r0 = m0 + wm * 64 + mt * 16 + g;
        #pragma unroll
        for (int nt = 0; nt < 4; nt++) {
            const int c = n0 + wn * 32 + nt * 8 + tig * 2;
            #pragma unroll
            for (int half = 0; half < 2; half++) {
                const int m = r0 + half * 8;
                float v0 = acc[mt][nt][half * 2 + 0];
                float v1 = acc[mt][nt][half * 2 + 1];
                if (n_even && (c + 1) < N) {
                    if (bias) { float2 bv = *reinterpret_cast<const float2*>(&bias[c]); v0 += bv.x; v1 += bv.y; }
                    if (res)  { float2 rv = *reinterpret_cast<const float2*>(&res[(size_t)m * N + c]); v0 += rv.x; v1 += rv.y; }
                    if (GELU) { v0 = gelu1(v0); v1 = gelu1(v1); }
                    *reinterpret_cast<float2*>(&C[(size_t)m * N + c]) = make_float2(v0, v1);
                } else {
                    if (c < N) {
                        float val = v0;
                        if (bias) val += bias[c];
                        if (res)  val += res[(size_t)m * N + c];
                        if (GELU) val = gelu1(val);
                        C[(size_t)m * N + c] = val;
                    }
                    if (c + 1 < N) {
                        float val = v1;
                        if (bias) val += bias[c + 1];
                        if (res)  val += res[(size_t)m * N + c + 1];
                        if (GELU) val = gelu1(val);
                        C[(size_t)m * N + c + 1] = val;
                    }
                }
            }
        }
    }
}

template<bool GELU>
__global__ __launch_bounds__(256, 2) void mma_gemm_k(
    const float* __restrict__ A, const float* __restrict__ W,
    const float* __restrict__ bias, const float* __restrict__ res,
    float* __restrict__ C, int M, int N, int K)
{
    gemm_mma_dev<GELU>(A, W, bias, res, C, M, N, K);
}

__global__ __launch_bounds__(256, 2) void mma_gemm_qkv_k(
    const float* __restrict__ A,
    const float* __restrict__ w0, const float* __restrict__ w1, const float* __restrict__ w2,
    float* __restrict__ o0, float* __restrict__ o1, float* __restrict__ o2,
    int M, int N, int K)
{
    const float* W = (blockIdx.z == 0) ? w0 : ((blockIdx.z == 1) ? w1 : w2);
    float* C = (blockIdx.z == 0) ? o0 : ((blockIdx.z == 1) ? o1 : o2);
    gemm_mma_dev<false>(A, W, nullptr, nullptr, C, M, N, K);
}

// ---------------- fused attention (unchanged) ----------------
__global__ void attn_kernel(const float* __restrict__ q,
                            const float* __restrict__ k,
                            const float* __restrict__ v,
                            const int* __restrict__ amask,
                            float* __restrict__ out) {
    int i = blockIdx.x;
    int hh = blockIdx.y;
    int b = blockIdx.z;
    int tid = threadIdx.x;
    const float scale = 0.125f;

    __shared__ float sc[SEQ];
    __shared__ float qv[HDIM];
    __shared__ float red[32];
    __shared__ float av[4][HDIM];

    size_t qoff = ((size_t)(b * SEQ + i)) * HID + hh * HDIM;
    if (tid < HDIM) qv[tid] = q[qoff + tid] * scale;
    __syncthreads();

    for (int j = tid; j <= i; j += blockDim.x) {
        const float* kr = k + ((size_t)(b * SEQ + j)) * HID + hh * HDIM;
        float s = 0.f;
        #pragma unroll
        for (int d = 0; d < HDIM; d += 4) {
            float4 kk4 = *reinterpret_cast<const float4*>(&kr[d]);
            s += qv[d] * kk4.x + qv[d + 1] * kk4.y + qv[d + 2] * kk4.z + qv[d + 3] * kk4.w;
        }
        if (amask[b * SEQ + j] == 0) s = -1e9f;
        sc[j] = s;
    }
    __syncthreads();

    int lane = tid & 31, wid = tid >> 5;
    float mx = -1e30f;
    for (int j = tid; j <= i; j += blockDim.x) mx = fmaxf(mx, sc[j]);
    #pragma unroll
    for (int o = 16; o > 0; o >>= 1) mx = fmaxf(mx, __shfl_xor_sync(0xffffffffu, mx, o));
    if (lane == 0) red[wid] = mx;
    __syncthreads();
    float m2 = (tid < 8) ? red[tid] : -1e30f;
    if (wid == 0) {
        #pragma unroll
        for (int o = 4; o > 0; o >>= 1) m2 = fmaxf(m2, __shfl_xor_sync(0xffffffffu, m2, o));
        if (lane == 0) red[0] = m2;
    }
    __syncthreads();
    float rowmax = red[0];
    __syncthreads();

    float sum = 0.f;
    for (int j = tid; j <= i; j += blockDim.x) {
        float e = expf(sc[j] - rowmax);
        sc[j] = e;
        sum += e;
    }
    #pragma unroll
    for (int o = 16; o > 0; o >>= 1) sum += __shfl_xor_sync(0xffffffffu, sum, o);
    if (lane == 0) red[wid] = sum;
    __syncthreads();
    float s2 = (tid < 8) ? red[tid] : 0.f;
    if (wid == 0) {
        #pragma unroll
        for (int o = 4; o > 0; o >>= 1) s2 += __shfl_xor_sync(0xffffffffu, s2, o);
        if (lane == 0) red[0] = s2;
    }
    __syncthreads();
    float inv = 1.0f / red[0];

    int d = tid & 63, grp = tid >> 6;
    float acc = 0.f;
    for (int j = grp; j <= i; j += 4)
        acc += sc[j] * v[((size_t)(b * SEQ + j)) * HID + hh * HDIM + d];
    av[grp][d] = acc;
    __syncthreads();
    if (grp == 0) {
        float r = av[0][d] + av[1][d] + av[2][d] + av[3][d];
        out[qoff + d] = r * inv;
    }
}

// ---------------- launcher ----------------
extern "C" void kernel_launch(void* const* d_in, const int* in_sizes, int n_in,
                              void* d_out, int out_size) {
    const int*   input_ids = (const int*)d_in[0];
    const int*   attn_mask = (const int*)d_in[1];
    const float* tok_emb   = (const float*)d_in[2];
    const float* pos_emb   = (const float*)d_in[3];
    const float* ln1_w     = (const float*)d_in[4];
    const float* ln1_b     = (const float*)d_in[5];
    const float* qw        = (const float*)d_in[6];
    const float* kw        = (const float*)d_in[7];
    const float* vw        = (const float*)d_in[8];
    const float* ow        = (const float*)d_in[9];
    const float* ob        = (const float*)d_in[10];
    const float* ln2_w     = (const float*)d_in[11];
    const float* ln2_b     = (const float*)d_in[12];
    const float* w1        = (const float*)d_in[13];
    const float* b1        = (const float*)d_in[14];
    const float* w2        = (const float*)d_in[15];
    const float* b2        = (const float*)d_in[16];
    const float* lnf_w     = (const float*)d_in[17];
    const float* lnf_b     = (const float*)d_in[18];
    const float* lm_w      = (const float*)d_in[19];
    float* out = (float*)d_out;

    float *x, *h, *q, *k, *v, *a, *ff;
    cudaGetSymbolAddress((void**)&x,  g_x);
    cudaGetSymbolAddress((void**)&h,  g_h);
    cudaGetSymbolAddress((void**)&q,  g_q);
    cudaGetSymbolAddress((void**)&k,  g_k);
    cudaGetSymbolAddress((void**)&v,  g_v);
    cudaGetSymbolAddress((void**)&a,  g_a);
    cudaGetSymbolAddress((void**)&ff, g_ff);

    {
        int n = T_TOK * HID;
        embed_kernel<<<(n + 255) / 256, 256>>>(input_ids, tok_emb, pos_emb, x);
    }

    dim3 gqkv(HID / 128, T_TOK / 128, 3);   // 6 x 16 x 3
    dim3 gproj(HID / 128, T_TOK / 128);     // 6 x 16
    dim3 gff1(FFI / 128, T_TOK / 128);      // 24 x 16
    dim3 gff2(HID / 128, T_TOK / 128);      // 6 x 16
    dim3 gattn(SEQ, NHEAD, BATCH);
    dim3 glm((VOCAB + 127) / 128, T_TOK / 128); // 393 x 16

    for (int l = 0; l < NLAYER; l++) {
        const float* l1w = ln1_w + (size_t)l * HID;
        const float* l1b = ln1_b + (size_t)l * HID;
        const float* qwl = qw + (size_t)l * HID * HID;
        const float* kwl = kw + (size_t)l * HID * HID;
        const float* vwl = vw + (size_t)l * HID * HID;
        const float* owl = ow + (size_t)l * HID * HID;
        const float* obl = ob + (size_t)l * HID;
        const float* l2w = ln2_w + (size_t)l * HID;
        const float* l2b = ln2_b + (size_t)l * HID;
        const float* w1l = w1 + (size_t)l * FFI * HID;
        const float* b1l = b1 + (size_t)l * FFI;
        const float* w2l = w2 + (size_t)l * HID * FFI;
        const float* b2l = b2 + (size_t)l * HID;

        layernorm_kernel<<<T_TOK, 256>>>(x, l1w, l1b, h);
        mma_gemm_qkv_k<<<gqkv, 256>>>(h, qwl, kwl, vwl, q, k, v, T_TOK, HID, HID);
        attn_kernel<<<gattn, 256>>>(q, k, v, attn_mask, a);
        mma_gemm_k<false><<<gproj, 256>>>(a, owl, obl, x, x, T_TOK, HID, HID);

        layernorm_kernel<<<T_TOK, 256>>>(x, l2w, l2b, h);
        mma_gemm_k<true><<<gff1, 256>>>(h, w1l, b1l, nullptr, ff, T_TOK, FFI, HID);
        mma_gemm_k<false><<<gff2, 256>>>(ff, w2l, b2l, x, x, T_TOK, HID, FFI);
    }

    layernorm_kernel<<<T_TOK, 256>>>(x, lnf_w, lnf_b, h);
    mma_gemm_k<false><<<glm, 256>>>(h, lm_w, nullptr, nullptr, out, T_TOK, VOCAB, HID);
}

// round 5
// speedup vs baseline: 1.6712x; 1.0004x over previous
#include <cuda_runtime.h>
#include <math.h>
#include <stdint.h>

#define T_TOK 2048
#define SEQ   1024
#define BATCH 2
#define HID   768
#define NHEAD 12
#define HDIM  64
#define NLAYER 12
#define FFI   3072
#define VOCAB 50257

// ---------------- scratch (device globals: allocation-free) ----------------
__device__ float g_x[T_TOK * HID];
__device__ float g_h[T_TOK * HID];
__device__ float g_q[T_TOK * HID];
__device__ float g_k[T_TOK * HID];
__device__ float g_v[T_TOK * HID];
__device__ float g_a[T_TOK * HID];
__device__ float g_ff[T_TOK * FFI];

// ---------------- embeddings ----------------
__global__ void embed_kernel(const int* __restrict__ ids,
                             const float* __restrict__ tok,
                             const float* __restrict__ pos,
                             float* __restrict__ x) {
    int idx = blockIdx.x * blockDim.x + threadIdx.x;
    if (idx >= T_TOK * HID) return;
    int t = idx / HID;
    int hh = idx - t * HID;
    int s = t % SEQ;
    int id = ids[t];
    x[idx] = tok[(size_t)id * HID + hh] + pos[(size_t)s * HID + hh];
}

// ---------------- layernorm ----------------
__global__ void layernorm_kernel(const float* __restrict__ x,
                                 const float* __restrict__ w,
                                 const float* __restrict__ b,
                                 float* __restrict__ out) {
    int row = blockIdx.x;
    const float* xr = x + (size_t)row * HID;
    float* orow = out + (size_t)row * HID;
    __shared__ float red[32];
    int tid = threadIdx.x, lane = tid & 31, wid = tid >> 5;
    int nwarp = blockDim.x >> 5;

    float s = 0.f;
    for (int i = tid; i < HID; i += blockDim.x) s += xr[i];
    #pragma unroll
    for (int o = 16; o > 0; o >>= 1) s += __shfl_xor_sync(0xffffffffu, s, o);
    if (lane == 0) red[wid] = s;
    __syncthreads();
    float tot = 0.f;
    if (tid < nwarp) tot = red[tid];
    if (wid == 0) {
        #pragma unroll
        for (int o = 16; o > 0; o >>= 1) tot += __shfl_xor_sync(0xffffffffu, tot, o);
        if (lane == 0) red[0] = tot;
    }
    __syncthreads();
    float mean = red[0] / (float)HID;
    __syncthreads();

    float vs = 0.f;
    for (int i = tid; i < HID; i += blockDim.x) {
        float d = xr[i] - mean;
        vs += d * d;
    }
    #pragma unroll
    for (int o = 16; o > 0; o >>= 1) vs += __shfl_xor_sync(0xffffffffu, vs, o);
    if (lane == 0) red[wid] = vs;
    __syncthreads();
    float vt = 0.f;
    if (tid < nwarp) vt = red[tid];
    if (wid == 0) {
        #pragma unroll
        for (int o = 16; o > 0; o >>= 1) vt += __shfl_xor_sync(0xffffffffu, vt, o);
        if (lane == 0) red[0] = vt;
    }
    __syncthreads();
    float inv = rsqrtf(red[0] / (float)HID + 1e-5f);

    for (int i = tid; i < HID; i += blockDim.x)
        orow[i] = (xr[i] - mean) * inv * w[i] + b[i];
}

// ---------------- helpers ----------------
__device__ __forceinline__ float gelu1(float x) {
    return 0.5f * x * (1.0f + erff(x * 0.70710678118654752f));
}
__device__ __forceinline__ uint32_t f2tf32(float f) {
    uint32_t u;
    asm("cvt.rna.tf32.f32 %0, %1;" : "=r"(u) : "f"(f));
    return u;
}
__device__ __forceinline__ void mma_tf32(float d[4], const uint32_t a[4], const uint32_t b[2]) {
    asm volatile(
        "mma.sync.aligned.m16n8k8.row.col.f32.tf32.tf32.f32 "
        "{%0,%1,%2,%3}, {%4,%5,%6,%7}, {%8,%9}, {%0,%1,%2,%3};\n"
        : "+f"(d[0]), "+f"(d[1]), "+f"(d[2]), "+f"(d[3])
        : "r"(a[0]), "r"(a[1]), "r"(a[2]), "r"(a[3]), "r"(b[0]), "r"(b[1]));
}

// ---------------- TF32 tensor-core GEMM ----------------
// C[M,N] = A[M,K] * W[N,K]^T (+bias)(+res)(+gelu)
// Block tile 128x128, BK=16, 256 threads (8 warps, warp tile 64x32).
// Requires M % 128 == 0, K % 16 == 0. N arbitrary.
#define ASTRIDE 20
#define BSTRIDE 136

template<bool GELU>
__device__ __forceinline__ void gemm_mma_dev(
    const float* __restrict__ A, const float* __restrict__ W,
    const float* __restrict__ bias, const float* __restrict__ res,
    float* __restrict__ C, int M, int N, int K)
{
    __shared__ uint32_t As[2][128 * ASTRIDE];  // [m][k], stride 20
    __shared__ uint32_t Bs[2][16 * BSTRIDE];   // [k][n], stride 136

    const int tid  = threadIdx.x;
    const int warp = tid >> 5;
    const int lane = tid & 31;
    const int g    = lane >> 2;   // group id 0..7
    const int tig  = lane & 3;    // thread-in-group 0..3
    const int wm   = warp & 1;    // 0..1 : 64-row slice
    const int wn   = warp >> 1;   // 0..3 : 32-col slice

    const int m0 = blockIdx.y * 128;
    const int n0 = blockIdx.x * 128;

    // global load mapping: 2 float4 per thread per operand
    const int lrow = tid >> 2;          // 0..63
    const int lcol = (tid & 3) << 2;    // 0,4,8,12

    float acc[4][4][4];
    #pragma unroll
    for (int i = 0; i < 4; i++)
        #pragma unroll
        for (int j = 0; j < 4; j++)
            #pragma unroll
            for (int r = 0; r < 4; r++) acc[i][j][r] = 0.f;

    const int NIT = K >> 4;
    float4 aR[2], bR[2];

    // ---- load tile 0 ----
    {
        const int kb = 0;
        #pragma unroll
        for (int i = 0; i < 2; i++) {
            int ar = lrow + i * 64;
            aR[i] = *reinterpret_cast<const float4*>(&A[(size_t)(m0 + ar) * K + kb + lcol]);
            int brn = n0 + lrow + i * 64;
            bR[i] = (brn < N) ? *reinterpret_cast<const float4*>(&W[(size_t)brn * K + kb + lcol])
                              : make_float4(0.f, 0.f, 0.f, 0.f);
        }
        #pragma unroll
        for (int i = 0; i < 2; i++) {
            int ar = lrow + i * 64;
            uint4 u = make_uint4(f2tf32(aR[i].x), f2tf32(aR[i].y), f2tf32(aR[i].z), f2tf32(aR[i].w));
            *reinterpret_cast<uint4*>(&As[0][ar * ASTRIDE + lcol]) = u;
            int bn = lrow + i * 64;
            Bs[0][(lcol + 0) * BSTRIDE + bn] = f2tf32(bR[i].x);
            Bs[0][(lcol + 1) * BSTRIDE + bn] = f2tf32(bR[i].y);
            Bs[0][(lcol + 2) * BSTRIDE + bn] = f2tf32(bR[i].z);
            Bs[0][(lcol + 3) * BSTRIDE + bn] = f2tf32(bR[i].w);
        }
    }
    __syncthreads();

    for (int it = 0; it < NIT; it++) {
        const int buf = it & 1;
        const bool more = (it + 1) < NIT;
        if (more) {
            const int kb = (it + 1) << 4;
            #pragma unroll
            for (int i = 0; i < 2; i++) {
                int ar = lrow + i * 64;
                aR[i] = *reinterpret_cast<const float4*>(&A[(size_t)(m0 + ar) * K + kb + lcol]);
                int brn = n0 + lrow + i * 64;
                bR[i] = (brn < N) ? *reinterpret_cast<const float4*>(&W[(size_t)brn * K + kb + lcol])
                                  : make_float4(0.f, 0.f, 0.f, 0.f);
            }
        }

        // ---- compute: 2 ksteps of 8 ----
        #pragma unroll
        for (int s = 0; s < 2; s++) {
            uint32_t af[4][4];
            #pragma unroll
            for (int mt = 0; mt < 4; mt++) {
                int r0 = wm * 64 + mt * 16 + g;
                int c0 = s * 8 + tig;
                af[mt][0] = As[buf][r0 * ASTRIDE + c0];
                af[mt][1] = As[buf][(r0 + 8) * ASTRIDE + c0];
                af[mt][2] = As[buf][r0 * ASTRIDE + c0 + 4];
                af[mt][3] = As[buf][(r0 + 8) * ASTRIDE + c0 + 4];
            }
            uint32_t bf[4][2];
            #pragma unroll
            for (int nt = 0; nt < 4; nt++) {
                int n = wn * 32 + nt * 8 + g;
                int k0 = s * 8 + tig;
                bf[nt][0] = Bs[buf][k0 * BSTRIDE + n];
                bf[nt][1] = Bs[buf][(k0 + 4) * BSTRIDE + n];
            }
            #pragma unroll
            for (int mt = 0; mt < 4; mt++)
                #pragma unroll
                for (int nt = 0; nt < 4; nt++)
                    mma_tf32(acc[mt][nt], af[mt], bf[nt]);
        }

        if (more) {
            const int nb = buf ^ 1;
            #pragma unroll
            for (int i = 0; i < 2; i++) {
                int ar = lrow + i * 64;
                uint4 u = make_uint4(f2tf32(aR[i].x), f2tf32(aR[i].y), f2tf32(aR[i].z), f2tf32(aR[i].w));
                *reinterpret_cast<uint4*>(&As[nb][ar * ASTRIDE + lcol]) = u;
                int bn = lrow + i * 64;
                Bs[nb][(lcol + 0) * BSTRIDE + bn] = f2tf32(bR[i].x);
                Bs[nb][(lcol + 1) * BSTRIDE + bn] = f2tf32(bR[i].y);
                Bs[nb][(lcol + 2) * BSTRIDE + bn] = f2tf32(bR[i].z);
                Bs[nb][(lcol + 3) * BSTRIDE + bn] = f2tf32(bR[i].w);
            }
        }
        __syncthreads();
    }

    // ---- epilogue ----
    const bool n_even = ((N & 1) == 0);
    #pragma unroll
    for (int mt = 0; mt < 4; mt++) {
        const int r0 = m0 + wm * 64 + mt * 16 + g;
        #pragma unroll
        for (int nt = 0; nt < 4; nt++) {
            const int c = n0 + wn * 32 + nt * 8 + tig * 2;
            #pragma unroll
            for (int half = 0; half < 2; half++) {
                const int m = r0 + half * 8;
                float v0 = acc[mt][nt][half * 2 + 0];
                float v1 = acc[mt][nt][half * 2 + 1];
                if (n_even && (c + 1) < N) {
                    if (bias) { float2 bv = *reinterpret_cast<const float2*>(&bias[c]); v0 += bv.x; v1 += bv.y; }
                    if (res)  { float2 rv = *reinterpret_cast<const float2*>(&res[(size_t)m * N + c]); v0 += rv.x; v1 += rv.y; }
                    if (GELU) { v0 = gelu1(v0); v1 = gelu1(v1); }
                    *reinterpret_cast<float2*>(&C[(size_t)m * N + c]) = make_float2(v0, v1);
                } else {
                    if (c < N) {
                        float val = v0;
                        if (bias) val += bias[c];
                        if (res)  val += res[(size_t)m * N + c];
                        if (GELU) val = gelu1(val);
                        C[(size_t)m * N + c] = val;
                    }
                    if (c + 1 < N) {
                        float val = v1;
                        if (bias) val += bias[c + 1];
                        if (res)  val += res[(size_t)m * N + c + 1];
                        if (GELU) val = gelu1(val);
                        C[(size_t)m * N + c + 1] = val;
                    }
                }
            }
        }
    }
}

template<bool GELU>
__global__ __launch_bounds__(256, 2) void mma_gemm_k(
    const float* __restrict__ A, const float* __restrict__ W,
    const float* __restrict__ bias, const float* __restrict__ res,
    float* __restrict__ C, int M, int N, int K)
{
    gemm_mma_dev<GELU>(A, W, bias, res, C, M, N, K);
}

__global__ __launch_bounds__(256, 2) void mma_gemm_qkv_k(
    const float* __restrict__ A,
    const float* __restrict__ w0, const float* __restrict__ w1, const float* __restrict__ w2,
    float* __restrict__ o0, float* __restrict__ o1, float* __restrict__ o2,
    int M, int N, int K)
{
    const float* W = (blockIdx.z == 0) ? w0 : ((blockIdx.z == 1) ? w1 : w2);
    float* C = (blockIdx.z == 0) ? o0 : ((blockIdx.z == 1) ? o1 : o2);
    gemm_mma_dev<false>(A, W, nullptr, nullptr, C, M, N, K);
}

// ---------------- fused attention (unchanged) ----------------
__global__ void attn_kernel(const float* __restrict__ q,
                            const float* __restrict__ k,
                            const float* __restrict__ v,
                            const int* __restrict__ amask,
                            float* __restrict__ out) {
    int i = blockIdx.x;
    int hh = blockIdx.y;
    int b = blockIdx.z;
    int tid = threadIdx.x;
    const float scale = 0.125f;

    __shared__ float sc[SEQ];
    __shared__ float qv[HDIM];
    __shared__ float red[32];
    __shared__ float av[4][HDIM];

    size_t qoff = ((size_t)(b * SEQ + i)) * HID + hh * HDIM;
    if (tid < HDIM) qv[tid] = q[qoff + tid] * scale;
    __syncthreads();

    for (int j = tid; j <= i; j += blockDim.x) {
        const float* kr = k + ((size_t)(b * SEQ + j)) * HID + hh * HDIM;
        float s = 0.f;
        #pragma unroll
        for (int d = 0; d < HDIM; d += 4) {
            float4 kk4 = *reinterpret_cast<const float4*>(&kr[d]);
            s += qv[d] * kk4.x + qv[d + 1] * kk4.y + qv[d + 2] * kk4.z + qv[d + 3] * kk4.w;
        }
        if (amask[b * SEQ + j] == 0) s = -1e9f;
        sc[j] = s;
    }
    __syncthreads();

    int lane = tid & 31, wid = tid >> 5;
    float mx = -1e30f;
    for (int j = tid; j <= i; j += blockDim.x) mx = fmaxf(mx, sc[j]);
    #pragma unroll
    for (int o = 16; o > 0; o >>= 1) mx = fmaxf(mx, __shfl_xor_sync(0xffffffffu, mx, o));
    if (lane == 0) red[wid] = mx;
    __syncthreads();
    float m2 = (tid < 8) ? red[tid] : -1e30f;
    if (wid == 0) {
        #pragma unroll
        for (int o = 4; o > 0; o >>= 1) m2 = fmaxf(m2, __shfl_xor_sync(0xffffffffu, m2, o));
        if (lane == 0) red[0] = m2;
    }
    __syncthreads();
    float rowmax = red[0];
    __syncthreads();

    float sum = 0.f;
    for (int j = tid; j <= i; j += blockDim.x) {
        float e = expf(sc[j] - rowmax);
        sc[j] = e;
        sum += e;
    }
    #pragma unroll
    for (int o = 16; o > 0; o >>= 1) sum += __shfl_xor_sync(0xffffffffu, sum, o);
    if (lane == 0) red[wid] = sum;
    __syncthreads();
    float s2 = (tid < 8) ? red[tid] : 0.f;
    if (wid == 0) {
        #pragma unroll
        for (int o = 4; o > 0; o >>= 1) s2 += __shfl_xor_sync(0xffffffffu, s2, o);
        if (lane == 0) red[0] = s2;
    }
    __syncthreads();
    float inv = 1.0f / red[0];

    int d = tid & 63, grp = tid >> 6;
    float acc = 0.f;
    for (int j = grp; j <= i; j += 4)
        acc += sc[j] * v[((size_t)(b * SEQ + j)) * HID + hh * HDIM + d];
    av[grp][d] = acc;
    __syncthreads();
    if (grp == 0) {
        float r = av[0][d] + av[1][d] + av[2][d] + av[3][d];
        out[qoff + d] = r * inv;
    }
}

// ---------------- launcher ----------------
extern "C" void kernel_launch(void* const* d_in, const int* in_sizes, int n_in,
                              void* d_out, int out_size) {
    const int*   input_ids = (const int*)d_in[0];
    const int*   attn_mask = (const int*)d_in[1];
    const float* tok_emb   = (const float*)d_in[2];
    const float* pos_emb   = (const float*)d_in[3];
    const float* ln1_w     = (const float*)d_in[4];
    const float* ln1_b     = (const float*)d_in[5];
    const float* qw        = (const float*)d_in[6];
    const float* kw        = (const float*)d_in[7];
    const float* vw        = (const float*)d_in[8];
    const float* ow        = (const float*)d_in[9];
    const float* ob        = (const float*)d_in[10];
    const float* ln2_w     = (const float*)d_in[11];
    const float* ln2_b     = (const float*)d_in[12];
    const float* w1        = (const float*)d_in[13];
    const float* b1        = (const float*)d_in[14];
    const float* w2        = (const float*)d_in[15];
    const float* b2        = (const float*)d_in[16];
    const float* lnf_w     = (const float*)d_in[17];
    const float* lnf_b     = (const float*)d_in[18];
    const float* lm_w      = (const float*)d_in[19];
    float* out = (float*)d_out;

    float *x, *h, *q, *k, *v, *a, *ff;
    cudaGetSymbolAddress((void**)&x,  g_x);
    cudaGetSymbolAddress((void**)&h,  g_h);
    cudaGetSymbolAddress((void**)&q,  g_q);
    cudaGetSymbolAddress((void**)&k,  g_k);
    cudaGetSymbolAddress((void**)&v,  g_v);
    cudaGetSymbolAddress((void**)&a,  g_a);
    cudaGetSymbolAddress((void**)&ff, g_ff);

    {
        int n = T_TOK * HID;
        embed_kernel<<<(n + 255) / 256, 256>>>(input_ids, tok_emb, pos_emb, x);
    }

    dim3 gqkv(HID / 128, T_TOK / 128, 3);   // 6 x 16 x 3
    dim3 gproj(HID / 128, T_TOK / 128);     // 6 x 16
    dim3 gff1(FFI / 128, T_TOK / 128);      // 24 x 16
    dim3 gff2(HID / 128, T_TOK / 128);      // 6 x 16
    dim3 gattn(SEQ, NHEAD, BATCH);
    dim3 glm((VOCAB + 127) / 128, T_TOK / 128); // 393 x 16

    for (int l = 0; l < NLAYER; l++) {
        const float* l1w = ln1_w + (size_t)l * HID;
        const float* l1b = ln1_b + (size_t)l * HID;
        const float* qwl = qw + (size_t)l * HID * HID;
        const float* kwl = kw + (size_t)l * HID * HID;
        const float* vwl = vw + (size_t)l * HID * HID;
        const float* owl = ow + (size_t)l * HID * HID;
        const float* obl = ob + (size_t)l * HID;
        const float* l2w = ln2_w + (size_t)l * HID;
        const float* l2b = ln2_b + (size_t)l * HID;
        const float* w1l = w1 + (size_t)l * FFI * HID;
        const float* b1l = b1 + (size_t)l * FFI;
        const float* w2l = w2 + (size_t)l * HID * FFI;
        const float* b2l = b2 + (size_t)l * HID;

        layernorm_kernel<<<T_TOK, 256>>>(x, l1w, l1b, h);
        mma_gemm_qkv_k<<<gqkv, 256>>>(h, qwl, kwl, vwl, q, k, v, T_TOK, HID, HID);
        attn_kernel<<<gattn, 256>>>(q, k, v, attn_mask, a);
        mma_gemm_k<false><<<gproj, 256>>>(a, owl, obl, x, x, T_TOK, HID, HID);

        layernorm_kernel<<<T_TOK, 256>>>(x, l2w, l2b, h);
        mma_gemm_k<true><<<gff1, 256>>>(h, w1l, b1l, nullptr, ff, T_TOK, FFI, HID);
        mma_gemm_k<false><<<gff2, 256>>>(ff, w2l, b2l, x, x, T_TOK, HID, FFI);
    }

    layernorm_kernel<<<T_TOK, 256>>>(x, lnf_w, lnf_b, h);
    mma_gemm_k<false><<<glm, 256>>>(h, lm_w, nullptr, nullptr, out, T_TOK, VOCAB, HID);
}

// round 6
// speedup vs baseline: 3.9007x; 2.3341x over previous
#include <cuda_runtime.h>
#include <math.h>
#include <stdint.h>

#define T_TOK 2048
#define SEQ   1024
#define BATCH 2
#define HID   768
#define NHEAD 12
#define HDIM  64
#define NLAYER 12
#define FFI   3072
#define VOCAB 50257

// ---------------- scratch (device globals: allocation-free) ----------------
__device__ float g_x[T_TOK * HID];
__device__ float g_h[T_TOK * HID];
__device__ float g_q[T_TOK * HID];
__device__ float g_k[T_TOK * HID];
__device__ float g_v[T_TOK * HID];
__device__ float g_a[T_TOK * HID];
__device__ float g_ff[T_TOK * FFI];

// ---------------- embeddings ----------------
__global__ void embed_kernel(const int* __restrict__ ids,
                             const float* __restrict__ tok,
                             const float* __restrict__ pos,
                             float* __restrict__ x) {
    int idx = blockIdx.x * blockDim.x + threadIdx.x;
    if (idx >= T_TOK * HID) return;
    int t = idx / HID;
    int hh = idx - t * HID;
    int s = t % SEQ;
    int id = ids[t];
    x[idx] = tok[(size_t)id * HID + hh] + pos[(size_t)s * HID + hh];
}

// ---------------- layernorm ----------------
__global__ void layernorm_kernel(const float* __restrict__ x,
                                 const float* __restrict__ w,
                                 const float* __restrict__ b,
                                 float* __restrict__ out) {
    int row = blockIdx.x;
    const float* xr = x + (size_t)row * HID;
    float* orow = out + (size_t)row * HID;
    __shared__ float red[32];
    int tid = threadIdx.x, lane = tid & 31, wid = tid >> 5;
    int nwarp = blockDim.x >> 5;

    float s = 0.f;
    for (int i = tid; i < HID; i += blockDim.x) s += xr[i];
    #pragma unroll
    for (int o = 16; o > 0; o >>= 1) s += __shfl_xor_sync(0xffffffffu, s, o);
    if (lane == 0) red[wid] = s;
    __syncthreads();
    float tot = 0.f;
    if (tid < nwarp) tot = red[tid];
    if (wid == 0) {
        #pragma unroll
        for (int o = 16; o > 0; o >>= 1) tot += __shfl_xor_sync(0xffffffffu, tot, o);
        if (lane == 0) red[0] = tot;
    }
    __syncthreads();
    float mean = red[0] / (float)HID;
    __syncthreads();

    float vs = 0.f;
    for (int i = tid; i < HID; i += blockDim.x) {
        float d = xr[i] - mean;
        vs += d * d;
    }
    #pragma unroll
    for (int o = 16; o > 0; o >>= 1) vs += __shfl_xor_sync(0xffffffffu, vs, o);
    if (lane == 0) red[wid] = vs;
    __syncthreads();
    float vt = 0.f;
    if (tid < nwarp) vt = red[tid];
    if (wid == 0) {
        #pragma unroll
        for (int o = 16; o > 0; o >>= 1) vt += __shfl_xor_sync(0xffffffffu, vt, o);
        if (lane == 0) red[0] = vt;
    }
    __syncthreads();
    float inv = rsqrtf(red[0] / (float)HID + 1e-5f);

    for (int i = tid; i < HID; i += blockDim.x)
        orow[i] = (xr[i] - mean) * inv * w[i] + b[i];
}

// ---------------- helpers ----------------
__device__ __forceinline__ float gelu1(float x) {
    return 0.5f * x * (1.0f + erff(x * 0.70710678118654752f));
}
__device__ __forceinline__ uint32_t f2tf32(float f) {
    uint32_t u;
    asm("cvt.rna.tf32.f32 %0, %1;" : "=r"(u) : "f"(f));
    return u;
}
__device__ __forceinline__ void mma_tf32(float d[4], const uint32_t a[4], const uint32_t b[2]) {
    asm volatile(
        "mma.sync.aligned.m16n8k8.row.col.f32.tf32.tf32.f32 "
        "{%0,%1,%2,%3}, {%4,%5,%6,%7}, {%8,%9}, {%0,%1,%2,%3};\n"
        : "+f"(d[0]), "+f"(d[1]), "+f"(d[2]), "+f"(d[3])
        : "r"(a[0]), "r"(a[1]), "r"(a[2]), "r"(a[3]), "r"(b[0]), "r"(b[1]));
}

// ---------------- TF32 tensor-core GEMM (unchanged from R5) ----------------
#define ASTRIDE 20
#define BSTRIDE 136

template<bool GELU>
__device__ __forceinline__ void gemm_mma_dev(
    const float* __restrict__ A, const float* __restrict__ W,
    const float* __restrict__ bias, const float* __restrict__ res,
    float* __restrict__ C, int M, int N, int K)
{
    __shared__ uint32_t As[2][128 * ASTRIDE];
    __shared__ uint32_t Bs[2][16 * BSTRIDE];

    const int tid  = threadIdx.x;
    const int warp = tid >> 5;
    const int lane = tid & 31;
    const int g    = lane >> 2;
    const int tig  = lane & 3;
    const int wm   = warp & 1;
    const int wn   = warp >> 1;

    const int m0 = blockIdx.y * 128;
    const int n0 = blockIdx.x * 128;

    const int lrow = tid >> 2;
    const int lcol = (tid & 3) << 2;

    float acc[4][4][4];
    #pragma unroll
    for (int i = 0; i < 4; i++)
        #pragma unroll
        for (int j = 0; j < 4; j++)
            #pragma unroll
            for (int r = 0; r < 4; r++) acc[i][j][r] = 0.f;

    const int NIT = K >> 4;
    float4 aR[2], bR[2];

    {
        const int kb = 0;
        #pragma unroll
        for (int i = 0; i < 2; i++) {
            int ar = lrow + i * 64;
            aR[i] = *reinterpret_cast<const float4*>(&A[(size_t)(m0 + ar) * K + kb + lcol]);
            int brn = n0 + lrow + i * 64;
            bR[i] = (brn < N) ? *reinterpret_cast<const float4*>(&W[(size_t)brn * K + kb + lcol])
                              : make_float4(0.f, 0.f, 0.f, 0.f);
        }
        #pragma unroll
        for (int i = 0; i < 2; i++) {
            int ar = lrow + i * 64;
            uint4 u = make_uint4(f2tf32(aR[i].x), f2tf32(aR[i].y), f2tf32(aR[i].z), f2tf32(aR[i].w));
            *reinterpret_cast<uint4*>(&As[0][ar * ASTRIDE + lcol]) = u;
            int bn = lrow + i * 64;
            Bs[0][(lcol + 0) * BSTRIDE + bn] = f2tf32(bR[i].x);
            Bs[0][(lcol + 1) * BSTRIDE + bn] = f2tf32(bR[i].y);
            Bs[0][(lcol + 2) * BSTRIDE + bn] = f2tf32(bR[i].z);
            Bs[0][(lcol + 3) * BSTRIDE + bn] = f2tf32(bR[i].w);
        }
    }
    __syncthreads();

    for (int it = 0; it < NIT; it++) {
        const int buf = it & 1;
        const bool more = (it + 1) < NIT;
        if (more) {
            const int kb = (it + 1) << 4;
            #pragma unroll
            for (int i = 0; i < 2; i++) {
                int ar = lrow + i * 64;
                aR[i] = *reinterpret_cast<const float4*>(&A[(size_t)(m0 + ar) * K + kb + lcol]);
                int brn = n0 + lrow + i * 64;
                bR[i] = (brn < N) ? *reinterpret_cast<const float4*>(&W[(size_t)brn * K + kb + lcol])
                                  : make_float4(0.f, 0.f, 0.f, 0.f);
            }
        }

        #pragma unroll
        for (int s = 0; s < 2; s++) {
            uint32_t af[4][4];
            #pragma unroll
            for (int mt = 0; mt < 4; mt++) {
                int r0 = wm * 64 + mt * 16 + g;
                int c0 = s * 8 + tig;
                af[mt][0] = As[buf][r0 * ASTRIDE + c0];
                af[mt][1] = As[buf][(r0 + 8) * ASTRIDE + c0];
                af[mt][2] = As[buf][r0 * ASTRIDE + c0 + 4];
                af[mt][3] = As[buf][(r0 + 8) * ASTRIDE + c0 + 4];
            }
            uint32_t bf[4][2];
            #pragma unroll
            for (int nt = 0; nt < 4; nt++) {
                int n = wn * 32 + nt * 8 + g;
                int k0 = s * 8 + tig;
                bf[nt][0] = Bs[buf][k0 * BSTRIDE + n];
                bf[nt][1] = Bs[buf][(k0 + 4) * BSTRIDE + n];
            }
            #pragma unroll
            for (int mt = 0; mt < 4; mt++)
                #pragma unroll
                for (int nt = 0; nt < 4; nt++)
                    mma_tf32(acc[mt][nt], af[mt], bf[nt]);
        }

        if (more) {
            const int nb = buf ^ 1;
            #pragma unroll
            for (int i = 0; i < 2; i++) {
                int ar = lrow + i * 64;
                uint4 u = make_uint4(f2tf32(aR[i].x), f2tf32(aR[i].y), f2tf32(aR[i].z), f2tf32(aR[i].w));
                *reinterpret_cast<uint4*>(&As[nb][ar * ASTRIDE + lcol]) = u;
                int bn = lrow + i * 64;
                Bs[nb][(lcol + 0) * BSTRIDE + bn] = f2tf32(bR[i].x);
                Bs[nb][(lcol + 1) * BSTRIDE + bn] = f2tf32(bR[i].y);
                Bs[nb][(lcol + 2) * BSTRIDE + bn] = f2tf32(bR[i].z);
                Bs[nb][(lcol + 3) * BSTRIDE + bn] = f2tf32(bR[i].w);
            }
        }
        __syncthreads();
    }

    const bool n_even = ((N & 1) == 0);
    #pragma unroll
    for (int mt = 0; mt < 4; mt++) {
        const int r0 = m0 + wm * 64 + mt * 16 + g;
        #pragma unroll
        for (int nt = 0; nt < 4; nt++) {
            const int c = n0 + wn * 32 + nt * 8 + tig * 2;
            #pragma unroll
            for (int half = 0; half < 2; half++) {
                const int m = r0 + half * 8;
                float v0 = acc[mt][nt][half * 2 + 0];
                float v1 = acc[mt][nt][half * 2 + 1];
                if (n_even && (c + 1) < N) {
                    if (bias) { float2 bv = *reinterpret_cast<const float2*>(&bias[c]); v0 += bv.x; v1 += bv.y; }
                    if (res)  { float2 rv = *reinterpret_cast<const float2*>(&res[(size_t)m * N + c]); v0 += rv.x; v1 += rv.y; }
                    if (GELU) { v0 = gelu1(v0); v1 = gelu1(v1); }
                    *reinterpret_cast<float2*>(&C[(size_t)m * N + c]) = make_float2(v0, v1);
                } else {
                    if (c < N) {
                        float val = v0;
                        if (bias) val += bias[c];
                        if (res)  val += res[(size_t)m * N + c];
                        if (GELU) val = gelu1(val);
                        C[(size_t)m * N + c] = val;
                    }
                    if (c + 1 < N) {
                        float val = v1;
                        if (bias) val += bias[c + 1];
                        if (res)  val += res[(size_t)m * N + c + 1];
                        if (GELU) val = gelu1(val);
                        C[(size_t)m * N + c + 1] = val;
                    }
                }
            }
        }
    }
}

template<bool GELU>
__global__ __launch_bounds__(256, 2) void mma_gemm_k(
    const float* __restrict__ A, const float* __restrict__ W,
    const float* __restrict__ bias, const float* __restrict__ res,
    float* __restrict__ C, int M, int N, int K)
{
    gemm_mma_dev<GELU>(A, W, bias, res, C, M, N, K);
}

__global__ __launch_bounds__(256, 2) void mma_gemm_qkv_k(
    const float* __restrict__ A,
    const float* __restrict__ w0, const float* __restrict__ w1, const float* __restrict__ w2,
    float* __restrict__ o0, float* __restrict__ o1, float* __restrict__ o2,
    int M, int N, int K)
{
    const float* W = (blockIdx.z == 0) ? w0 : ((blockIdx.z == 1) ? w1 : w2);
    float* C = (blockIdx.z == 0) ? o0 : ((blockIdx.z == 1) ? o1 : o2);
    gemm_mma_dev<false>(A, W, nullptr, nullptr, C, M, N, K);
}

// ---------------- flash attention: 64-query tile per block ----------------
// 256 threads as 16(tx: keys/cols) x 16(ty: rows). Each thread: 4x4 micro-tile.
// Q,K staged d-major (stride 68); V,P row-major (stride 68). Online softmax.
#define BQ   64
#define BKT  64
#define PSTR 68
#define ATTN_SMEM (4 * BKT * PSTR * sizeof(float))

__global__ __launch_bounds__(256) void flash_attn_kernel(
    const float* __restrict__ q, const float* __restrict__ k,
    const float* __restrict__ v, const int* __restrict__ amask,
    float* __restrict__ out)
{
    extern __shared__ float sm[];
    float* Qs = sm;                  // [d][row]
    float* Ks = Qs + BKT * PSTR;     // [d][col]
    float* Vs = Ks + BKT * PSTR;     // [key][d]
    float* Ps = Vs + BKT * PSTR;     // [row][key]
    __shared__ int msk[BKT];

    const int qt = gridDim.x - 1 - blockIdx.x;   // heavy tiles first
    const int hh = blockIdx.y;
    const int b  = blockIdx.z;
    const int q0 = qt * BQ;
    const int tid = threadIdx.x;
    const int tx = tid & 15, ty = tid >> 4;

    // load Q tile, d-major, pre-scaled
    {
        const int r = tid >> 2;
        const float* gq = q + ((size_t)(b * SEQ + q0 + r)) * HID + hh * HDIM;
        #pragma unroll
        for (int c = 0; c < 4; c++) {
            const int d = ((tid & 3) + c * 4) * 4;
            float4 t4 = *reinterpret_cast<const float4*>(&gq[d]);
            Qs[(d + 0) * PSTR + r] = t4.x * 0.125f;
            Qs[(d + 1) * PSTR + r] = t4.y * 0.125f;
            Qs[(d + 2) * PSTR + r] = t4.z * 0.125f;
            Qs[(d + 3) * PSTR + r] = t4.w * 0.125f;
        }
    }

    float m_i[4], l_i[4], o[4][4];
    #pragma unroll
    for (int i = 0; i < 4; i++) {
        m_i[i] = -1e30f; l_i[i] = 0.f;
        #pragma unroll
        for (int j = 0; j < 4; j++) o[i][j] = 0.f;
    }

    for (int kt = 0; kt <= qt; kt++) {
        __syncthreads();  // protect Ks/Vs from previous iteration's readers
        {
            const int r = tid >> 2;
            const size_t grow = (size_t)(b * SEQ + kt * BKT + r) * HID + hh * HDIM;
            const float* gk = k + grow;
            const float* gv = v + grow;
            #pragma unroll
            for (int c = 0; c < 4; c++) {
                const int d = ((tid & 3) + c * 4) * 4;
                float4 k4 = *reinterpret_cast<const float4*>(&gk[d]);
                Ks[(d + 0) * PSTR + r] = k4.x;
                Ks[(d + 1) * PSTR + r] = k4.y;
                Ks[(d + 2) * PSTR + r] = k4.z;
                Ks[(d + 3) * PSTR + r] = k4.w;
                float4 v4 = *reinterpret_cast<const float4*>(&gv[d]);
                *reinterpret_cast<float4*>(&Vs[r * PSTR + d]) = v4;
            }
            if (tid < BKT) msk[tid] = amask[b * SEQ + kt * BKT + tid];
        }
        __syncthreads();

        // ---- scores S = Q K^T ----
        float s[4][4];
        #pragma unroll
        for (int i = 0; i < 4; i++)
            #pragma unroll
            for (int j = 0; j < 4; j++) s[i][j] = 0.f;

        #pragma unroll 4
        for (int d = 0; d < HDIM; d++) {
            float4 q4 = *reinterpret_cast<const float4*>(&Qs[d * PSTR + ty * 4]);
            float4 k4 = *reinterpret_cast<const float4*>(&Ks[d * PSTR + tx * 4]);
            float qa[4] = {q4.x, q4.y, q4.z, q4.w};
            float ka[4] = {k4.x, k4.y, k4.z, k4.w};
            #pragma unroll
            for (int i = 0; i < 4; i++)
                #pragma unroll
                for (int j = 0; j < 4; j++)
                    s[i][j] = fmaf(qa[i], ka[j], s[i][j]);
        }

        // ---- masking ----
        const bool diag = (kt == qt);
        #pragma unroll
        for (int j = 0; j < 4; j++) {
            const int kj = tx * 4 + j;
            const bool padded = (msk[kj] == 0);
            #pragma unroll
            for (int i = 0; i < 4; i++) {
                const int qi = ty * 4 + i;
                if (padded || (diag && (kt * BKT + kj) > (q0 + qi)))
                    s[i][j] = -1e9f;
            }
        }

        // ---- online softmax update ----
        #pragma unroll
        for (int i = 0; i < 4; i++) {
            float rm = fmaxf(fmaxf(s[i][0], s[i][1]), fmaxf(s[i][2], s[i][3]));
            #pragma unroll
            for (int off = 8; off > 0; off >>= 1)
                rm = fmaxf(rm, __shfl_xor_sync(0xffffffffu, rm, off));
            const float mn = fmaxf(m_i[i], rm);
            const float sc = __expf(m_i[i] - mn);
            float rs = 0.f;
            float p[4];
            #pragma unroll
            for (int j = 0; j < 4; j++) {
                p[j] = __expf(s[i][j] - mn);
                rs += p[j];
            }
            #pragma unroll
            for (int j = 0; j < 4; j++)
                Ps[(ty * 4 + i) * PSTR + tx * 4 + j] = p[j];
            #pragma unroll
            for (int off = 8; off > 0; off >>= 1)
                rs += __shfl_xor_sync(0xffffffffu, rs, off);
            l_i[i] = l_i[i] * sc + rs;
            m_i[i] = mn;
            #pragma unroll
            for (int j = 0; j < 4; j++) o[i][j] *= sc;
        }
        __syncwarp();  // P produced/consumed within the same warp's lanes

        // ---- O += P V ----
        #pragma unroll 4
        for (int kk = 0; kk < BKT; kk += 4) {
            float4 p4[4];
            #pragma unroll
            for (int i = 0; i < 4; i++)
                p4[i] = *reinterpret_cast<const float4*>(&Ps[(ty * 4 + i) * PSTR + kk]);
            float4 v4[4];
            #pragma unroll
            for (int t = 0; t < 4; t++)
                v4[t] = *reinterpret_cast<const float4*>(&Vs[(kk + t) * PSTR + tx * 4]);
            #pragma unroll
            for (int i = 0; i < 4; i++) {
                float pa[4] = {p4[i].x, p4[i].y, p4[i].z, p4[i].w};
                #pragma unroll
                for (int t = 0; t < 4; t++) {
                    o[i][0] = fmaf(pa[t], v4[t].x, o[i][0]);
                    o[i][1] = fmaf(pa[t], v4[t].y, o[i][1]);
                    o[i][2] = fmaf(pa[t], v4[t].z, o[i][2]);
                    o[i][3] = fmaf(pa[t], v4[t].w, o[i][3]);
                }
            }
        }
    }

    // ---- write out ----
    #pragma unroll
    for (int i = 0; i < 4; i++) {
        const float inv = 1.0f / l_i[i];
        float4 ov = make_float4(o[i][0] * inv, o[i][1] * inv, o[i][2] * inv, o[i][3] * inv);
        const size_t off = (size_t)(b * SEQ + q0 + ty * 4 + i) * HID + hh * HDIM + tx * 4;
        *reinterpret_cast<float4*>(&out[off]) = ov;
    }
}

// ---------------- launcher ----------------
extern "C" void kernel_launch(void* const* d_in, const int* in_sizes, int n_in,
                              void* d_out, int out_size) {
    const int*   input_ids = (const int*)d_in[0];
    const int*   attn_mask = (const int*)d_in[1];
    const float* tok_emb   = (const float*)d_in[2];
    const float* pos_emb   = (const float*)d_in[3];
    const float* ln1_w     = (const float*)d_in[4];
    const float* ln1_b     = (const float*)d_in[5];
    const float* qw        = (const float*)d_in[6];
    const float* kw        = (const float*)d_in[7];
    const float* vw        = (const float*)d_in[8];
    const float* ow        = (const float*)d_in[9];
    const float* ob        = (const float*)d_in[10];
    const float* ln2_w     = (const float*)d_in[11];
    const float* ln2_b     = (const float*)d_in[12];
    const float* w1        = (const float*)d_in[13];
    const float* b1        = (const float*)d_in[14];
    const float* w2        = (const float*)d_in[15];
    const float* b2        = (const float*)d_in[16];
    const float* lnf_w     = (const float*)d_in[17];
    const float* lnf_b     = (const float*)d_in[18];
    const float* lm_w      = (const float*)d_in[19];
    float* out = (float*)d_out;

    float *x, *h, *q, *k, *v, *a, *ff;
    cudaGetSymbolAddress((void**)&x,  g_x);
    cudaGetSymbolAddress((void**)&h,  g_h);
    cudaGetSymbolAddress((void**)&q,  g_q);
    cudaGetSymbolAddress((void**)&k,  g_k);
    cudaGetSymbolAddress((void**)&v,  g_v);
    cudaGetSymbolAddress((void**)&a,  g_a);
    cudaGetSymbolAddress((void**)&ff, g_ff);

    cudaFuncSetAttribute(flash_attn_kernel,
                         cudaFuncAttributeMaxDynamicSharedMemorySize, (int)ATTN_SMEM);

    {
        int n = T_TOK * HID;
        embed_kernel<<<(n + 255) / 256, 256>>>(input_ids, tok_emb, pos_emb, x);
    }

    dim3 gqkv(HID / 128, T_TOK / 128, 3);
    dim3 gproj(HID / 128, T_TOK / 128);
    dim3 gff1(FFI / 128, T_TOK / 128);
    dim3 gff2(HID / 128, T_TOK / 128);
    dim3 gattn(SEQ / BQ, NHEAD, BATCH);
    dim3 glm((VOCAB + 127) / 128, T_TOK / 128);

    for (int l = 0; l < NLAYER; l++) {
        const float* l1w = ln1_w + (size_t)l * HID;
        const float* l1b = ln1_b + (size_t)l * HID;
        const float* qwl = qw + (size_t)l * HID * HID;
        const float* kwl = kw + (size_t)l * HID * HID;
        const float* vwl = vw + (size_t)l * HID * HID;
        const float* owl = ow + (size_t)l * HID * HID;
        const float* obl = ob + (size_t)l * HID;
        const float* l2w = ln2_w + (size_t)l * HID;
        const float* l2b = ln2_b + (size_t)l * HID;
        const float* w1l = w1 + (size_t)l * FFI * HID;
        const float* b1l = b1 + (size_t)l * FFI;
        const float* w2l = w2 + (size_t)l * HID * FFI;
        const float* b2l = b2 + (size_t)l * HID;

        layernorm_kernel<<<T_TOK, 256>>>(x, l1w, l1b, h);
        mma_gemm_qkv_k<<<gqkv, 256>>>(h, qwl, kwl, vwl, q, k, v, T_TOK, HID, HID);
        flash_attn_kernel<<<gattn, 256, ATTN_SMEM>>>(q, k, v, attn_mask, a);
        mma_gemm_k<false><<<gproj, 256>>>(a, owl, obl, x, x, T_TOK, HID, HID);

        layernorm_kernel<<<T_TOK, 256>>>(x, l2w, l2b, h);
        mma_gemm_k<true><<<gff1, 256>>>(h, w1l, b1l, nullptr, ff, T_TOK, FFI, HID);
        mma_gemm_k<false><<<gff2, 256>>>(ff, w2l, b2l, x, x, T_TOK, HID, FFI);
    }

    layernorm_kernel<<<T_TOK, 256>>>(x, lnf_w, lnf_b, h);
    mma_gemm_k<false><<<glm, 256>>>(h, lm_w, nullptr, nullptr, out, T_TOK, VOCAB, HID);
}

// round 7
// speedup vs baseline: 4.4636x; 1.1443x over previous
#include <cuda_runtime.h>
#include <math.h>
#include <stdint.h>

#define T_TOK 2048
#define SEQ   1024
#define BATCH 2
#define HID   768
#define NHEAD 12
#define HDIM  64
#define NLAYER 12
#define FFI   3072
#define VOCAB 50257

// ---------------- scratch (device globals: allocation-free) ----------------
__device__ float g_x[T_TOK * HID];
__device__ float g_h[T_TOK * HID];
__device__ float g_q[T_TOK * HID];
__device__ float g_k[T_TOK * HID];
__device__ float g_v[T_TOK * HID];
__device__ float g_a[T_TOK * HID];
__device__ float g_ff[T_TOK * FFI];

// ---------------- embeddings ----------------
__global__ void embed_kernel(const int* __restrict__ ids,
                             const float* __restrict__ tok,
                             const float* __restrict__ pos,
                             float* __restrict__ x) {
    int idx = blockIdx.x * blockDim.x + threadIdx.x;
    if (idx >= T_TOK * HID) return;
    int t = idx / HID;
    int hh = idx - t * HID;
    int s = t % SEQ;
    int id = ids[t];
    x[idx] = tok[(size_t)id * HID + hh] + pos[(size_t)s * HID + hh];
}

// ---------------- layernorm ----------------
__global__ void layernorm_kernel(const float* __restrict__ x,
                                 const float* __restrict__ w,
                                 const float* __restrict__ b,
                                 float* __restrict__ out) {
    int row = blockIdx.x;
    const float* xr = x + (size_t)row * HID;
    float* orow = out + (size_t)row * HID;
    __shared__ float red[32];
    int tid = threadIdx.x, lane = tid & 31, wid = tid >> 5;
    int nwarp = blockDim.x >> 5;

    float s = 0.f;
    for (int i = tid; i < HID; i += blockDim.x) s += xr[i];
    #pragma unroll
    for (int o = 16; o > 0; o >>= 1) s += __shfl_xor_sync(0xffffffffu, s, o);
    if (lane == 0) red[wid] = s;
    __syncthreads();
    float tot = 0.f;
    if (tid < nwarp) tot = red[tid];
    if (wid == 0) {
        #pragma unroll
        for (int o = 16; o > 0; o >>= 1) tot += __shfl_xor_sync(0xffffffffu, tot, o);
        if (lane == 0) red[0] = tot;
    }
    __syncthreads();
    float mean = red[0] / (float)HID;
    __syncthreads();

    float vs = 0.f;
    for (int i = tid; i < HID; i += blockDim.x) {
        float d = xr[i] - mean;
        vs += d * d;
    }
    #pragma unroll
    for (int o = 16; o > 0; o >>= 1) vs += __shfl_xor_sync(0xffffffffu, vs, o);
    if (lane == 0) red[wid] = vs;
    __syncthreads();
    float vt = 0.f;
    if (tid < nwarp) vt = red[tid];
    if (wid == 0) {
        #pragma unroll
        for (int o = 16; o > 0; o >>= 1) vt += __shfl_xor_sync(0xffffffffu, vt, o);
        if (lane == 0) red[0] = vt;
    }
    __syncthreads();
    float inv = rsqrtf(red[0] / (float)HID + 1e-5f);

    for (int i = tid; i < HID; i += blockDim.x)
        orow[i] = (xr[i] - mean) * inv * w[i] + b[i];
}

// ---------------- helpers ----------------
__device__ __forceinline__ float gelu1(float x) {
    return 0.5f * x * (1.0f + erff(x * 0.70710678118654752f));
}
__device__ __forceinline__ uint32_t f2tf32(float f) {
    uint32_t u;
    asm("cvt.rna.tf32.f32 %0, %1;" : "=r"(u) : "f"(f));
    return u;
}
__device__ __forceinline__ void mma_tf32(float d[4], const uint32_t a[4], const uint32_t b[2]) {
    asm volatile(
        "mma.sync.aligned.m16n8k8.row.col.f32.tf32.tf32.f32 "
        "{%0,%1,%2,%3}, {%4,%5,%6,%7}, {%8,%9}, {%0,%1,%2,%3};\n"
        : "+f"(d[0]), "+f"(d[1]), "+f"(d[2]), "+f"(d[3])
        : "r"(a[0]), "r"(a[1]), "r"(a[2]), "r"(a[3]), "r"(b[0]), "r"(b[1]));
}
__device__ __forceinline__ void cp_async16(uint32_t dst, const float* src, int sz) {
    asm volatile("cp.async.cg.shared.global [%0], [%1], 16, %2;\n"
                 :: "r"(dst), "l"(src), "r"(sz));
}
#define CP_COMMIT() asm volatile("cp.async.commit_group;\n" ::: "memory")
#define CP_WAIT2()  asm volatile("cp.async.wait_group 2;\n" ::: "memory")

// ---------------- TF32 tensor-core GEMM, 4-stage cp.async pipeline ----------
// C[M,N] = A[M,K] * W[N,K]^T (+bias)(+res)(+gelu)
// Block 128x128, BK=16, 256 thr (8 warps, warp tile 64x32), smem row-major
// [row][k] stride 20 for BOTH A and B (conflict-free fragment LDS).
#define GSTAGES 4
#define GSTR 20
#define GSTAGE_F (128 * GSTR)
#define GEMM_SMEM (GSTAGES * 2 * GSTAGE_F * (int)sizeof(float))

template<bool GELU>
__device__ __forceinline__ void gemm_mma_dev(
    const float* __restrict__ A, const float* __restrict__ W,
    const float* __restrict__ bias, const float* __restrict__ res,
    float* __restrict__ C, int M, int N, int K)
{
    extern __shared__ float smem[];
    float* sA = smem;                          // [stage][128][GSTR]
    float* sB = smem + GSTAGES * GSTAGE_F;     // [stage][128][GSTR]

    const int tid  = threadIdx.x;
    const int warp = tid >> 5;
    const int lane = tid & 31;
    const int g    = lane >> 2;
    const int tig  = lane & 3;
    const int wm   = warp & 1;
    const int wn   = warp >> 1;

    const int m0 = blockIdx.y * 128;
    const int n0 = blockIdx.x * 128;

    // cp.async mapping: thread -> (row, 8-float chunk)
    const int lrow = tid >> 1;          // 0..127
    const int lk8  = (tid & 1) << 3;    // 0 or 8

    const float* gA = A + (size_t)(m0 + lrow) * K + lk8;
    const int brow = n0 + lrow;
    const int bsz  = (brow < N) ? 16 : 0;
    const float* gB = W + (size_t)(brow < N ? brow : (N - 1)) * K + lk8;

    const uint32_t dA0 = (uint32_t)__cvta_generic_to_shared(sA + lrow * GSTR + lk8);
    const uint32_t dB0 = (uint32_t)__cvta_generic_to_shared(sB + lrow * GSTR + lk8);
    const uint32_t stageB = GSTAGE_F * (uint32_t)sizeof(float);

    float acc[4][4][4];
    #pragma unroll
    for (int i = 0; i < 4; i++)
        #pragma unroll
        for (int j = 0; j < 4; j++)
            #pragma unroll
            for (int r = 0; r < 4; r++) acc[i][j][r] = 0.f;

    const int NIT = K >> 4;

    // prologue: issue stages 0,1,2
    #pragma unroll
    for (int s = 0; s < GSTAGES - 1; s++) {
        if (s < NIT) {
            const int kb = s << 4;
            cp_async16(dA0 + s * stageB, gA + kb, 16);
            cp_async16(dA0 + s * stageB + 16, gA + kb + 4, 16);
            cp_async16(dB0 + s * stageB, gB + kb, bsz);
            cp_async16(dB0 + s * stageB + 16, gB + kb + 4, bsz);
        }
        CP_COMMIT();
    }
    CP_WAIT2();
    __syncthreads();

    for (int it = 0; it < NIT; it++) {
        const int buf = it & 3;   // GSTAGES = 4
        const float* bufA = sA + buf * GSTAGE_F;
        const float* bufB = sB + buf * GSTAGE_F;

        #pragma unroll
        for (int s = 0; s < 2; s++) {
            const int c0 = s * 8 + tig;
            uint32_t af[4][4];
            #pragma unroll
            for (int mt = 0; mt < 4; mt++) {
                const int r0 = wm * 64 + mt * 16 + g;
                af[mt][0] = f2tf32(bufA[r0 * GSTR + c0]);
                af[mt][1] = f2tf32(bufA[(r0 + 8) * GSTR + c0]);
                af[mt][2] = f2tf32(bufA[r0 * GSTR + c0 + 4]);
                af[mt][3] = f2tf32(bufA[(r0 + 8) * GSTR + c0 + 4]);
            }
            uint32_t bf[4][2];
            #pragma unroll
            for (int nt = 0; nt < 4; nt++) {
                const int n = wn * 32 + nt * 8 + g;
                bf[nt][0] = f2tf32(bufB[n * GSTR + c0]);
                bf[nt][1] = f2tf32(bufB[n * GSTR + c0 + 4]);
            }
            #pragma unroll
            for (int mt = 0; mt < 4; mt++)
                #pragma unroll
                for (int nt = 0; nt < 4; nt++)
                    mma_tf32(acc[mt][nt], af[mt], bf[nt]);
        }

        // issue stage it+3
        const int nit = it + GSTAGES - 1;
        if (nit < NIT) {
            const int ns = nit & 3;
            const int kb = nit << 4;
            cp_async16(dA0 + ns * stageB, gA + kb, 16);
            cp_async16(dA0 + ns * stageB + 16, gA + kb + 4, 16);
            cp_async16(dB0 + ns * stageB, gB + kb, bsz);
            cp_async16(dB0 + ns * stageB + 16, gB + kb + 4, bsz);
        }
        CP_COMMIT();
        CP_WAIT2();
        __syncthreads();
    }

    // ---- epilogue ----
    const bool n_even = ((N & 1) == 0);
    #pragma unroll
    for (int mt = 0; mt < 4; mt++) {
        const int r0 = m0 + wm * 64 + mt * 16 + g;
        #pragma unroll
        for (int nt = 0; nt < 4; nt++) {
            const int c = n0 + wn * 32 + nt * 8 + tig * 2;
            #pragma unroll
            for (int half = 0; half < 2; half++) {
                const int m = r0 + half * 8;
                float v0 = acc[mt][nt][half * 2 + 0];
                float v1 = acc[mt][nt][half * 2 + 1];
                if (n_even && (c + 1) < N) {
                    if (bias) { float2 bv = *reinterpret_cast<const float2*>(&bias[c]); v0 += bv.x; v1 += bv.y; }
                    if (res)  { float2 rv = *reinterpret_cast<const float2*>(&res[(size_t)m * N + c]); v0 += rv.x; v1 += rv.y; }
                    if (GELU) { v0 = gelu1(v0); v1 = gelu1(v1); }
                    *reinterpret_cast<float2*>(&C[(size_t)m * N + c]) = make_float2(v0, v1);
                } else {
                    if (c < N) {
                        float val = v0;
                        if (bias) val += bias[c];
                        if (res)  val += res[(size_t)m * N + c];
                        if (GELU) val = gelu1(val);
                        C[(size_t)m * N + c] = val;
                    }
                    if (c + 1 < N) {
                        float val = v1;
                        if (bias) val += bias[c + 1];
                        if (res)  val += res[(size_t)m * N + c + 1];
                        if (GELU) val = gelu1(val);
                        C[(size_t)m * N + c + 1] = val;
                    }
                }
            }
        }
    }
}

template<bool GELU>
__global__ __launch_bounds__(256, 2) void mma_gemm_k(
    const float* __restrict__ A, const float* __restrict__ W,
    const float* __restrict__ bias, const float* __restrict__ res,
    float* __restrict__ C, int M, int N, int K)
{
    gemm_mma_dev<GELU>(A, W, bias, res, C, M, N, K);
}

__global__ __launch_bounds__(256, 2) void mma_gemm_qkv_k(
    const float* __restrict__ A,
    const float* __restrict__ w0, const float* __restrict__ w1, const float* __restrict__ w2,
    float* __restrict__ o0, float* __restrict__ o1, float* __restrict__ o2,
    int M, int N, int K)
{
    const float* W = (blockIdx.z == 0) ? w0 : ((blockIdx.z == 1) ? w1 : w2);
    float* C = (blockIdx.z == 0) ? o0 : ((blockIdx.z == 1) ? o1 : o2);
    gemm_mma_dev<false>(A, W, nullptr, nullptr, C, M, N, K);
}

// ---------------- flash attention: 64-query tile per block (unchanged) ----
#define BQ   64
#define BKT  64
#define PSTR 68
#define ATTN_SMEM (4 * BKT * PSTR * (int)sizeof(float))

__global__ __launch_bounds__(256) void flash_attn_kernel(
    const float* __restrict__ q, const float* __restrict__ k,
    const float* __restrict__ v, const int* __restrict__ amask,
    float* __restrict__ out)
{
    extern __shared__ float sm[];
    float* Qs = sm;                  // [d][row]
    float* Ks = Qs + BKT * PSTR;     // [d][col]
    float* Vs = Ks + BKT * PSTR;     // [key][d]
    float* Ps = Vs + BKT * PSTR;     // [row][key]
    __shared__ int msk[BKT];

    const int qt = gridDim.x - 1 - blockIdx.x;
    const int hh = blockIdx.y;
    const int b  = blockIdx.z;
    const int q0 = qt * BQ;
    const int tid = threadIdx.x;
    const int tx = tid & 15, ty = tid >> 4;

    {
        const int r = tid >> 2;
        const float* gq = q + ((size_t)(b * SEQ + q0 + r)) * HID + hh * HDIM;
        #pragma unroll
        for (int c = 0; c < 4; c++) {
            const int d = ((tid & 3) + c * 4) * 4;
            float4 t4 = *reinterpret_cast<const float4*>(&gq[d]);
            Qs[(d + 0) * PSTR + r] = t4.x * 0.125f;
            Qs[(d + 1) * PSTR + r] = t4.y * 0.125f;
            Qs[(d + 2) * PSTR + r] = t4.z * 0.125f;
            Qs[(d + 3) * PSTR + r] = t4.w * 0.125f;
        }
    }

    float m_i[4], l_i[4], o[4][4];
    #pragma unroll
    for (int i = 0; i < 4; i++) {
        m_i[i] = -1e30f; l_i[i] = 0.f;
        #pragma unroll
        for (int j = 0; j < 4; j++) o[i][j] = 0.f;
    }

    for (int kt = 0; kt <= qt; kt++) {
        __syncthreads();
        {
            const int r = tid >> 2;
            const size_t grow = (size_t)(b * SEQ + kt * BKT + r) * HID + hh * HDIM;
            const float* gk = k + grow;
            const float* gv = v + grow;
            #pragma unroll
            for (int c = 0; c < 4; c++) {
                const int d = ((tid & 3) + c * 4) * 4;
                float4 k4 = *reinterpret_cast<const float4*>(&gk[d]);
                Ks[(d + 0) * PSTR + r] = k4.x;
                Ks[(d + 1) * PSTR + r] = k4.y;
                Ks[(d + 2) * PSTR + r] = k4.z;
                Ks[(d + 3) * PSTR + r] = k4.w;
                float4 v4 = *reinterpret_cast<const float4*>(&gv[d]);
                *reinterpret_cast<float4*>(&Vs[r * PSTR + d]) = v4;
            }
            if (tid < BKT) msk[tid] = amask[b * SEQ + kt * BKT + tid];
        }
        __syncthreads();

        float s[4][4];
        #pragma unroll
        for (int i = 0; i < 4; i++)
            #pragma unroll
            for (int j = 0; j < 4; j++) s[i][j] = 0.f;

        #pragma unroll 4
        for (int d = 0; d < HDIM; d++) {
            float4 q4 = *reinterpret_cast<const float4*>(&Qs[d * PSTR + ty * 4]);
            float4 k4 = *reinterpret_cast<const float4*>(&Ks[d * PSTR + tx * 4]);
            float qa[4] = {q4.x, q4.y, q4.z, q4.w};
            float ka[4] = {k4.x, k4.y, k4.z, k4.w};
            #pragma unroll
            for (int i = 0; i < 4; i++)
                #pragma unroll
                for (int j = 0; j < 4; j++)
                    s[i][j] = fmaf(qa[i], ka[j], s[i][j]);
        }

        const bool diag = (kt == qt);
        #pragma unroll
        for (int j = 0; j < 4; j++) {
            const int kj = tx * 4 + j;
            const bool padded = (msk[kj] == 0);
            #pragma unroll
            for (int i = 0; i < 4; i++) {
                const int qi = ty * 4 + i;
                if (padded || (diag && (kt * BKT + kj) > (q0 + qi)))
                    s[i][j] = -1e9f;
            }
        }

        #pragma unroll
        for (int i = 0; i < 4; i++) {
            float rm = fmaxf(fmaxf(s[i][0], s[i][1]), fmaxf(s[i][2], s[i][3]));
            #pragma unroll
            for (int off = 8; off > 0; off >>= 1)
                rm = fmaxf(rm, __shfl_xor_sync(0xffffffffu, rm, off));
            const float mn = fmaxf(m_i[i], rm);
            const float sc = __expf(m_i[i] - mn);
            float rs = 0.f;
            float p[4];
            #pragma unroll
            for (int j = 0; j < 4; j++) {
                p[j] = __expf(s[i][j] - mn);
                rs += p[j];
            }
            #pragma unroll
            for (int j = 0; j < 4; j++)
                Ps[(ty * 4 + i) * PSTR + tx * 4 + j] = p[j];
            #pragma unroll
            for (int off = 8; off > 0; off >>= 1)
                rs += __shfl_xor_sync(0xffffffffu, rs, off);
            l_i[i] = l_i[i] * sc + rs;
            m_i[i] = mn;
            #pragma unroll
            for (int j = 0; j < 4; j++) o[i][j] *= sc;
        }
        __syncwarp();

        #pragma unroll 4
        for (int kk = 0; kk < BKT; kk += 4) {
            float4 p4[4];
            #pragma unroll
            for (int i = 0; i < 4; i++)
                p4[i] = *reinterpret_cast<const float4*>(&Ps[(ty * 4 + i) * PSTR + kk]);
            float4 v4[4];
            #pragma unroll
            for (int t = 0; t < 4; t++)
                v4[t] = *reinterpret_cast<const float4*>(&Vs[(kk + t) * PSTR + tx * 4]);
            #pragma unroll
            for (int i = 0; i < 4; i++) {
                float pa[4] = {p4[i].x, p4[i].y, p4[i].z, p4[i].w};
                #pragma unroll
                for (int t = 0; t < 4; t++) {
                    o[i][0] = fmaf(pa[t], v4[t].x, o[i][0]);
                    o[i][1] = fmaf(pa[t], v4[t].y, o[i][1]);
                    o[i][2] = fmaf(pa[t], v4[t].z, o[i][2]);
                    o[i][3] = fmaf(pa[t], v4[t].w, o[i][3]);
                }
            }
        }
    }

    #pragma unroll
    for (int i = 0; i < 4; i++) {
        const float inv = 1.0f / l_i[i];
        float4 ov = make_float4(o[i][0] * inv, o[i][1] * inv, o[i][2] * inv, o[i][3] * inv);
        const size_t off = (size_t)(b * SEQ + q0 + ty * 4 + i) * HID + hh * HDIM + tx * 4;
        *reinterpret_cast<float4*>(&out[off]) = ov;
    }
}

// ---------------- launcher ----------------
extern "C" void kernel_launch(void* const* d_in, const int* in_sizes, int n_in,
                              void* d_out, int out_size) {
    const int*   input_ids = (const int*)d_in[0];
    const int*   attn_mask = (const int*)d_in[1];
    const float* tok_emb   = (const float*)d_in[2];
    const float* pos_emb   = (const float*)d_in[3];
    const float* ln1_w     = (const float*)d_in[4];
    const float* ln1_b     = (const float*)d_in[5];
    const float* qw        = (const float*)d_in[6];
    const float* kw        = (const float*)d_in[7];
    const float* vw        = (const float*)d_in[8];
    const float* ow        = (const float*)d_in[9];
    const float* ob        = (const float*)d_in[10];
    const float* ln2_w     = (const float*)d_in[11];
    const float* ln2_b     = (const float*)d_in[12];
    const float* w1        = (const float*)d_in[13];
    const float* b1        = (const float*)d_in[14];
    const float* w2        = (const float*)d_in[15];
    const float* b2        = (const float*)d_in[16];
    const float* lnf_w     = (const float*)d_in[17];
    const float* lnf_b     = (const float*)d_in[18];
    const float* lm_w      = (const float*)d_in[19];
    float* out = (float*)d_out;

    float *x, *h, *q, *k, *v, *a, *ff;
    cudaGetSymbolAddress((void**)&x,  g_x);
    cudaGetSymbolAddress((void**)&h,  g_h);
    cudaGetSymbolAddress((void**)&q,  g_q);
    cudaGetSymbolAddress((void**)&k,  g_k);
    cudaGetSymbolAddress((void**)&v,  g_v);
    cudaGetSymbolAddress((void**)&a,  g_a);
    cudaGetSymbolAddress((void**)&ff, g_ff);

    cudaFuncSetAttribute(flash_attn_kernel,
                         cudaFuncAttributeMaxDynamicSharedMemorySize, ATTN_SMEM);
    cudaFuncSetAttribute(mma_gemm_k<false>,
                         cudaFuncAttributeMaxDynamicSharedMemorySize, GEMM_SMEM);
    cudaFuncSetAttribute(mma_gemm_k<true>,
                         cudaFuncAttributeMaxDynamicSharedMemorySize, GEMM_SMEM);
    cudaFuncSetAttribute(mma_gemm_qkv_k,
                         cudaFuncAttributeMaxDynamicSharedMemorySize, GEMM_SMEM);

    {
        int n = T_TOK * HID;
        embed_kernel<<<(n + 255) / 256, 256>>>(input_ids, tok_emb, pos_emb, x);
    }

    dim3 gqkv(HID / 128, T_TOK / 128, 3);
    dim3 gproj(HID / 128, T_TOK / 128);
    dim3 gff1(FFI / 128, T_TOK / 128);
    dim3 gff2(HID / 128, T_TOK / 128);
    dim3 gattn(SEQ / BQ, NHEAD, BATCH);
    dim3 glm((VOCAB + 127) / 128, T_TOK / 128);

    for (int l = 0; l < NLAYER; l++) {
        const float* l1w = ln1_w + (size_t)l * HID;
        const float* l1b = ln1_b + (size_t)l * HID;
        const float* qwl = qw + (size_t)l * HID * HID;
        const float* kwl = kw + (size_t)l * HID * HID;
        const float* vwl = vw + (size_t)l * HID * HID;
        const float* owl = ow + (size_t)l * HID * HID;
        const float* obl = ob + (size_t)l * HID;
        const float* l2w = ln2_w + (size_t)l * HID;
        const float* l2b = ln2_b + (size_t)l * HID;
        const float* w1l = w1 + (size_t)l * FFI * HID;
        const float* b1l = b1 + (size_t)l * FFI;
        const float* w2l = w2 + (size_t)l * HID * FFI;
        const float* b2l = b2 + (size_t)l * HID;

        layernorm_kernel<<<T_TOK, 256>>>(x, l1w, l1b, h);
        mma_gemm_qkv_k<<<gqkv, 256, GEMM_SMEM>>>(h, qwl, kwl, vwl, q, k, v, T_TOK, HID, HID);
        flash_attn_kernel<<<gattn, 256, ATTN_SMEM>>>(q, k, v, attn_mask, a);
        mma_gemm_k<false><<<gproj, 256, GEMM_SMEM>>>(a, owl, obl, x, x, T_TOK, HID, HID);

        layernorm_kernel<<<T_TOK, 256>>>(x, l2w, l2b, h);
        mma_gemm_k<true><<<gff1, 256, GEMM_SMEM>>>(h, w1l, b1l, nullptr, ff, T_TOK, FFI, HID);
        mma_gemm_k<false><<<gff2, 256, GEMM_SMEM>>>(ff, w2l, b2l, x, x, T_TOK, HID, FFI);
    }

    layernorm_kernel<<<T_TOK, 256>>>(x, lnf_w, lnf_b, h);
    mma_gemm_k<false><<<glm, 256, GEMM_SMEM>>>(h, lm_w, nullptr, nullptr, out, T_TOK, VOCAB, HID);
}

// round 9
// speedup vs baseline: 4.5384x; 1.0168x over previous
#include <cuda_runtime.h>
#include <math.h>
#include <stdint.h>

#define T_TOK 2048
#define SEQ   1024
#define BATCH 2
#define HID   768
#define NHEAD 12
#define HDIM  64
#define NLAYER 12
#define FFI   3072
#define VOCAB 50257

// ---------------- scratch (device globals: allocation-free) ----------------
__device__ float g_x[T_TOK * HID];
__device__ float g_h[T_TOK * HID];
__device__ float g_q[T_TOK * HID];
__device__ float g_k[T_TOK * HID];
__device__ float g_v[T_TOK * HID];
__device__ float g_a[T_TOK * HID];
__device__ float g_ff[T_TOK * FFI];
// tf32-rounded weight copies
__device__ float g_wq[NLAYER * HID * HID];
__device__ float g_wk[NLAYER * HID * HID];
__device__ float g_wv[NLAYER * HID * HID];
__device__ float g_wo[NLAYER * HID * HID];
__device__ float g_w1[NLAYER * FFI * HID];
__device__ float g_w2[NLAYER * HID * FFI];
__device__ float g_wlm[VOCAB * HID];

// ---------------- helpers ----------------
__device__ __forceinline__ float gelu1(float x) {
    return 0.5f * x * (1.0f + erff(x * 0.70710678118654752f));
}
__device__ __forceinline__ uint32_t f2tf32(float f) {
    uint32_t u;
    asm("cvt.rna.tf32.f32 %0, %1;" : "=r"(u) : "f"(f));
    return u;
}
__device__ __forceinline__ float r2t(float f) { return __uint_as_float(f2tf32(f)); }

__device__ __forceinline__ void mma_tf32(float d[4], const uint32_t a[4], const uint32_t b[2]) {
    asm volatile(
        "mma.sync.aligned.m16n8k8.row.col.f32.tf32.tf32.f32 "
        "{%0,%1,%2,%3}, {%4,%5,%6,%7}, {%8,%9}, {%0,%1,%2,%3};\n"
        : "+f"(d[0]), "+f"(d[1]), "+f"(d[2]), "+f"(d[3])
        : "r"(a[0]), "r"(a[1]), "r"(a[2]), "r"(a[3]), "r"(b[0]), "r"(b[1]));
}
__device__ __forceinline__ void cp_async16(uint32_t dst, const float* src, int sz) {
    asm volatile("cp.async.cg.shared.global [%0], [%1], 16, %2;\n"
                 :: "r"(dst), "l"(src), "r"(sz));
}
#define CP_COMMIT() asm volatile("cp.async.commit_group;\n" ::: "memory")
#define CP_WAIT2()  asm volatile("cp.async.wait_group 2;\n" ::: "memory")

// ---------------- embeddings ----------------
__global__ void embed_kernel(const int* __restrict__ ids,
                             const float* __restrict__ tok,
                             const float* __restrict__ pos,
                             float* __restrict__ x) {
    int idx = blockIdx.x * blockDim.x + threadIdx.x;
    if (idx >= T_TOK * HID) return;
    int t = idx / HID;
    int hh = idx - t * HID;
    int s = t % SEQ;
    int id = ids[t];
    x[idx] = tok[(size_t)id * HID + hh] + pos[(size_t)s * HID + hh];
}

// ---------------- tf32-rounding weight copy ----------------
__global__ void cvt_tf32_k(const float* __restrict__ in, float* __restrict__ outp, int n4) {
    int i = blockIdx.x * blockDim.x + threadIdx.x;
    if (i >= n4) return;
    float4 v = reinterpret_cast<const float4*>(in)[i];
    v.x = r2t(v.x); v.y = r2t(v.y); v.z = r2t(v.z); v.w = r2t(v.w);
    reinterpret_cast<float4*>(outp)[i] = v;
}

// ---------------- layernorm (tf32-rounded output: feeds GEMMs only) -------
__global__ void layernorm_kernel(const float* __restrict__ x,
                                 const float* __restrict__ w,
                                 const float* __restrict__ b,
                                 float* __restrict__ out) {
    int row = blockIdx.x;
    const float* xr = x + (size_t)row * HID;
    float* orow = out + (size_t)row * HID;
    __shared__ float red[32];
    int tid = threadIdx.x, lane = tid & 31, wid = tid >> 5;
    int nwarp = blockDim.x >> 5;

    float s = 0.f;
    for (int i = tid; i < HID; i += blockDim.x) s += xr[i];
    #pragma unroll
    for (int o = 16; o > 0; o >>= 1) s += __shfl_xor_sync(0xffffffffu, s, o);
    if (lane == 0) red[wid] = s;
    __syncthreads();
    float tot = 0.f;
    if (tid < nwarp) tot = red[tid];
    if (wid == 0) {
        #pragma unroll
        for (int o = 16; o > 0; o >>= 1) tot += __shfl_xor_sync(0xffffffffu, tot, o);
        if (lane == 0) red[0] = tot;
    }
    __syncthreads();
    float mean = red[0] / (float)HID;
    __syncthreads();

    float vs = 0.f;
    for (int i = tid; i < HID; i += blockDim.x) {
        float d = xr[i] - mean;
        vs += d * d;
    }
    #pragma unroll
    for (int o = 16; o > 0; o >>= 1) vs += __shfl_xor_sync(0xffffffffu, vs, o);
    if (lane == 0) red[wid] = vs;
    __syncthreads();
    float vt = 0.f;
    if (tid < nwarp) vt = red[tid];
    if (wid == 0) {
        #pragma unroll
        for (int o = 16; o > 0; o >>= 1) vt += __shfl_xor_sync(0xffffffffu, vt, o);
        if (lane == 0) red[0] = vt;
    }
    __syncthreads();
    float inv = rsqrtf(red[0] / (float)HID + 1e-5f);

    for (int i = tid; i < HID; i += blockDim.x)
        orow[i] = r2t((xr[i] - mean) * inv * w[i] + b[i]);
}

// ---------------- TF32 mma GEMM, 4-stage cp.async, templated BM -----------
// C[M,N] = A[M,K] * W[N,K]^T (+bias)(+res)(+gelu)(+round)
// Inputs MUST be pre-rounded to tf32 (low 13 mantissa bits zero).
// BM in {128, 64}; BN = 128; BK = 16; 256 threads.
#define GSTAGES 4
#define GSTR 20

template<int BM, bool GELU, bool ROUND>
__device__ __forceinline__ void gemm_mma_dev(
    const float* __restrict__ A, const float* __restrict__ W,
    const float* __restrict__ bias, const float* __restrict__ res,
    float* __restrict__ C, int M, int N, int K)
{
    extern __shared__ float smem[];
    constexpr int STAGEF = (BM + 128) * GSTR;
    constexpr int MT = BM / 32;          // m-tiles per warp (4 or 2)
    constexpr int WMROWS = BM / 2;       // rows per wm slice

    const int tid  = threadIdx.x;
    const int warp = tid >> 5;
    const int lane = tid & 31;
    const int g    = lane >> 2;
    const int tig  = lane & 3;
    const int wm   = warp & 1;
    const int wn   = warp >> 1;

    const int m0 = blockIdx.y * BM;
    const int n0 = blockIdx.x * 128;

    // ---- global->smem load mapping ----
    // B: 128 rows x 16k, 256 thr -> row=tid>>1, k8=(tid&1)*8, two cp16
    const int brl = tid >> 1;
    const int bk8 = (tid & 1) << 3;
    const int bn  = n0 + brl;
    const int bsz = (bn < N) ? 16 : 0;
    const float* gB = W + (size_t)(bn < N ? bn : 0) * K + bk8;
    const uint32_t dB = (uint32_t)__cvta_generic_to_shared(smem + BM * GSTR + brl * GSTR + bk8);

    const float* gA;
    uint32_t dA;
    if constexpr (BM == 128) {
        gA = A + (size_t)(m0 + brl) * K + bk8;
        dA = (uint32_t)__cvta_generic_to_shared(smem + brl * GSTR + bk8);
    } else {
        const int arow = tid >> 2;
        const int ak4  = (tid & 3) << 2;
        gA = A + (size_t)(m0 + arow) * K + ak4;
        dA = (uint32_t)__cvta_generic_to_shared(smem + arow * GSTR + ak4);
    }
    const uint32_t stageB = STAGEF * (uint32_t)sizeof(float);

    float acc[MT][4][4];
    #pragma unroll
    for (int i = 0; i < MT; i++)
        #pragma unroll
        for (int j = 0; j < 4; j++)
            #pragma unroll
            for (int r = 0; r < 4; r++) acc[i][j][r] = 0.f;

    const int NIT = K >> 4;

    #define FILLG(it_) do { \
        const uint32_t _o = ((it_) & 3) * stageB; \
        const int _kb = (it_) << 4; \
        if constexpr (BM == 128) { \
            cp_async16(dA + _o, gA + _kb, 16); \
            cp_async16(dA + _o + 16, gA + _kb + 4, 16); \
        } else { \
            cp_async16(dA + _o, gA + _kb, 16); \
        } \
        cp_async16(dB + _o, gB + _kb, bsz); \
        cp_async16(dB + _o + 16, gB + _kb + 4, bsz); \
    } while (0)

    #pragma unroll
    for (int s = 0; s < GSTAGES - 1; s++) {
        if (s < NIT) FILLG(s);
        CP_COMMIT();
    }
    CP_WAIT2();
    __syncthreads();

    for (int it = 0; it < NIT; it++) {
        const int buf = it & 3;
        const uint32_t* bufA = reinterpret_cast<const uint32_t*>(smem + buf * STAGEF);
        const uint32_t* bufB = bufA + BM * GSTR;

        #pragma unroll
        for (int s = 0; s < 2; s++) {
            const int c0 = s * 8 + tig;
            uint32_t af[MT][4];
            #pragma unroll
            for (int mt = 0; mt < MT; mt++) {
                const int r0 = wm * WMROWS + mt * 16 + g;
                af[mt][0] = bufA[r0 * GSTR + c0];
                af[mt][1] = bufA[(r0 + 8) * GSTR + c0];
                af[mt][2] = bufA[r0 * GSTR + c0 + 4];
                af[mt][3] = bufA[(r0 + 8) * GSTR + c0 + 4];
            }
            uint32_t bf[4][2];
            #pragma unroll
            for (int nt = 0; nt < 4; nt++) {
                const int n = wn * 32 + nt * 8 + g;
                bf[nt][0] = bufB[n * GSTR + c0];
                bf[nt][1] = bufB[n * GSTR + c0 + 4];
            }
            #pragma unroll
            for (int mt = 0; mt < MT; mt++)
                #pragma unroll
                for (int nt = 0; nt < 4; nt++)
                    mma_tf32(acc[mt][nt], af[mt], bf[nt]);
        }

        const int nit = it + GSTAGES - 1;
        if (nit < NIT) FILLG(nit);
        CP_COMMIT();
        CP_WAIT2();
        __syncthreads();
    }
    #undef FILLG

    // ---- epilogue ----
    const bool n_even = ((N & 1) == 0);
    #pragma unroll
    for (int mt = 0; mt < MT; mt++) {
        const int r0 = m0 + wm * WMROWS + mt * 16 + g;
        #pragma unroll
        for (int nt = 0; nt < 4; nt++) {
            const int c = n0 + wn * 32 + nt * 8 + tig * 2;
            #pragma unroll
            for (int half = 0; half < 2; half++) {
                const int m = r0 + half * 8;
                float v0 = acc[mt][nt][half * 2 + 0];
                float v1 = acc[mt][nt][half * 2 + 1];
                if (n_even && (c + 1) < N) {
                    if (bias) { float2 bv = *reinterpret_cast<const float2*>(&bias[c]); v0 += bv.x; v1 += bv.y; }
                    if (res)  { float2 rv = *reinterpret_cast<const float2*>(&res[(size_t)m * N + c]); v0 += rv.x; v1 += rv.y; }
                    if (GELU) { v0 = gelu1(v0); v1 = gelu1(v1); }
                    if (ROUND) { v0 = r2t(v0); v1 = r2t(v1); }
                    *reinterpret_cast<float2*>(&C[(size_t)m * N + c]) = make_float2(v0, v1);
                } else {
                    if (c < N) {
                        float val = v0;
                        if (bias) val += bias[c];
                        if (res)  val += res[(size_t)m * N + c];
                        if (GELU) val = gelu1(val);
                        if (ROUND) val = r2t(val);
                        C[(size_t)m * N + c] = val;
                    }
                    if (c + 1 < N) {
                        float val = v1;
                        if (bias) val += bias[c + 1];
                        if (res)  val += res[(size_t)m * N + c + 1];
                        if (GELU) val = gelu1(val);
                        if (ROUND) val = r2t(val);
                        C[(size_t)m * N + c + 1] = val;
                    }
                }
            }
        }
    }
}

template<int BM, bool GELU, bool ROUND>
__global__ __launch_bounds__(256, 2) void mma_gemm_k(
    const float* __restrict__ A, const float* __restrict__ W,
    const float* __restrict__ bias, const float* __restrict__ res,
    float* __restrict__ C, int M, int N, int K)
{
    gemm_mma_dev<BM, GELU, ROUND>(A, W, bias, res, C, M, N, K);
}

__global__ __launch_bounds__(256, 2) void mma_gemm_qkv_k(
    const float* __restrict__ A,
    const float* __restrict__ w0, const float* __restrict__ w1, const float* __restrict__ w2,
    float* __restrict__ o0, float* __restrict__ o1, float* __restrict__ o2,
    int M, int N, int K)
{
    const float* W = (blockIdx.z == 0) ? w0 : ((blockIdx.z == 1) ? w1 : w2);
    float* C = (blockIdx.z == 0) ? o0 : ((blockIdx.z == 1) ? o1 : o2);
    gemm_mma_dev<128, false, false>(A, W, nullptr, nullptr, C, M, N, K);
}

#define GEMM_SMEM_128 (GSTAGES * (128 + 128) * GSTR * (int)sizeof(float))
#define GEMM_SMEM_64  (GSTAGES * (64 + 128) * GSTR * (int)sizeof(float))

// ---------------- flash attention (tf32-rounded output -> proj GEMM) ------
#define BQ   64
#define BKT  64
#define PSTR 68
#define ATTN_SMEM (4 * BKT * PSTR * (int)sizeof(float))

__global__ __launch_bounds__(256) void flash_attn_kernel(
    const float* __restrict__ q, const float* __restrict__ k,
    const float* __restrict__ v, const int* __restrict__ amask,
    float* __restrict__ out)
{
    extern __shared__ float sm[];
    float* Qs = sm;
    float* Ks = Qs + BKT * PSTR;
    float* Vs = Ks + BKT * PSTR;
    float* Ps = Vs + BKT * PSTR;
    __shared__ int msk[BKT];

    const int qt = gridDim.x - 1 - blockIdx.x;
    const int hh = blockIdx.y;
    const int b  = blockIdx.z;
    const int q0 = qt * BQ;
    const int tid = threadIdx.x;
    const int tx = tid & 15, ty = tid >> 4;

    {
        const int r = tid >> 2;
        const float* gq = q + ((size_t)(b * SEQ + q0 + r)) * HID + hh * HDIM;
        #pragma unroll
        for (int c = 0; c < 4; c++) {
            const int d = ((tid & 3) + c * 4) * 4;
            float4 t4 = *reinterpret_cast<const float4*>(&gq[d]);
            Qs[(d + 0) * PSTR + r] = t4.x * 0.125f;
            Qs[(d + 1) * PSTR + r] = t4.y * 0.125f;
            Qs[(d + 2) * PSTR + r] = t4.z * 0.125f;
            Qs[(d + 3) * PSTR + r] = t4.w * 0.125f;
        }
    }

    float m_i[4], l_i[4], o[4][4];
    #pragma unroll
    for (int i = 0; i < 4; i++) {
        m_i[i] = -1e30f; l_i[i] = 0.f;
        #pragma unroll
        for (int j = 0; j < 4; j++) o[i][j] = 0.f;
    }

    for (int kt = 0; kt <= qt; kt++) {
        __syncthreads();
        {
            const int r = tid >> 2;
            const size_t grow = (size_t)(b * SEQ + kt * BKT + r) * HID + hh * HDIM;
            const float* gk = k + grow;
            const float* gv = v + grow;
            #pragma unroll
            for (int c = 0; c < 4; c++) {
                const int d = ((tid & 3) + c * 4) * 4;
                float4 k4 = *reinterpret_cast<const float4*>(&gk[d]);
                Ks[(d + 0) * PSTR + r] = k4.x;
                Ks[(d + 1) * PSTR + r] = k4.y;
                Ks[(d + 2) * PSTR + r] = k4.z;
                Ks[(d + 3) * PSTR + r] = k4.w;
                float4 v4 = *reinterpret_cast<const float4*>(&gv[d]);
                *reinterpret_cast<float4*>(&Vs[r * PSTR + d]) = v4;
            }
            if (tid < BKT) msk[tid] = amask[b * SEQ + kt * BKT + tid];
        }
        __syncthreads();

        float s[4][4];
        #pragma unroll
        for (int i = 0; i < 4; i++)
            #pragma unroll
            for (int j = 0; j < 4; j++) s[i][j] = 0.f;

        #pragma unroll 4
        for (int d = 0; d < HDIM; d++) {
            float4 q4 = *reinterpret_cast<const float4*>(&Qs[d * PSTR + ty * 4]);
            float4 k4 = *reinterpret_cast<const float4*>(&Ks[d * PSTR + tx * 4]);
            float qa[4] = {q4.x, q4.y, q4.z, q4.w};
            float ka[4] = {k4.x, k4.y, k4.z, k4.w};
            #pragma unroll
            for (int i = 0; i < 4; i++)
                #pragma unroll
                for (int j = 0; j < 4; j++)
                    s[i][j] = fmaf(qa[i], ka[j], s[i][j]);
        }

        const bool diag = (kt == qt);
        #pragma unroll
        for (int j = 0; j < 4; j++) {
            const int kj = tx * 4 + j;
            const bool padded = (msk[kj] == 0);
            #pragma unroll
            for (int i = 0; i < 4; i++) {
                const int qi = ty * 4 + i;
                if (padded || (diag && (kt * BKT + kj) > (q0 + qi)))
                    s[i][j] = -1e9f;
            }
        }

        #pragma unroll
        for (int i = 0; i < 4; i++) {
            float rm = fmaxf(fmaxf(s[i][0], s[i][1]), fmaxf(s[i][2], s[i][3]));
            #pragma unroll
            for (int off = 8; off > 0; off >>= 1)
                rm = fmaxf(rm, __shfl_xor_sync(0xffffffffu, rm, off));
            const float mn = fmaxf(m_i[i], rm);
            const float sc = __expf(m_i[i] - mn);
            float rs = 0.f;
            float p[4];
            #pragma unroll
            for (int j = 0; j < 4; j++) {
                p[j] = __expf(s[i][j] - mn);
                rs += p[j];
            }
            #pragma unroll
            for (int j = 0; j < 4; j++)
                Ps[(ty * 4 + i) * PSTR + tx * 4 + j] = p[j];
            #pragma unroll
            for (int off = 8; off > 0; off >>= 1)
                rs += __shfl_xor_sync(0xffffffffu, rs, off);
            l_i[i] = l_i[i] * sc + rs;
            m_i[i] = mn;
            #pragma unroll
            for (int j = 0; j < 4; j++) o[i][j] *= sc;
        }
        __syncwarp();

        #pragma unroll 4
        for (int kk = 0; kk < BKT; kk += 4) {
            float4 p4[4];
            #pragma unroll
            for (int i = 0; i < 4; i++)
                p4[i] = *reinterpret_cast<const float4*>(&Ps[(ty * 4 + i) * PSTR + kk]);
            float4 v4[4];
            #pragma unroll
            for (int t = 0; t < 4; t++)
                v4[t] = *reinterpret_cast<const float4*>(&Vs[(kk + t) * PSTR + tx * 4]);
            #pragma unroll
            for (int i = 0; i < 4; i++) {
                float pa[4] = {p4[i].x, p4[i].y, p4[i].z, p4[i].w};
                #pragma unroll
                for (int t = 0; t < 4; t++) {
                    o[i][0] = fmaf(pa[t], v4[t].x, o[i][0]);
                    o[i][1] = fmaf(pa[t], v4[t].y, o[i][1]);
                    o[i][2] = fmaf(pa[t], v4[t].z, o[i][2]);
                    o[i][3] = fmaf(pa[t], v4[t].w, o[i][3]);
                }
            }
        }
    }

    #pragma unroll
    for (int i = 0; i < 4; i++) {
        const float inv = 1.0f / l_i[i];
        float4 ov = make_float4(r2t(o[i][0] * inv), r2t(o[i][1] * inv),
                                r2t(o[i][2] * inv), r2t(o[i][3] * inv));
        const size_t off = (size_t)(b * SEQ + q0 + ty * 4 + i) * HID + hh * HDIM + tx * 4;
        *reinterpret_cast<float4*>(&out[off]) = ov;
    }
}

// ---------------- launcher ----------------
extern "C" void kernel_launch(void* const* d_in, const int* in_sizes, int n_in,
                              void* d_out, int out_size) {
    const int*   input_ids = (const int*)d_in[0];
    const int*   attn_mask = (const int*)d_in[1];
    const float* tok_emb   = (const float*)d_in[2];
    const float* pos_emb   = (const float*)d_in[3];
    const float* ln1_w     = (const float*)d_in[4];
    const float* ln1_b     = (const float*)d_in[5];
    const float* qw        = (const float*)d_in[6];
    const float* kw        = (const float*)d_in[7];
    const float* vw        = (const float*)d_in[8];
    const float* ow        = (const float*)d_in[9];
    const float* ob        = (const float*)d_in[10];
    const float* ln2_w     = (const float*)d_in[11];
    const float* ln2_b     = (const float*)d_in[12];
    const float* w1        = (const float*)d_in[13];
    const float* b1        = (const float*)d_in[14];
    const float* w2        = (const float*)d_in[15];
    const float* b2        = (const float*)d_in[16];
    const float* lnf_w     = (const float*)d_in[17];
    const float* lnf_b     = (const float*)d_in[18];
    const float* lm_w      = (const float*)d_in[19];
    float* out = (float*)d_out;

    float *x, *h, *q, *k, *v, *a, *ff;
    float *wq, *wk, *wv, *wo, *cw1, *cw2, *wlm;
    cudaGetSymbolAddress((void**)&x,  g_x);
    cudaGetSymbolAddress((void**)&h,  g_h);
    cudaGetSymbolAddress((void**)&q,  g_q);
    cudaGetSymbolAddress((void**)&k,  g_k);
    cudaGetSymbolAddress((void**)&v,  g_v);
    cudaGetSymbolAddress((void**)&a,  g_a);
    cudaGetSymbolAddress((void**)&ff, g_ff);
    cudaGetSymbolAddress((void**)&wq, g_wq);
    cudaGetSymbolAddress((void**)&wk, g_wk);
    cudaGetSymbolAddress((void**)&wv, g_wv);
    cudaGetSymbolAddress((void**)&wo, g_wo);
    cudaGetSymbolAddress((void**)&cw1, g_w1);
    cudaGetSymbolAddress((void**)&cw2, g_w2);
    cudaGetSymbolAddress((void**)&wlm, g_wlm);

    cudaFuncSetAttribute(flash_attn_kernel,
                         cudaFuncAttributeMaxDynamicSharedMemorySize, ATTN_SMEM);
    cudaFuncSetAttribute((const void*)mma_gemm_k<128, false, false>,
                         cudaFuncAttributeMaxDynamicSharedMemorySize, GEMM_SMEM_128);
    cudaFuncSetAttribute((const void*)mma_gemm_k<128, true, true>,
                         cudaFuncAttributeMaxDynamicSharedMemorySize, GEMM_SMEM_128);
    cudaFuncSetAttribute((const void*)mma_gemm_k<64, false, false>,
                         cudaFuncAttributeMaxDynamicSharedMemorySize, GEMM_SMEM_64);
    cudaFuncSetAttribute((const void*)mma_gemm_qkv_k,
                         cudaFuncAttributeMaxDynamicSharedMemorySize, GEMM_SMEM_128);

    // one-time-per-launch weight rounding (tf32 rna)
    {
        const int nqk = NLAYER * HID * HID / 4;
        cvt_tf32_k<<<(nqk + 255) / 256, 256>>>(qw, wq, nqk);
        cvt_tf32_k<<<(nqk + 255) / 256, 256>>>(kw, wk, nqk);
        cvt_tf32_k<<<(nqk + 255) / 256, 256>>>(vw, wv, nqk);
        cvt_tf32_k<<<(nqk + 255) / 256, 256>>>(ow, wo, nqk);
        const int nff = NLAYER * FFI * HID / 4;
        cvt_tf32_k<<<(nff + 255) / 256, 256>>>(w1, cw1, nff);
        cvt_tf32_k<<<(nff + 255) / 256, 256>>>(w2, cw2, nff);
        const int nlm = VOCAB * HID / 4;
        cvt_tf32_k<<<(nlm + 255) / 256, 256>>>(lm_w, wlm, nlm);
    }

    {
        int n = T_TOK * HID;
        embed_kernel<<<(n + 255) / 256, 256>>>(input_ids, tok_emb, pos_emb, x);
    }

    dim3 gqkv(HID / 128, T_TOK / 128, 3);    // 288 blocks
    dim3 gproj(HID / 128, T_TOK / 64);       // 6 x 32 = 192 blocks (BM=64)
    dim3 gff1(FFI / 128, T_TOK / 128);       // 384 blocks
    dim3 gff2(HID / 128, T_TOK / 64);        // 192 blocks (BM=64)
    dim3 gattn(SEQ / BQ, NHEAD, BATCH);
    dim3 glm((VOCAB + 127) / 128, T_TOK / 128);

    for (int l = 0; l < NLAYER; l++) {
        const float* l1w = ln1_w + (size_t)l * HID;
        const float* l1b = ln1_b + (size_t)l * HID;
        const float* qwl = wq + (size_t)l * HID * HID;
        const float* kwl = wk + (size_t)l * HID * HID;
        const float* vwl = wv + (size_t)l * HID * HID;
        const float* owl = wo + (size_t)l * HID * HID;
        const float* obl = ob + (size_t)l * HID;
        const float* l2w = ln2_w + (size_t)l * HID;
        const float* l2b = ln2_b + (size_t)l * HID;
        const float* w1l = cw1 + (size_t)l * FFI * HID;
        const float* b1l = b1 + (size_t)l * FFI;
        const float* w2l = cw2 + (size_t)l * HID * FFI;
        const float* b2l = b2 + (size_t)l * HID;

        layernorm_kernel<<<T_TOK, 256>>>(x, l1w, l1b, h);
        mma_gemm_qkv_k<<<gqkv, 256, GEMM_SMEM_128>>>(h, qwl, kwl, vwl, q, k, v, T_TOK, HID, HID);
        flash_attn_kernel<<<gattn, 256, ATTN_SMEM>>>(q, k, v, attn_mask, a);
        mma_gemm_k<64, false, false><<<gproj, 256, GEMM_SMEM_64>>>(a, owl, obl, x, x, T_TOK, HID, HID);

        layernorm_kernel<<<T_TOK, 256>>>(x, l2w, l2b, h);
        mma_gemm_k<128, true, true><<<gff1, 256, GEMM_SMEM_128>>>(h, w1l, b1l, nullptr, ff, T_TOK, FFI, HID);
        mma_gemm_k<64, false, false><<<gff2, 256, GEMM_SMEM_64>>>(ff, w2l, b2l, x, x, T_TOK, HID, FFI);
    }

    layernorm_kernel<<<T_TOK, 256>>>(x, lnf_w, lnf_b, h);
    mma_gemm_k<128, false, false><<<glm, 256, GEMM_SMEM_128>>>(h, wlm, nullptr, nullptr, out, T_TOK, VOCAB, HID);
}

// round 10
// speedup vs baseline: 6.3198x; 1.3925x over previous
#include <cuda_runtime.h>
#include <cuda_fp16.h>
#include <math.h>
#include <stdint.h>

#define T_TOK 2048
#define SEQ   1024
#define BATCH 2
#define HID   768
#define NHEAD 12
#define HDIM  64
#define NLAYER 12
#define FFI   3072
#define VOCAB 50257

// ---------------- scratch (device globals: allocation-free) ----------------
__device__ float  g_x[T_TOK * HID];
__device__ __half g_h[T_TOK * HID];
__device__ float  g_q[T_TOK * HID];
__device__ float  g_k[T_TOK * HID];
__device__ float  g_v[T_TOK * HID];
__device__ __half g_a[T_TOK * HID];
__device__ __half g_ff[T_TOK * FFI];
// fp16 weight copies
__device__ __half g_wq[NLAYER * HID * HID];
__device__ __half g_wk[NLAYER * HID * HID];
__device__ __half g_wv[NLAYER * HID * HID];
__device__ __half g_wo[NLAYER * HID * HID];
__device__ __half g_w1[NLAYER * FFI * HID];
__device__ __half g_w2[NLAYER * HID * FFI];
__device__ __half g_wlm[VOCAB * HID];

// ---------------- helpers ----------------
__device__ __forceinline__ float gelu1(float x) {
    return 0.5f * x * (1.0f + erff(x * 0.70710678118654752f));
}
__device__ __forceinline__ void mma_f16(float d[4], const uint32_t a[4], const uint32_t b[2]) {
    asm volatile(
        "mma.sync.aligned.m16n8k16.row.col.f32.f16.f16.f32 "
        "{%0,%1,%2,%3}, {%4,%5,%6,%7}, {%8,%9}, {%0,%1,%2,%3};\n"
        : "+f"(d[0]), "+f"(d[1]), "+f"(d[2]), "+f"(d[3])
        : "r"(a[0]), "r"(a[1]), "r"(a[2]), "r"(a[3]), "r"(b[0]), "r"(b[1]));
}
__device__ __forceinline__ void cp_async16(uint32_t dst, const void* src, int sz) {
    asm volatile("cp.async.cg.shared.global [%0], [%1], 16, %2;\n"
                 :: "r"(dst), "l"(src), "r"(sz));
}
#define CP_COMMIT() asm volatile("cp.async.commit_group;\n" ::: "memory")
#define CP_WAIT2()  asm volatile("cp.async.wait_group 2;\n" ::: "memory")

// ---------------- embeddings ----------------
__global__ void embed_kernel(const int* __restrict__ ids,
                             const float* __restrict__ tok,
                             const float* __restrict__ pos,
                             float* __restrict__ x) {
    int idx = blockIdx.x * blockDim.x + threadIdx.x;
    if (idx >= T_TOK * HID) return;
    int t = idx / HID;
    int hh = idx - t * HID;
    int s = t % SEQ;
    int id = ids[t];
    x[idx] = tok[(size_t)id * HID + hh] + pos[(size_t)s * HID + hh];
}

// ---------------- fp16 weight copy ----------------
__global__ void cvt_half_k(const float* __restrict__ in, __half* __restrict__ outp, int n2) {
    int i = blockIdx.x * blockDim.x + threadIdx.x;
    if (i >= n2) return;
    float2 v = reinterpret_cast<const float2*>(in)[i];
    reinterpret_cast<__half2*>(outp)[i] = __floats2half2_rn(v.x, v.y);
}

// ---------------- layernorm (fp16 output: feeds GEMMs) ----------------
__global__ void layernorm_kernel(const float* __restrict__ x,
                                 const float* __restrict__ w,
                                 const float* __restrict__ b,
                                 __half* __restrict__ out) {
    int row = blockIdx.x;
    const float* xr = x + (size_t)row * HID;
    __half* orow = out + (size_t)row * HID;
    __shared__ float red[32];
    int tid = threadIdx.x, lane = tid & 31, wid = tid >> 5;
    int nwarp = blockDim.x >> 5;

    float s = 0.f;
    for (int i = tid; i < HID; i += blockDim.x) s += xr[i];
    #pragma unroll
    for (int o = 16; o > 0; o >>= 1) s += __shfl_xor_sync(0xffffffffu, s, o);
    if (lane == 0) red[wid] = s;
    __syncthreads();
    float tot = 0.f;
    if (tid < nwarp) tot = red[tid];
    if (wid == 0) {
        #pragma unroll
        for (int o = 16; o > 0; o >>= 1) tot += __shfl_xor_sync(0xffffffffu, tot, o);
        if (lane == 0) red[0] = tot;
    }
    __syncthreads();
    float mean = red[0] / (float)HID;
    __syncthreads();

    float vs = 0.f;
    for (int i = tid; i < HID; i += blockDim.x) {
        float d = xr[i] - mean;
        vs += d * d;
    }
    #pragma unroll
    for (int o = 16; o > 0; o >>= 1) vs += __shfl_xor_sync(0xffffffffu, vs, o);
    if (lane == 0) red[wid] = vs;
    __syncthreads();
    float vt = 0.f;
    if (tid < nwarp) vt = red[tid];
    if (wid == 0) {
        #pragma unroll
        for (int o = 16; o > 0; o >>= 1) vt += __shfl_xor_sync(0xffffffffu, vt, o);
        if (lane == 0) red[0] = vt;
    }
    __syncthreads();
    float inv = rsqrtf(red[0] / (float)HID + 1e-5f);

    for (int i = tid; i < HID; i += blockDim.x)
        orow[i] = __float2half_rn((xr[i] - mean) * inv * w[i] + b[i]);
}

// ---------------- FP16 mma GEMM, 4-stage cp.async ----------------
// C[M,N] = A[M,K]*W[N,K]^T (+bias)(+res)(+gelu). A,W fp16; acc/bias/res fp32.
// BM in {128,64}; BN=128; BK=32; 256 threads (8 warps, warp tile BMx32... BM/2 x 32).
#define GSTAGES 4
#define HSTR 40   // halves per smem row (32 data + 8 pad)

template<int BM, bool GELU, bool OUTHALF>
__device__ __forceinline__ void gemm_f16_dev(
    const __half* __restrict__ A, const __half* __restrict__ W,
    const float* __restrict__ bias, const float* __restrict__ res,
    void* __restrict__ Cv, int M, int N, int K)
{
    extern __shared__ __half smh[];
    constexpr int SH = (BM + 128) * HSTR;   // halves per stage
    constexpr int MT = BM / 32;
    constexpr int WMROWS = BM / 2;

    const int tid  = threadIdx.x;
    const int warp = tid >> 5;
    const int lane = tid & 31;
    const int g    = lane >> 2;
    const int tig  = lane & 3;
    const int wm   = warp & 1;
    const int wn   = warp >> 1;

    const int m0 = blockIdx.y * BM;
    const int n0 = blockIdx.x * 128;

    // B: 128 rows x 64B; row=tid>>1, koff=(tid&1)*16 halves, 2x cp16
    const int brl = tid >> 1;
    const int bk  = (tid & 1) << 4;
    const int bn  = n0 + brl;
    const int bsz = (bn < N) ? 16 : 0;
    const __half* gB = W + (size_t)(bn < N ? bn : 0) * K + bk;
    const uint32_t dB = (uint32_t)__cvta_generic_to_shared(smh + BM * HSTR + brl * HSTR + bk);

    const __half* gA;
    uint32_t dA;
    if constexpr (BM == 128) {
        gA = A + (size_t)(m0 + brl) * K + bk;
        dA = (uint32_t)__cvta_generic_to_shared(smh + brl * HSTR + bk);
    } else {
        const int arl = tid >> 2;
        const int ak  = (tid & 3) << 3;
        gA = A + (size_t)(m0 + arl) * K + ak;
        dA = (uint32_t)__cvta_generic_to_shared(smh + arl * HSTR + ak);
    }
    const uint32_t stageB = SH * 2u;  // bytes per stage

    float acc[MT][4][4];
    #pragma unroll
    for (int i = 0; i < MT; i++)
        #pragma unroll
        for (int j = 0; j < 4; j++)
            #pragma unroll
            for (int r = 0; r < 4; r++) acc[i][j][r] = 0.f;

    const int NIT = K >> 5;  // K / 32

    #define FILLG(it_) do { \
        const uint32_t _o = ((it_) & 3) * stageB; \
        const int _kb = (it_) << 5; \
        if constexpr (BM == 128) { \
            cp_async16(dA + _o, gA + _kb, 16); \
            cp_async16(dA + _o + 16, gA + _kb + 8, 16); \
        } else { \
            cp_async16(dA + _o, gA + _kb, 16); \
        } \
        cp_async16(dB + _o, gB + _kb, bsz); \
        cp_async16(dB + _o + 16, gB + _kb + 8, bsz); \
    } while (0)

    #pragma unroll
    for (int s = 0; s < GSTAGES - 1; s++) {
        if (s < NIT) FILLG(s);
        CP_COMMIT();
    }
    CP_WAIT2();
    __syncthreads();

    for (int it = 0; it < NIT; it++) {
        const int buf = it & 3;
        const __half* bufA = smh + buf * SH;
        const __half* bufB = bufA + BM * HSTR;

        #pragma unroll
        for (int s = 0; s < 2; s++) {
            const int c0 = s * 16 + 2 * tig;
            uint32_t af[MT][4];
            #pragma unroll
            for (int mt = 0; mt < MT; mt++) {
                const int r0 = wm * WMROWS + mt * 16 + g;
                af[mt][0] = *reinterpret_cast<const uint32_t*>(&bufA[r0 * HSTR + c0]);
                af[mt][1] = *reinterpret_cast<const uint32_t*>(&bufA[(r0 + 8) * HSTR + c0]);
                af[mt][2] = *reinterpret_cast<const uint32_t*>(&bufA[r0 * HSTR + c0 + 8]);
                af[mt][3] = *reinterpret_cast<const uint32_t*>(&bufA[(r0 + 8) * HSTR + c0 + 8]);
            }
            uint32_t bf[4][2];
            #pragma unroll
            for (int nt = 0; nt < 4; nt++) {
                const int n = wn * 32 + nt * 8 + g;
                bf[nt][0] = *reinterpret_cast<const uint32_t*>(&bufB[n * HSTR + c0]);
                bf[nt][1] = *reinterpret_cast<const uint32_t*>(&bufB[n * HSTR + c0 + 8]);
            }
            #pragma unroll
            for (int mt = 0; mt < MT; mt++)
                #pragma unroll
                for (int nt = 0; nt < 4; nt++)
                    mma_f16(acc[mt][nt], af[mt], bf[nt]);
        }

        const int nit = it + GSTAGES - 1;
        if (nit < NIT) FILLG(nit);
        CP_COMMIT();
        CP_WAIT2();
        __syncthreads();
    }
    #undef FILLG

    // ---- epilogue ----
    float* Cf = (float*)Cv;
    __half* Ch = (__half*)Cv;
    const bool n_even = ((N & 1) == 0);
    #pragma unroll
    for (int mt = 0; mt < MT; mt++) {
        const int r0 = m0 + wm * WMROWS + mt * 16 + g;
        #pragma unroll
        for (int nt = 0; nt < 4; nt++) {
            const int c = n0 + wn * 32 + nt * 8 + tig * 2;
            #pragma unroll
            for (int half_ = 0; half_ < 2; half_++) {
                const int m = r0 + half_ * 8;
                float v0 = acc[mt][nt][half_ * 2 + 0];
                float v1 = acc[mt][nt][half_ * 2 + 1];
                if (n_even && (c + 1) < N) {
                    if (bias) { float2 bv = *reinterpret_cast<const float2*>(&bias[c]); v0 += bv.x; v1 += bv.y; }
                    if (res)  { float2 rv = *reinterpret_cast<const float2*>(&res[(size_t)m * N + c]); v0 += rv.x; v1 += rv.y; }
                    if (GELU) { v0 = gelu1(v0); v1 = gelu1(v1); }
                    if (OUTHALF) {
                        *reinterpret_cast<__half2*>(&Ch[(size_t)m * N + c]) = __floats2half2_rn(v0, v1);
                    } else {
                        *reinterpret_cast<float2*>(&Cf[(size_t)m * N + c]) = make_float2(v0, v1);
                    }
                } else {
                    #pragma unroll
                    for (int q2 = 0; q2 < 2; q2++) {
                        const int n = c + q2;
                        if (n < N) {
                            float val = (q2 == 0) ? v0 : v1;
                            if (bias) val += bias[n];
                            if (res)  val += res[(size_t)m * N + n];
                            if (GELU) val = gelu1(val);
                            if (OUTHALF) Ch[(size_t)m * N + n] = __float2half_rn(val);
                            else         Cf[(size_t)m * N + n] = val;
                        }
                    }
                }
            }
        }
    }
}

template<int BM, bool GELU, bool OUTHALF>
__global__ __launch_bounds__(256, 2) void gemm_f16_k(
    const __half* __restrict__ A, const __half* __restrict__ W,
    const float* __restrict__ bias, const float* __restrict__ res,
    void* __restrict__ C, int M, int N, int K)
{
    gemm_f16_dev<BM, GELU, OUTHALF>(A, W, bias, res, C, M, N, K);
}

__global__ __launch_bounds__(256, 2) void gemm_f16_qkv_k(
    const __half* __restrict__ A,
    const __half* __restrict__ w0, const __half* __restrict__ w1, const __half* __restrict__ w2,
    float* __restrict__ o0, float* __restrict__ o1, float* __restrict__ o2,
    int M, int N, int K)
{
    const __half* W = (blockIdx.z == 0) ? w0 : ((blockIdx.z == 1) ? w1 : w2);
    float* C = (blockIdx.z == 0) ? o0 : ((blockIdx.z == 1) ? o1 : o2);
    gemm_f16_dev<128, false, false>(A, W, nullptr, nullptr, (void*)C, M, N, K);
}

#define GEMM_SMEM_128 (GSTAGES * (128 + 128) * HSTR * 2)
#define GEMM_SMEM_64  (GSTAGES * (64 + 128) * HSTR * 2)

// ---------------- flash attention (fp32 core, fp16 output) ----------------
#define BQ   64
#define BKT  64
#define PSTR 68
#define ATTN_SMEM (4 * BKT * PSTR * (int)sizeof(float))

__global__ __launch_bounds__(256) void flash_attn_kernel(
    const float* __restrict__ q, const float* __restrict__ k,
    const float* __restrict__ v, const int* __restrict__ amask,
    __half* __restrict__ out)
{
    extern __shared__ float sm[];
    float* Qs = sm;
    float* Ks = Qs + BKT * PSTR;
    float* Vs = Ks + BKT * PSTR;
    float* Ps = Vs + BKT * PSTR;
    __shared__ int msk[BKT];

    const int qt = gridDim.x - 1 - blockIdx.x;
    const int hh = blockIdx.y;
    const int b  = blockIdx.z;
    const int q0 = qt * BQ;
    const int tid = threadIdx.x;
    const int tx = tid & 15, ty = tid >> 4;

    {
        const int r = tid >> 2;
        const float* gq = q + ((size_t)(b * SEQ + q0 + r)) * HID + hh * HDIM;
        #pragma unroll
        for (int c = 0; c < 4; c++) {
            const int d = ((tid & 3) + c * 4) * 4;
            float4 t4 = *reinterpret_cast<const float4*>(&gq[d]);
            Qs[(d + 0) * PSTR + r] = t4.x * 0.125f;
            Qs[(d + 1) * PSTR + r] = t4.y * 0.125f;
            Qs[(d + 2) * PSTR + r] = t4.z * 0.125f;
            Qs[(d + 3) * PSTR + r] = t4.w * 0.125f;
        }
    }

    float m_i[4], l_i[4], o[4][4];
    #pragma unroll
    for (int i = 0; i < 4; i++) {
        m_i[i] = -1e30f; l_i[i] = 0.f;
        #pragma unroll
        for (int j = 0; j < 4; j++) o[i][j] = 0.f;
    }

    for (int kt = 0; kt <= qt; kt++) {
        __syncthreads();
        {
            const int r = tid >> 2;
            const size_t grow = (size_t)(b * SEQ + kt * BKT + r) * HID + hh * HDIM;
            const float* gk = k + grow;
            const float* gv = v + grow;
            #pragma unroll
            for (int c = 0; c < 4; c++) {
                const int d = ((tid & 3) + c * 4) * 4;
                float4 k4 = *reinterpret_cast<const float4*>(&gk[d]);
                Ks[(d + 0) * PSTR + r] = k4.x;
                Ks[(d + 1) * PSTR + r] = k4.y;
                Ks[(d + 2) * PSTR + r] = k4.z;
                Ks[(d + 3) * PSTR + r] = k4.w;
                float4 v4 = *reinterpret_cast<const float4*>(&gv[d]);
                *reinterpret_cast<float4*>(&Vs[r * PSTR + d]) = v4;
            }
            if (tid < BKT) msk[tid] = amask[b * SEQ + kt * BKT + tid];
        }
        __syncthreads();

        float s[4][4];
        #pragma unroll
        for (int i = 0; i < 4; i++)
            #pragma unroll
            for (int j = 0; j < 4; j++) s[i][j] = 0.f;

        #pragma unroll 4
        for (int d = 0; d < HDIM; d++) {
            float4 q4 = *reinterpret_cast<const float4*>(&Qs[d * PSTR + ty * 4]);
            float4 k4 = *reinterpret_cast<const float4*>(&Ks[d * PSTR + tx * 4]);
            float qa[4] = {q4.x, q4.y, q4.z, q4.w};
            float ka[4] = {k4.x, k4.y, k4.z, k4.w};
            #pragma unroll
            for (int i = 0; i < 4; i++)
                #pragma unroll
                for (int j = 0; j < 4; j++)
                    s[i][j] = fmaf(qa[i], ka[j], s[i][j]);
        }

        const bool diag = (kt == qt);
        #pragma unroll
        for (int j = 0; j < 4; j++) {
            const int kj = tx * 4 + j;
            const bool padded = (msk[kj] == 0);
            #pragma unroll
            for (int i = 0; i < 4; i++) {
                const int qi = ty * 4 + i;
                if (padded || (diag && (kt * BKT + kj) > (q0 + qi)))
                    s[i][j] = -1e9f;
            }
        }

        #pragma unroll
        for (int i = 0; i < 4; i++) {
            float rm = fmaxf(fmaxf(s[i][0], s[i][1]), fmaxf(s[i][2], s[i][3]));
            #pragma unroll
            for (int off = 8; off > 0; off >>= 1)
                rm = fmaxf(rm, __shfl_xor_sync(0xffffffffu, rm, off));
            const float mn = fmaxf(m_i[i], rm);
            const float sc = __expf(m_i[i] - mn);
            float rs = 0.f;
            float p[4];
            #pragma unroll
            for (int j = 0; j < 4; j++) {
                p[j] = __expf(s[i][j] - mn);
                rs += p[j];
            }
            #pragma unroll
            for (int j = 0; j < 4; j++)
                Ps[(ty * 4 + i) * PSTR + tx * 4 + j] = p[j];
            #pragma unroll
            for (int off = 8; off > 0; off >>= 1)
                rs += __shfl_xor_sync(0xffffffffu, rs, off);
            l_i[i] = l_i[i] * sc + rs;
            m_i[i] = mn;
            #pragma unroll
            for (int j = 0; j < 4; j++) o[i][j] *= sc;
        }
        __syncwarp();

        #pragma unroll 4
        for (int kk = 0; kk < BKT; kk += 4) {
            float4 p4[4];
            #pragma unroll
            for (int i = 0; i < 4; i++)
                p4[i] = *reinterpret_cast<const float4*>(&Ps[(ty * 4 + i) * PSTR + kk]);
            float4 v4[4];
            #pragma unroll
            for (int t = 0; t < 4; t++)
                v4[t] = *reinterpret_cast<const float4*>(&Vs[(kk + t) * PSTR + tx * 4]);
            #pragma unroll
            for (int i = 0; i < 4; i++) {
                float pa[4] = {p4[i].x, p4[i].y, p4[i].z, p4[i].w};
                #pragma unroll
                for (int t = 0; t < 4; t++) {
                    o[i][0] = fmaf(pa[t], v4[t].x, o[i][0]);
                    o[i][1] = fmaf(pa[t], v4[t].y, o[i][1]);
                    o[i][2] = fmaf(pa[t], v4[t].z, o[i][2]);
                    o[i][3] = fmaf(pa[t], v4[t].w, o[i][3]);
                }
            }
        }
    }

    #pragma unroll
    for (int i = 0; i < 4; i++) {
        const float inv = 1.0f / l_i[i];
        const size_t off = (size_t)(b * SEQ + q0 + ty * 4 + i) * HID + hh * HDIM + tx * 4;
        *reinterpret_cast<__half2*>(&out[off])     = __floats2half2_rn(o[i][0] * inv, o[i][1] * inv);
        *reinterpret_cast<__half2*>(&out[off + 2]) = __floats2half2_rn(o[i][2] * inv, o[i][3] * inv);
    }
}

// ---------------- launcher ----------------
extern "C" void kernel_launch(void* const* d_in, const int* in_sizes, int n_in,
                              void* d_out, int out_size) {
    const int*   input_ids = (const int*)d_in[0];
    const int*   attn_mask = (const int*)d_in[1];
    const float* tok_emb   = (const float*)d_in[2];
    const float* pos_emb   = (const float*)d_in[3];
    const float* ln1_w     = (const float*)d_in[4];
    const float* ln1_b     = (const float*)d_in[5];
    const float* qw        = (const float*)d_in[6];
    const float* kw        = (const float*)d_in[7];
    const float* vw        = (const float*)d_in[8];
    const float* ow        = (const float*)d_in[9];
    const float* ob        = (const float*)d_in[10];
    const float* ln2_w     = (const float*)d_in[11];
    const float* ln2_b     = (const float*)d_in[12];
    const float* w1        = (const float*)d_in[13];
    const float* b1        = (const float*)d_in[14];
    const float* w2        = (const float*)d_in[15];
    const float* b2        = (const float*)d_in[16];
    const float* lnf_w     = (const float*)d_in[17];
    const float* lnf_b     = (const float*)d_in[18];
    const float* lm_w      = (const float*)d_in[19];
    float* out = (float*)d_out;

    float *x, *q, *k, *v;
    __half *h, *a, *ff, *wq, *wk, *wv, *wo, *cw1, *cw2, *wlm;
    cudaGetSymbolAddress((void**)&x,  g_x);
    cudaGetSymbolAddress((void**)&h,  g_h);
    cudaGetSymbolAddress((void**)&q,  g_q);
    cudaGetSymbolAddress((void**)&k,  g_k);
    cudaGetSymbolAddress((void**)&v,  g_v);
    cudaGetSymbolAddress((void**)&a,  g_a);
    cudaGetSymbolAddress((void**)&ff, g_ff);
    cudaGetSymbolAddress((void**)&wq, g_wq);
    cudaGetSymbolAddress((void**)&wk, g_wk);
    cudaGetSymbolAddress((void**)&wv, g_wv);
    cudaGetSymbolAddress((void**)&wo, g_wo);
    cudaGetSymbolAddress((void**)&cw1, g_w1);
    cudaGetSymbolAddress((void**)&cw2, g_w2);
    cudaGetSymbolAddress((void**)&wlm, g_wlm);

    cudaFuncSetAttribute(flash_attn_kernel,
                         cudaFuncAttributeMaxDynamicSharedMemorySize, ATTN_SMEM);
    cudaFuncSetAttribute((const void*)gemm_f16_k<128, false, false>,
                         cudaFuncAttributeMaxDynamicSharedMemorySize, GEMM_SMEM_128);
    cudaFuncSetAttribute((const void*)gemm_f16_k<128, true, true>,
                         cudaFuncAttributeMaxDynamicSharedMemorySize, GEMM_SMEM_128);
    cudaFuncSetAttribute((const void*)gemm_f16_k<64, false, false>,
                         cudaFuncAttributeMaxDynamicSharedMemorySize, GEMM_SMEM_64);
    cudaFuncSetAttribute((const void*)gemm_f16_qkv_k,
                         cudaFuncAttributeMaxDynamicSharedMemorySize, GEMM_SMEM_128);

    // one-time-per-launch fp16 weight conversion
    {
        const int nqk = NLAYER * HID * HID / 2;
        cvt_half_k<<<(nqk + 255) / 256, 256>>>(qw, wq, nqk);
        cvt_half_k<<<(nqk + 255) / 256, 256>>>(kw, wk, nqk);
        cvt_half_k<<<(nqk + 255) / 256, 256>>>(vw, wv, nqk);
        cvt_half_k<<<(nqk + 255) / 256, 256>>>(ow, wo, nqk);
        const int nff = NLAYER * FFI * HID / 2;
        cvt_half_k<<<(nff + 255) / 256, 256>>>(w1, cw1, nff);
        cvt_half_k<<<(nff + 255) / 256, 256>>>(w2, cw2, nff);
        const int nlm = VOCAB * HID / 2;
        cvt_half_k<<<(nlm + 255) / 256, 256>>>(lm_w, wlm, nlm);
    }

    {
        int n = T_TOK * HID;
        embed_kernel<<<(n + 255) / 256, 256>>>(input_ids, tok_emb, pos_emb, x);
    }

    dim3 gqkv(HID / 128, T_TOK / 128, 3);    // 288 blocks
    dim3 gproj(HID / 128, T_TOK / 64);       // 192 blocks (BM=64)
    dim3 gff1(FFI / 128, T_TOK / 128);       // 384 blocks
    dim3 gff2(HID / 128, T_TOK / 64);        // 192 blocks (BM=64)
    dim3 gattn(SEQ / BQ, NHEAD, BATCH);
    dim3 glm((VOCAB + 127) / 128, T_TOK / 128);

    for (int l = 0; l < NLAYER; l++) {
        const float* l1w = ln1_w + (size_t)l * HID;
        const float* l1b = ln1_b + (size_t)l * HID;
        const __half* qwl = wq + (size_t)l * HID * HID;
        const __half* kwl = wk + (size_t)l * HID * HID;
        const __half* vwl = wv + (size_t)l * HID * HID;
        const __half* owl = wo + (size_t)l * HID * HID;
        const float* obl = ob + (size_t)l * HID;
        const float* l2w = ln2_w + (size_t)l * HID;
        const float* l2b = ln2_b + (size_t)l * HID;
        const __half* w1l = cw1 + (size_t)l * FFI * HID;
        const float* b1l = b1 + (size_t)l * FFI;
        const __half* w2l = cw2 + (size_t)l * HID * FFI;
        const float* b2l = b2 + (size_t)l * HID;

        layernorm_kernel<<<T_TOK, 256>>>(x, l1w, l1b, h);
        gemm_f16_qkv_k<<<gqkv, 256, GEMM_SMEM_128>>>(h, qwl, kwl, vwl, q, k, v, T_TOK, HID, HID);
        flash_attn_kernel<<<gattn, 256, ATTN_SMEM>>>(q, k, v, attn_mask, a);
        gemm_f16_k<64, false, false><<<gproj, 256, GEMM_SMEM_64>>>(a, owl, obl, x, (void*)x, T_TOK, HID, HID);

        layernorm_kernel<<<T_TOK, 256>>>(x, l2w, l2b, h);
        gemm_f16_k<128, true, true><<<gff1, 256, GEMM_SMEM_128>>>(h, w1l, b1l, nullptr, (void*)ff, T_TOK, FFI, HID);
        gemm_f16_k<64, false, false><<<gff2, 256, GEMM_SMEM_64>>>(ff, w2l, b2l, x, (void*)x, T_TOK, HID, FFI);
    }

    layernorm_kernel<<<T_TOK, 256>>>(x, lnf_w, lnf_b, h);
    gemm_f16_k<128, false, false><<<glm, 256, GEMM_SMEM_128>>>(h, wlm, nullptr, nullptr, (void*)out, T_TOK, VOCAB, HID);
}

// round 11
// speedup vs baseline: 9.4798x; 1.5000x over previous
#include <cuda_runtime.h>
#include <cuda_fp16.h>
#include <math.h>
#include <stdint.h>

#define T_TOK 2048
#define SEQ   1024
#define BATCH 2
#define HID   768
#define NHEAD 12
#define HDIM  64
#define NLAYER 12
#define FFI   3072
#define VOCAB 50257

// ---------------- scratch (device globals: allocation-free) ----------------
__device__ float  g_x[T_TOK * HID];
__device__ __half g_h[T_TOK * HID];
__device__ __half g_q[T_TOK * HID];
__device__ __half g_k[T_TOK * HID];
__device__ __half g_v[T_TOK * HID];
__device__ __half g_a[T_TOK * HID];
__device__ __half g_ff[T_TOK * FFI];
// fp16 weight copies
__device__ __half g_wq[NLAYER * HID * HID];
__device__ __half g_wk[NLAYER * HID * HID];
__device__ __half g_wv[NLAYER * HID * HID];
__device__ __half g_wo[NLAYER * HID * HID];
__device__ __half g_w1[NLAYER * FFI * HID];
__device__ __half g_w2[NLAYER * HID * FFI];
__device__ __half g_wlm[VOCAB * HID];

// ---------------- helpers ----------------
__device__ __forceinline__ float gelu1(float x) {
    return 0.5f * x * (1.0f + erff(x * 0.70710678118654752f));
}
__device__ __forceinline__ void mma_f16(float d[4], const uint32_t a[4], const uint32_t b[2]) {
    asm volatile(
        "mma.sync.aligned.m16n8k16.row.col.f32.f16.f16.f32 "
        "{%0,%1,%2,%3}, {%4,%5,%6,%7}, {%8,%9}, {%0,%1,%2,%3};\n"
        : "+f"(d[0]), "+f"(d[1]), "+f"(d[2]), "+f"(d[3])
        : "r"(a[0]), "r"(a[1]), "r"(a[2]), "r"(a[3]), "r"(b[0]), "r"(b[1]));
}
__device__ __forceinline__ void ldsm_x4(uint32_t* r, uint32_t addr) {
    asm volatile("ldmatrix.sync.aligned.m8n8.x4.shared.b16 {%0,%1,%2,%3}, [%4];"
        : "=r"(r[0]), "=r"(r[1]), "=r"(r[2]), "=r"(r[3]) : "r"(addr));
}
__device__ __forceinline__ void ldsm_x4_t(uint32_t* r, uint32_t addr) {
    asm volatile("ldmatrix.sync.aligned.m8n8.x4.trans.shared.b16 {%0,%1,%2,%3}, [%4];"
        : "=r"(r[0]), "=r"(r[1]), "=r"(r[2]), "=r"(r[3]) : "r"(addr));
}
__device__ __forceinline__ void cp_async16(uint32_t dst, const void* src, int sz) {
    asm volatile("cp.async.cg.shared.global [%0], [%1], 16, %2;\n"
                 :: "r"(dst), "l"(src), "r"(sz));
}
#define CP_COMMIT() asm volatile("cp.async.commit_group;\n" ::: "memory")
#define CP_WAIT2()  asm volatile("cp.async.wait_group 2;\n" ::: "memory")

// ---------------- embeddings ----------------
__global__ void embed_kernel(const int* __restrict__ ids,
                             const float* __restrict__ tok,
                             const float* __restrict__ pos,
                             float* __restrict__ x) {
    int idx = blockIdx.x * blockDim.x + threadIdx.x;
    if (idx >= T_TOK * HID) return;
    int t = idx / HID;
    int hh = idx - t * HID;
    int s = t % SEQ;
    int id = ids[t];
    x[idx] = tok[(size_t)id * HID + hh] + pos[(size_t)s * HID + hh];
}

// ---------------- fp16 weight copy ----------------
__global__ void cvt_half_k(const float* __restrict__ in, __half* __restrict__ outp, int n2) {
    int i = blockIdx.x * blockDim.x + threadIdx.x;
    if (i >= n2) return;
    float2 v = reinterpret_cast<const float2*>(in)[i];
    reinterpret_cast<__half2*>(outp)[i] = __floats2half2_rn(v.x, v.y);
}

// ---------------- layernorm (fp16 output) ----------------
__global__ void layernorm_kernel(const float* __restrict__ x,
                                 const float* __restrict__ w,
                                 const float* __restrict__ b,
                                 __half* __restrict__ out) {
    int row = blockIdx.x;
    const float* xr = x + (size_t)row * HID;
    __half* orow = out + (size_t)row * HID;
    __shared__ float red[32];
    int tid = threadIdx.x, lane = tid & 31, wid = tid >> 5;
    int nwarp = blockDim.x >> 5;

    float s = 0.f;
    for (int i = tid; i < HID; i += blockDim.x) s += xr[i];
    #pragma unroll
    for (int o = 16; o > 0; o >>= 1) s += __shfl_xor_sync(0xffffffffu, s, o);
    if (lane == 0) red[wid] = s;
    __syncthreads();
    float tot = 0.f;
    if (tid < nwarp) tot = red[tid];
    if (wid == 0) {
        #pragma unroll
        for (int o = 16; o > 0; o >>= 1) tot += __shfl_xor_sync(0xffffffffu, tot, o);
        if (lane == 0) red[0] = tot;
    }
    __syncthreads();
    float mean = red[0] / (float)HID;
    __syncthreads();

    float vs = 0.f;
    for (int i = tid; i < HID; i += blockDim.x) {
        float d = xr[i] - mean;
        vs += d * d;
    }
    #pragma unroll
    for (int o = 16; o > 0; o >>= 1) vs += __shfl_xor_sync(0xffffffffu, vs, o);
    if (lane == 0) red[wid] = vs;
    __syncthreads();
    float vt = 0.f;
    if (tid < nwarp) vt = red[tid];
    if (wid == 0) {
        #pragma unroll
        for (int o = 16; o > 0; o >>= 1) vt += __shfl_xor_sync(0xffffffffu, vt, o);
        if (lane == 0) red[0] = vt;
    }
    __syncthreads();
    float inv = rsqrtf(red[0] / (float)HID + 1e-5f);

    for (int i = tid; i < HID; i += blockDim.x)
        orow[i] = __float2half_rn((xr[i] - mean) * inv * w[i] + b[i]);
}

// ---------------- FP16 mma GEMM, 4-stage cp.async ----------------
#define GSTAGES 4
#define HSTR 40

template<int BM, bool GELU, bool OUTHALF>
__device__ __forceinline__ void gemm_f16_dev(
    const __half* __restrict__ A, const __half* __restrict__ W,
    const float* __restrict__ bias, const float* __restrict__ res,
    void* __restrict__ Cv, int M, int N, int K)
{
    extern __shared__ __half smh[];
    constexpr int SH = (BM + 128) * HSTR;
    constexpr int MT = BM / 32;
    constexpr int WMROWS = BM / 2;

    const int tid  = threadIdx.x;
    const int warp = tid >> 5;
    const int lane = tid & 31;
    const int g    = lane >> 2;
    const int tig  = lane & 3;
    const int wm   = warp & 1;
    const int wn   = warp >> 1;

    const int m0 = blockIdx.y * BM;
    const int n0 = blockIdx.x * 128;

    const int brl = tid >> 1;
    const int bk  = (tid & 1) << 4;
    const int bn  = n0 + brl;
    const int bsz = (bn < N) ? 16 : 0;
    const __half* gB = W + (size_t)(bn < N ? bn : 0) * K + bk;
    const uint32_t dB = (uint32_t)__cvta_generic_to_shared(smh + BM * HSTR + brl * HSTR + bk);

    const __half* gA;
    uint32_t dA;
    if constexpr (BM == 128) {
        gA = A + (size_t)(m0 + brl) * K + bk;
        dA = (uint32_t)__cvta_generic_to_shared(smh + brl * HSTR + bk);
    } else {
        const int arl = tid >> 2;
        const int ak  = (tid & 3) << 3;
        gA = A + (size_t)(m0 + arl) * K + ak;
        dA = (uint32_t)__cvta_generic_to_shared(smh + arl * HSTR + ak);
    }
    const uint32_t stageB = SH * 2u;

    float acc[MT][4][4];
    #pragma unroll
    for (int i = 0; i < MT; i++)
        #pragma unroll
        for (int j = 0; j < 4; j++)
            #pragma unroll
            for (int r = 0; r < 4; r++) acc[i][j][r] = 0.f;

    const int NIT = K >> 5;

    #define FILLG(it_) do { \
        const uint32_t _o = ((it_) & 3) * stageB; \
        const int _kb = (it_) << 5; \
        if constexpr (BM == 128) { \
            cp_async16(dA + _o, gA + _kb, 16); \
            cp_async16(dA + _o + 16, gA + _kb + 8, 16); \
        } else { \
            cp_async16(dA + _o, gA + _kb, 16); \
        } \
        cp_async16(dB + _o, gB + _kb, bsz); \
        cp_async16(dB + _o + 16, gB + _kb + 8, bsz); \
    } while (0)

    #pragma unroll
    for (int s = 0; s < GSTAGES - 1; s++) {
        if (s < NIT) FILLG(s);
        CP_COMMIT();
    }
    CP_WAIT2();
    __syncthreads();

    for (int it = 0; it < NIT; it++) {
        const int buf = it & 3;
        const __half* bufA = smh + buf * SH;
        const __half* bufB = bufA + BM * HSTR;

        #pragma unroll
        for (int s = 0; s < 2; s++) {
            const int c0 = s * 16 + 2 * tig;
            uint32_t af[MT][4];
            #pragma unroll
            for (int mt = 0; mt < MT; mt++) {
                const int r0 = wm * WMROWS + mt * 16 + g;
                af[mt][0] = *reinterpret_cast<const uint32_t*>(&bufA[r0 * HSTR + c0]);
                af[mt][1] = *reinterpret_cast<const uint32_t*>(&bufA[(r0 + 8) * HSTR + c0]);
                af[mt][2] = *reinterpret_cast<const uint32_t*>(&bufA[r0 * HSTR + c0 + 8]);
                af[mt][3] = *reinterpret_cast<const uint32_t*>(&bufA[(r0 + 8) * HSTR + c0 + 8]);
            }
            uint32_t bf[4][2];
            #pragma unroll
            for (int nt = 0; nt < 4; nt++) {
                const int n = wn * 32 + nt * 8 + g;
                bf[nt][0] = *reinterpret_cast<const uint32_t*>(&bufB[n * HSTR + c0]);
                bf[nt][1] = *reinterpret_cast<const uint32_t*>(&bufB[n * HSTR + c0 + 8]);
            }
            #pragma unroll
            for (int mt = 0; mt < MT; mt++)
                #pragma unroll
                for (int nt = 0; nt < 4; nt++)
                    mma_f16(acc[mt][nt], af[mt], bf[nt]);
        }

        const int nit = it + GSTAGES - 1;
        if (nit < NIT) FILLG(nit);
        CP_COMMIT();
        CP_WAIT2();
        __syncthreads();
    }
    #undef FILLG

    float* Cf = (float*)Cv;
    __half* Ch = (__half*)Cv;
    const bool n_even = ((N & 1) == 0);
    #pragma unroll
    for (int mt = 0; mt < MT; mt++) {
        const int r0 = m0 + wm * WMROWS + mt * 16 + g;
        #pragma unroll
        for (int nt = 0; nt < 4; nt++) {
            const int c = n0 + wn * 32 + nt * 8 + tig * 2;
            #pragma unroll
            for (int half_ = 0; half_ < 2; half_++) {
                const int m = r0 + half_ * 8;
                float v0 = acc[mt][nt][half_ * 2 + 0];
                float v1 = acc[mt][nt][half_ * 2 + 1];
                if (n_even && (c + 1) < N) {
                    if (bias) { float2 bv = *reinterpret_cast<const float2*>(&bias[c]); v0 += bv.x; v1 += bv.y; }
                    if (res)  { float2 rv = *reinterpret_cast<const float2*>(&res[(size_t)m * N + c]); v0 += rv.x; v1 += rv.y; }
                    if (GELU) { v0 = gelu1(v0); v1 = gelu1(v1); }
                    if (OUTHALF) {
                        *reinterpret_cast<__half2*>(&Ch[(size_t)m * N + c]) = __floats2half2_rn(v0, v1);
                    } else {
                        *reinterpret_cast<float2*>(&Cf[(size_t)m * N + c]) = make_float2(v0, v1);
                    }
                } else {
                    #pragma unroll
                    for (int q2 = 0; q2 < 2; q2++) {
                        const int n = c + q2;
                        if (n < N) {
                            float val = (q2 == 0) ? v0 : v1;
                            if (bias) val += bias[n];
                            if (res)  val += res[(size_t)m * N + n];
                            if (GELU) val = gelu1(val);
                            if (OUTHALF) Ch[(size_t)m * N + n] = __float2half_rn(val);
                            else         Cf[(size_t)m * N + n] = val;
                        }
                    }
                }
            }
        }
    }
}

template<int BM, bool GELU, bool OUTHALF>
__global__ __launch_bounds__(256, 2) void gemm_f16_k(
    const __half* __restrict__ A, const __half* __restrict__ W,
    const float* __restrict__ bias, const float* __restrict__ res,
    void* __restrict__ C, int M, int N, int K)
{
    gemm_f16_dev<BM, GELU, OUTHALF>(A, W, bias, res, C, M, N, K);
}

__global__ __launch_bounds__(256, 2) void gemm_f16_qkv_k(
    const __half* __restrict__ A,
    const __half* __restrict__ w0, const __half* __restrict__ w1, const __half* __restrict__ w2,
    __half* __restrict__ o0, __half* __restrict__ o1, __half* __restrict__ o2,
    int M, int N, int K)
{
    const __half* W = (blockIdx.z == 0) ? w0 : ((blockIdx.z == 1) ? w1 : w2);
    __half* C = (blockIdx.z == 0) ? o0 : ((blockIdx.z == 1) ? o1 : o2);
    gemm_f16_dev<128, false, true>(A, W, nullptr, nullptr, (void*)C, M, N, K);
}

#define GEMM_SMEM_128 (GSTAGES * (128 + 128) * HSTR * 2)
#define GEMM_SMEM_64  (GSTAGES * (64 + 128) * HSTR * 2)

// ---------------- tensor-core flash attention ----------------
// 64-query CTA, 4 warps (16 rows each), 64-key tiles, fp16 mma, fp32 softmax.
#define ASTR 72  // halves per smem row

__global__ __launch_bounds__(128) void flash_attn_f16_kernel(
    const __half* __restrict__ q, const __half* __restrict__ k,
    const __half* __restrict__ v, const int* __restrict__ amask,
    __half* __restrict__ out)
{
    __shared__ __half Qs[64 * ASTR];
    __shared__ __half Ks[64 * ASTR];
    __shared__ __half Vs[64 * ASTR];
    __shared__ int msk[64];

    const int qt = gridDim.x - 1 - blockIdx.x;   // heavy tiles first
    const int hh = blockIdx.y;
    const int b  = blockIdx.z;
    const int q0 = qt * 64;
    const int tid = threadIdx.x;
    const int lane = tid & 31;
    const int w = tid >> 5;
    const int tig = lane & 3;
    const int gid = lane >> 2;

    // load Q tile, scaled by 1/8 (exact power of two)
    {
        const __half2 s125 = __float2half2_rn(0.125f);
        #pragma unroll
        for (int ch = tid; ch < 512; ch += 128) {
            const int row = ch >> 3, part = ch & 7;
            uint4 u = *reinterpret_cast<const uint4*>(
                q + (size_t)(b * SEQ + q0 + row) * HID + hh * HDIM + part * 8);
            __half2* hp = reinterpret_cast<__half2*>(&u);
            hp[0] = __hmul2(hp[0], s125); hp[1] = __hmul2(hp[1], s125);
            hp[2] = __hmul2(hp[2], s125); hp[3] = __hmul2(hp[3], s125);
            *reinterpret_cast<uint4*>(&Qs[row * ASTR + part * 8]) = u;
        }
    }
    __syncthreads();

    // Q fragments (held in registers for the whole kernel)
    uint32_t qf[4][4];
    {
        const int r = 16 * w + (lane & 15);
        const int c = (lane >> 4) * 8;
        #pragma unroll
        for (int kk = 0; kk < 4; kk++)
            ldsm_x4(qf[kk], (uint32_t)__cvta_generic_to_shared(&Qs[r * ASTR + kk * 16 + c]));
    }

    float o[8][4];
    #pragma unroll
    for (int i = 0; i < 8; i++)
        #pragma unroll
        for (int j = 0; j < 4; j++) o[i][j] = 0.f;
    float mi0 = -1e30f, mi1 = -1e30f, li0 = 0.f, li1 = 0.f;
    const int row0 = q0 + 16 * w + gid;
    const int row1 = row0 + 8;

    for (int kt = 0; kt <= qt; kt++) {
        __syncthreads();
        #pragma unroll
        for (int ch = tid; ch < 512; ch += 128) {
            const int row = ch >> 3, part = ch & 7;
            const size_t go = (size_t)(b * SEQ + kt * 64 + row) * HID + hh * HDIM + part * 8;
            *reinterpret_cast<uint4*>(&Ks[row * ASTR + part * 8]) =
                *reinterpret_cast<const uint4*>(k + go);
            *reinterpret_cast<uint4*>(&Vs[row * ASTR + part * 8]) =
                *reinterpret_cast<const uint4*>(v + go);
        }
        if (tid < 64) msk[tid] = amask[b * SEQ + kt * 64 + tid];
        __syncthreads();

        // ---- S = Q K^T ----
        float s[8][4];
        #pragma unroll
        for (int j = 0; j < 8; j++) {
            s[j][0] = s[j][1] = s[j][2] = s[j][3] = 0.f;
            uint32_t kb[8];
            const uint32_t base = (uint32_t)__cvta_generic_to_shared(
                &Ks[(8 * j + (lane & 7)) * ASTR + (lane >> 3) * 8]);
            ldsm_x4(kb, base);
            ldsm_x4(kb + 4, base + 64);  // +32 halves
            mma_f16(s[j], qf[0], kb);
            mma_f16(s[j], qf[1], kb + 2);
            mma_f16(s[j], qf[2], kb + 4);
            mma_f16(s[j], qf[3], kb + 6);
        }

        // ---- mask ----
        const bool diag = (kt == qt);
        #pragma unroll
        for (int j = 0; j < 8; j++) {
            const int c0i = kt * 64 + 8 * j + 2 * tig;
            if (msk[8 * j + 2 * tig] == 0)     { s[j][0] = -1e9f; s[j][2] = -1e9f; }
            if (msk[8 * j + 2 * tig + 1] == 0) { s[j][1] = -1e9f; s[j][3] = -1e9f; }
            if (diag) {
                if (c0i > row0)     s[j][0] = -1e9f;
                if (c0i + 1 > row0) s[j][1] = -1e9f;
                if (c0i > row1)     s[j][2] = -1e9f;
                if (c0i + 1 > row1) s[j][3] = -1e9f;
            }
        }

        // ---- online softmax ----
        float m0 = -1e30f, m1 = -1e30f;
        #pragma unroll
        for (int j = 0; j < 8; j++) {
            m0 = fmaxf(m0, fmaxf(s[j][0], s[j][1]));
            m1 = fmaxf(m1, fmaxf(s[j][2], s[j][3]));
        }
        m0 = fmaxf(m0, __shfl_xor_sync(0xffffffffu, m0, 1));
        m0 = fmaxf(m0, __shfl_xor_sync(0xffffffffu, m0, 2));
        m1 = fmaxf(m1, __shfl_xor_sync(0xffffffffu, m1, 1));
        m1 = fmaxf(m1, __shfl_xor_sync(0xffffffffu, m1, 2));
        const float mn0 = fmaxf(mi0, m0);
        const float mn1 = fmaxf(mi1, m1);
        const float sc0 = __expf(mi0 - mn0);
        const float sc1 = __expf(mi1 - mn1);

        uint32_t ph[8][2];
        float ls0 = 0.f, ls1 = 0.f;
        #pragma unroll
        for (int j = 0; j < 8; j++) {
            const float p0 = __expf(s[j][0] - mn0);
            const float p1 = __expf(s[j][1] - mn0);
            const float p2 = __expf(s[j][2] - mn1);
            const float p3 = __expf(s[j][3] - mn1);
            ls0 += p0 + p1; ls1 += p2 + p3;
            __half2 h01 = __floats2half2_rn(p0, p1);
            __half2 h23 = __floats2half2_rn(p2, p3);
            ph[j][0] = *reinterpret_cast<uint32_t*>(&h01);
            ph[j][1] = *reinterpret_cast<uint32_t*>(&h23);
        }
        li0 = li0 * sc0 + ls0;
        li1 = li1 * sc1 + ls1;
        mi0 = mn0; mi1 = mn1;
        #pragma unroll
        for (int dn = 0; dn < 8; dn++) {
            o[dn][0] *= sc0; o[dn][1] *= sc0;
            o[dn][2] *= sc1; o[dn][3] *= sc1;
        }

        // ---- O += P V ----
        #pragma unroll
        for (int kj = 0; kj < 4; kj++) {
            const uint32_t a[4] = {ph[2 * kj][0], ph[2 * kj][1],
                                   ph[2 * kj + 1][0], ph[2 * kj + 1][1]};
            #pragma unroll
            for (int dnp = 0; dnp < 4; dnp++) {
                uint32_t vb[4];
                const uint32_t addr = (uint32_t)__cvta_generic_to_shared(
                    &Vs[(16 * kj + (lane & 7) + ((lane >> 3) & 1) * 8) * ASTR
                        + 16 * dnp + (lane >> 4) * 8]);
                ldsm_x4_t(vb, addr);
                mma_f16(o[2 * dnp], a, vb);
                mma_f16(o[2 * dnp + 1], a, vb + 2);
            }
        }
    }

    // ---- finalize ----
    li0 += __shfl_xor_sync(0xffffffffu, li0, 1);
    li0 += __shfl_xor_sync(0xffffffffu, li0, 2);
    li1 += __shfl_xor_sync(0xffffffffu, li1, 1);
    li1 += __shfl_xor_sync(0xffffffffu, li1, 2);
    const float inv0 = 1.0f / li0;
    const float inv1 = 1.0f / li1;
    #pragma unroll
    for (int dn = 0; dn < 8; dn++) {
        const int cb = hh * HDIM + 8 * dn + 2 * tig;
        __half2 h0 = __floats2half2_rn(o[dn][0] * inv0, o[dn][1] * inv0);
        __half2 h1 = __floats2half2_rn(o[dn][2] * inv1, o[dn][3] * inv1);
        *reinterpret_cast<__half2*>(&out[(size_t)(b * SEQ + row0) * HID + cb]) = h0;
        *reinterpret_cast<__half2*>(&out[(size_t)(b * SEQ + row1) * HID + cb]) = h1;
    }
}

// ---------------- launcher ----------------
extern "C" void kernel_launch(void* const* d_in, const int* in_sizes, int n_in,
                              void* d_out, int out_size) {
    const int*   input_ids = (const int*)d_in[0];
    const int*   attn_mask = (const int*)d_in[1];
    const float* tok_emb   = (const float*)d_in[2];
    const float* pos_emb   = (const float*)d_in[3];
    const float* ln1_w     = (const float*)d_in[4];
    const float* ln1_b     = (const float*)d_in[5];
    const float* qw        = (const float*)d_in[6];
    const float* kw        = (const float*)d_in[7];
    const float* vw        = (const float*)d_in[8];
    const float* ow        = (const float*)d_in[9];
    const float* ob        = (const float*)d_in[10];
    const float* ln2_w     = (const float*)d_in[11];
    const float* ln2_b     = (const float*)d_in[12];
    const float* w1        = (const float*)d_in[13];
    const float* b1        = (const float*)d_in[14];
    const float* w2        = (const float*)d_in[15];
    const float* b2        = (const float*)d_in[16];
    const float* lnf_w     = (const float*)d_in[17];
    const float* lnf_b     = (const float*)d_in[18];
    const float* lm_w      = (const float*)d_in[19];
    float* out = (float*)d_out;

    float *x;
    __half *h, *q, *k, *v, *a, *ff, *wq, *wk, *wv, *wo, *cw1, *cw2, *wlm;
    cudaGetSymbolAddress((void**)&x,  g_x);
    cudaGetSymbolAddress((void**)&h,  g_h);
    cudaGetSymbolAddress((void**)&q,  g_q);
    cudaGetSymbolAddress((void**)&k,  g_k);
    cudaGetSymbolAddress((void**)&v,  g_v);
    cudaGetSymbolAddress((void**)&a,  g_a);
    cudaGetSymbolAddress((void**)&ff, g_ff);
    cudaGetSymbolAddress((void**)&wq, g_wq);
    cudaGetSymbolAddress((void**)&wk, g_wk);
    cudaGetSymbolAddress((void**)&wv, g_wv);
    cudaGetSymbolAddress((void**)&wo, g_wo);
    cudaGetSymbolAddress((void**)&cw1, g_w1);
    cudaGetSymbolAddress((void**)&cw2, g_w2);
    cudaGetSymbolAddress((void**)&wlm, g_wlm);

    cudaFuncSetAttribute((const void*)gemm_f16_k<128, false, false>,
                         cudaFuncAttributeMaxDynamicSharedMemorySize, GEMM_SMEM_128);
    cudaFuncSetAttribute((const void*)gemm_f16_k<128, true, true>,
                         cudaFuncAttributeMaxDynamicSharedMemorySize, GEMM_SMEM_128);
    cudaFuncSetAttribute((const void*)gemm_f16_k<64, false, false>,
                         cudaFuncAttributeMaxDynamicSharedMemorySize, GEMM_SMEM_64);
    cudaFuncSetAttribute((const void*)gemm_f16_qkv_k,
                         cudaFuncAttributeMaxDynamicSharedMemorySize, GEMM_SMEM_128);

    // one-time-per-launch fp16 weight conversion
    {
        const int nqk = NLAYER * HID * HID / 2;
        cvt_half_k<<<(nqk + 255) / 256, 256>>>(qw, wq, nqk);
        cvt_half_k<<<(nqk + 255) / 256, 256>>>(kw, wk, nqk);
        cvt_half_k<<<(nqk + 255) / 256, 256>>>(vw, wv, nqk);
        cvt_half_k<<<(nqk + 255) / 256, 256>>>(ow, wo, nqk);
        const int nff = NLAYER * FFI * HID / 2;
        cvt_half_k<<<(nff + 255) / 256, 256>>>(w1, cw1, nff);
        cvt_half_k<<<(nff + 255) / 256, 256>>>(w2, cw2, nff);
        const int nlm = VOCAB * HID / 2;
        cvt_half_k<<<(nlm + 255) / 256, 256>>>(lm_w, wlm, nlm);
    }

    {
        int n = T_TOK * HID;
        embed_kernel<<<(n + 255) / 256, 256>>>(input_ids, tok_emb, pos_emb, x);
    }

    dim3 gqkv(HID / 128, T_TOK / 128, 3);
    dim3 gproj(HID / 128, T_TOK / 64);
    dim3 gff1(FFI / 128, T_TOK / 128);
    dim3 gff2(HID / 128, T_TOK / 64);
    dim3 gattn(SEQ / 64, NHEAD, BATCH);
    dim3 glm((VOCAB + 127) / 128, T_TOK / 128);

    for (int l = 0; l < NLAYER; l++) {
        const float* l1w = ln1_w + (size_t)l * HID;
        const float* l1b = ln1_b + (size_t)l * HID;
        const __half* qwl = wq + (size_t)l * HID * HID;
        const __half* kwl = wk + (size_t)l * HID * HID;
        const __half* vwl = wv + (size_t)l * HID * HID;
        const __half* owl = wo + (size_t)l * HID * HID;
        const float* obl = ob + (size_t)l * HID;
        const float* l2w = ln2_w + (size_t)l * HID;
        const float* l2b = ln2_b + (size_t)l * HID;
        const __half* w1l = cw1 + (size_t)l * FFI * HID;
        const float* b1l = b1 + (size_t)l * FFI;
        const __half* w2l = cw2 + (size_t)l * HID * FFI;
        const float* b2l = b2 + (size_t)l * HID;

        layernorm_kernel<<<T_TOK, 256>>>(x, l1w, l1b, h);
        gemm_f16_qkv_k<<<gqkv, 256, GEMM_SMEM_128>>>(h, qwl, kwl, vwl, q, k, v, T_TOK, HID, HID);
        flash_attn_f16_kernel<<<gattn, 128>>>(q, k, v, attn_mask, a);
        gemm_f16_k<64, false, false><<<gproj, 256, GEMM_SMEM_64>>>(a, owl, obl, x, (void*)x, T_TOK, HID, HID);

        layernorm_kernel<<<T_TOK, 256>>>(x, l2w, l2b, h);
        gemm_f16_k<128, true, true><<<gff1, 256, GEMM_SMEM_128>>>(h, w1l, b1l, nullptr, (void*)ff, T_TOK, FFI, HID);
        gemm_f16_k<64, false, false><<<gff2, 256, GEMM_SMEM_64>>>(ff, w2l, b2l, x, (void*)x, T_TOK, HID, FFI);
    }

    layernorm_kernel<<<T_TOK, 256>>>(x, lnf_w, lnf_b, h);
    gemm_f16_k<128, false, false><<<glm, 256, GEMM_SMEM_128>>>(h, wlm, nullptr, nullptr, (void*)out, T_TOK, VOCAB, HID);
}

// round 12
// speedup vs baseline: 10.3838x; 1.0954x over previous
#include <cuda_runtime.h>
#include <cuda_fp16.h>
#include <math.h>
#include <stdint.h>

#define T_TOK 2048
#define SEQ   1024
#define BATCH 2
#define HID   768
#define NHEAD 12
#define HDIM  64
#define NLAYER 12
#define FFI   3072
#define VOCAB 50257

// ---------------- scratch (device globals: allocation-free) ----------------
__device__ float  g_x[T_TOK * HID];
__device__ __half g_h[T_TOK * HID];
__device__ __half g_q[T_TOK * HID];
__device__ __half g_k[T_TOK * HID];
__device__ __half g_v[T_TOK * HID];
__device__ __half g_a[T_TOK * HID];
__device__ __half g_ff[T_TOK * FFI];
// fp16 weight copies
__device__ __half g_wq[NLAYER * HID * HID];
__device__ __half g_wk[NLAYER * HID * HID];
__device__ __half g_wv[NLAYER * HID * HID];
__device__ __half g_wo[NLAYER * HID * HID];
__device__ __half g_w1[NLAYER * FFI * HID];
__device__ __half g_w2[NLAYER * HID * FFI];
__device__ __half g_wlm[VOCAB * HID];

// ---------------- helpers ----------------
__device__ __forceinline__ float gelu1(float x) {
    return 0.5f * x * (1.0f + erff(x * 0.70710678118654752f));
}
__device__ __forceinline__ void mma_f16(float d[4], const uint32_t a[4], const uint32_t b[2]) {
    asm volatile(
        "mma.sync.aligned.m16n8k16.row.col.f32.f16.f16.f32 "
        "{%0,%1,%2,%3}, {%4,%5,%6,%7}, {%8,%9}, {%0,%1,%2,%3};\n"
        : "+f"(d[0]), "+f"(d[1]), "+f"(d[2]), "+f"(d[3])
        : "r"(a[0]), "r"(a[1]), "r"(a[2]), "r"(a[3]), "r"(b[0]), "r"(b[1]));
}
__device__ __forceinline__ void ldsm_x4(uint32_t* r, uint32_t addr) {
    asm volatile("ldmatrix.sync.aligned.m8n8.x4.shared.b16 {%0,%1,%2,%3}, [%4];"
        : "=r"(r[0]), "=r"(r[1]), "=r"(r[2]), "=r"(r[3]) : "r"(addr));
}
__device__ __forceinline__ void ldsm_x4_t(uint32_t* r, uint32_t addr) {
    asm volatile("ldmatrix.sync.aligned.m8n8.x4.trans.shared.b16 {%0,%1,%2,%3}, [%4];"
        : "=r"(r[0]), "=r"(r[1]), "=r"(r[2]), "=r"(r[3]) : "r"(addr));
}
__device__ __forceinline__ void cp_async16(uint32_t dst, const void* src, int sz) {
    asm volatile("cp.async.cg.shared.global [%0], [%1], 16, %2;\n"
                 :: "r"(dst), "l"(src), "r"(sz));
}
#define CP_COMMIT() asm volatile("cp.async.commit_group;\n" ::: "memory")
#define CP_WAIT2()  asm volatile("cp.async.wait_group 2;\n" ::: "memory")

// ---------------- embeddings ----------------
__global__ void embed_kernel(const int* __restrict__ ids,
                             const float* __restrict__ tok,
                             const float* __restrict__ pos,
                             float* __restrict__ x) {
    int idx = blockIdx.x * blockDim.x + threadIdx.x;
    if (idx >= T_TOK * HID) return;
    int t = idx / HID;
    int hh = idx - t * HID;
    int s = t % SEQ;
    int id = ids[t];
    x[idx] = tok[(size_t)id * HID + hh] + pos[(size_t)s * HID + hh];
}

// ---------------- fp16 weight copy (4 float4 per thread for MLP) ----------
__global__ void cvt_half_k(const float* __restrict__ in, __half* __restrict__ outp, int n4) {
    const int i0 = blockIdx.x * 1024 + threadIdx.x;
    #pragma unroll
    for (int c = 0; c < 4; c++) {
        const int i = i0 + c * 256;
        if (i < n4) {
            float4 v = reinterpret_cast<const float4*>(in)[i];
            __half2 h0 = __floats2half2_rn(v.x, v.y);
            __half2 h1 = __floats2half2_rn(v.z, v.w);
            uint2 u;
            u.x = *reinterpret_cast<uint32_t*>(&h0);
            u.y = *reinterpret_cast<uint32_t*>(&h1);
            *reinterpret_cast<uint2*>(&outp[(size_t)i * 4]) = u;
        }
    }
}

// ---------------- layernorm: one warp per row, register-resident ----------
__global__ __launch_bounds__(256) void layernorm_kernel(
    const float* __restrict__ x, const float* __restrict__ w,
    const float* __restrict__ b, __half* __restrict__ out)
{
    const int warp = threadIdx.x >> 5;
    const int lane = threadIdx.x & 31;
    const int row  = blockIdx.x * 8 + warp;
    const float* xr = x + (size_t)row * HID;
    __half* orow = out + (size_t)row * HID;

    float4 vv[6];
    #pragma unroll
    for (int i = 0; i < 6; i++)
        vv[i] = *reinterpret_cast<const float4*>(&xr[(i * 32 + lane) * 4]);

    float s = 0.f;
    #pragma unroll
    for (int i = 0; i < 6; i++) s += vv[i].x + vv[i].y + vv[i].z + vv[i].w;
    #pragma unroll
    for (int o = 16; o > 0; o >>= 1) s += __shfl_xor_sync(0xffffffffu, s, o);
    const float mean = s * (1.0f / (float)HID);

    float vs = 0.f;
    #pragma unroll
    for (int i = 0; i < 6; i++) {
        float d0 = vv[i].x - mean, d1 = vv[i].y - mean;
        float d2 = vv[i].z - mean, d3 = vv[i].w - mean;
        vs += d0 * d0 + d1 * d1 + d2 * d2 + d3 * d3;
    }
    #pragma unroll
    for (int o = 16; o > 0; o >>= 1) vs += __shfl_xor_sync(0xffffffffu, vs, o);
    const float inv = rsqrtf(vs * (1.0f / (float)HID) + 1e-5f);

    #pragma unroll
    for (int i = 0; i < 6; i++) {
        const int c = (i * 32 + lane) * 4;
        float4 wv = *reinterpret_cast<const float4*>(&w[c]);
        float4 bv = *reinterpret_cast<const float4*>(&b[c]);
        float y0 = (vv[i].x - mean) * inv * wv.x + bv.x;
        float y1 = (vv[i].y - mean) * inv * wv.y + bv.y;
        float y2 = (vv[i].z - mean) * inv * wv.z + bv.z;
        float y3 = (vv[i].w - mean) * inv * wv.w + bv.w;
        __half2 h0 = __floats2half2_rn(y0, y1);
        __half2 h1 = __floats2half2_rn(y2, y3);
        uint2 u;
        u.x = *reinterpret_cast<uint32_t*>(&h0);
        u.y = *reinterpret_cast<uint32_t*>(&h1);
        *reinterpret_cast<uint2*>(&orow[c]) = u;
    }
}

// ---------------- FP16 mma GEMM, 4-stage cp.async, ldmatrix fragments -----
#define GSTAGES 4
#define HSTR 40

template<int BM, bool GELU, bool OUTHALF>
__device__ __forceinline__ void gemm_f16_dev(
    const __half* __restrict__ A, const __half* __restrict__ W,
    const float* __restrict__ bias, const float* __restrict__ res,
    void* __restrict__ Cv, int M, int N, int K)
{
    extern __shared__ __half smh[];
    constexpr int SH = (BM + 128) * HSTR;
    constexpr int MT = BM / 32;
    constexpr int WMROWS = BM / 2;

    const int tid  = threadIdx.x;
    const int warp = tid >> 5;
    const int lane = tid & 31;
    const int g    = lane >> 2;
    const int tig  = lane & 3;
    const int wm   = warp & 1;
    const int wn   = warp >> 1;

    const int m0 = blockIdx.y * BM;
    const int n0 = blockIdx.x * 128;

    const int brl = tid >> 1;
    const int bk  = (tid & 1) << 4;
    const int bn  = n0 + brl;
    const int bsz = (bn < N) ? 16 : 0;
    const __half* gB = W + (size_t)(bn < N ? bn : 0) * K + bk;
    const uint32_t dB = (uint32_t)__cvta_generic_to_shared(smh + BM * HSTR + brl * HSTR + bk);

    const __half* gA;
    uint32_t dA;
    if constexpr (BM == 128) {
        gA = A + (size_t)(m0 + brl) * K + bk;
        dA = (uint32_t)__cvta_generic_to_shared(smh + brl * HSTR + bk);
    } else {
        const int arl = tid >> 2;
        const int ak  = (tid & 3) << 3;
        gA = A + (size_t)(m0 + arl) * K + ak;
        dA = (uint32_t)__cvta_generic_to_shared(smh + arl * HSTR + ak);
    }
    const uint32_t stageB = SH * 2u;

    // ldmatrix lane mappings
    const int alr = lane & 15;            // A: row within 16
    const int alc = (lane >> 4) * 8;      // A: k-offset 0/8
    const int bnr = (lane & 7) + ((lane >> 4) & 1) * 8;  // B: n row
    const int bkc = ((lane >> 3) & 1) * 8;               // B: k-offset

    float acc[MT][4][4];
    #pragma unroll
    for (int i = 0; i < MT; i++)
        #pragma unroll
        for (int j = 0; j < 4; j++)
            #pragma unroll
            for (int r = 0; r < 4; r++) acc[i][j][r] = 0.f;

    const int NIT = K >> 5;

    #define FILLG(it_) do { \
        const uint32_t _o = ((it_) & 3) * stageB; \
        const int _kb = (it_) << 5; \
        if constexpr (BM == 128) { \
            cp_async16(dA + _o, gA + _kb, 16); \
            cp_async16(dA + _o + 16, gA + _kb + 8, 16); \
        } else { \
            cp_async16(dA + _o, gA + _kb, 16); \
        } \
        cp_async16(dB + _o, gB + _kb, bsz); \
        cp_async16(dB + _o + 16, gB + _kb + 8, bsz); \
    } while (0)

    #pragma unroll
    for (int s = 0; s < GSTAGES - 1; s++) {
        if (s < NIT) FILLG(s);
        CP_COMMIT();
    }
    CP_WAIT2();
    __syncthreads();

    for (int it = 0; it < NIT; it++) {
        const int buf = it & 3;
        const __half* bufA = smh + buf * SH;
        const __half* bufB = bufA + BM * HSTR;

        #pragma unroll
        for (int s = 0; s < 2; s++) {
            uint32_t af[MT][4];
            #pragma unroll
            for (int mt = 0; mt < MT; mt++)
                ldsm_x4(af[mt], (uint32_t)__cvta_generic_to_shared(
                    &bufA[(wm * WMROWS + mt * 16 + alr) * HSTR + s * 16 + alc]));
            uint32_t bf[4][2];
            #pragma unroll
            for (int p = 0; p < 2; p++) {
                uint32_t bq[4];
                ldsm_x4(bq, (uint32_t)__cvta_generic_to_shared(
                    &bufB[(wn * 32 + p * 16 + bnr) * HSTR + s * 16 + bkc]));
                bf[2 * p][0] = bq[0]; bf[2 * p][1] = bq[1];
                bf[2 * p + 1][0] = bq[2]; bf[2 * p + 1][1] = bq[3];
            }
            #pragma unroll
            for (int mt = 0; mt < MT; mt++)
                #pragma unroll
                for (int nt = 0; nt < 4; nt++)
                    mma_f16(acc[mt][nt], af[mt], bf[nt]);
        }

        const int nit = it + GSTAGES - 1;
        if (nit < NIT) FILLG(nit);
        CP_COMMIT();
        CP_WAIT2();
        __syncthreads();
    }
    #undef FILLG

    float* Cf = (float*)Cv;
    __half* Ch = (__half*)Cv;
    const bool n_even = ((N & 1) == 0);
    #pragma unroll
    for (int mt = 0; mt < MT; mt++) {
        const int r0 = m0 + wm * WMROWS + mt * 16 + g;
        #pragma unroll
        for (int nt = 0; nt < 4; nt++) {
            const int c = n0 + wn * 32 + nt * 8 + tig * 2;
            #pragma unroll
            for (int half_ = 0; half_ < 2; half_++) {
                const int m = r0 + half_ * 8;
                float v0 = acc[mt][nt][half_ * 2 + 0];
                float v1 = acc[mt][nt][half_ * 2 + 1];
                if (n_even && (c + 1) < N) {
                    if (bias) { float2 bv = *reinterpret_cast<const float2*>(&bias[c]); v0 += bv.x; v1 += bv.y; }
                    if (res)  { float2 rv = *reinterpret_cast<const float2*>(&res[(size_t)m * N + c]); v0 += rv.x; v1 += rv.y; }
                    if (GELU) { v0 = gelu1(v0); v1 = gelu1(v1); }
                    if (OUTHALF) {
                        *reinterpret_cast<__half2*>(&Ch[(size_t)m * N + c]) = __floats2half2_rn(v0, v1);
                    } else {
                        *reinterpret_cast<float2*>(&Cf[(size_t)m * N + c]) = make_float2(v0, v1);
                    }
                } else {
                    #pragma unroll
                    for (int q2 = 0; q2 < 2; q2++) {
                        const int n = c + q2;
                        if (n < N) {
                            float val = (q2 == 0) ? v0 : v1;
                            if (bias) val += bias[n];
                            if (res)  val += res[(size_t)m * N + n];
                            if (GELU) val = gelu1(val);
                            if (OUTHALF) Ch[(size_t)m * N + n] = __float2half_rn(val);
                            else         Cf[(size_t)m * N + n] = val;
                        }
                    }
                }
            }
        }
    }
}

template<int BM, bool GELU, bool OUTHALF>
__global__ __launch_bounds__(256, 2) void gemm_f16_k(
    const __half* __restrict__ A, const __half* __restrict__ W,
    const float* __restrict__ bias, const float* __restrict__ res,
    void* __restrict__ C, int M, int N, int K)
{
    gemm_f16_dev<BM, GELU, OUTHALF>(A, W, bias, res, C, M, N, K);
}

__global__ __launch_bounds__(256, 2) void gemm_f16_qkv_k(
    const __half* __restrict__ A,
    const __half* __restrict__ w0, const __half* __restrict__ w1, const __half* __restrict__ w2,
    __half* __restrict__ o0, __half* __restrict__ o1, __half* __restrict__ o2,
    int M, int N, int K)
{
    const __half* W = (blockIdx.z == 0) ? w0 : ((blockIdx.z == 1) ? w1 : w2);
    __half* C = (blockIdx.z == 0) ? o0 : ((blockIdx.z == 1) ? o1 : o2);
    gemm_f16_dev<128, false, true>(A, W, nullptr, nullptr, (void*)C, M, N, K);
}

#define GEMM_SMEM_128 (GSTAGES * (128 + 128) * HSTR * 2)
#define GEMM_SMEM_64  (GSTAGES * (64 + 128) * HSTR * 2)

// ---------------- tensor-core flash attention (unchanged from R11) --------
#define ASTR 72

__global__ __launch_bounds__(128) void flash_attn_f16_kernel(
    const __half* __restrict__ q, const __half* __restrict__ k,
    const __half* __restrict__ v, const int* __restrict__ amask,
    __half* __restrict__ out)
{
    __shared__ __half Qs[64 * ASTR];
    __shared__ __half Ks[64 * ASTR];
    __shared__ __half Vs[64 * ASTR];
    __shared__ int msk[64];

    const int qt = gridDim.x - 1 - blockIdx.x;
    const int hh = blockIdx.y;
    const int b  = blockIdx.z;
    const int q0 = qt * 64;
    const int tid = threadIdx.x;
    const int lane = tid & 31;
    const int w = tid >> 5;
    const int tig = lane & 3;
    const int gid = lane >> 2;

    {
        const __half2 s125 = __float2half2_rn(0.125f);
        #pragma unroll
        for (int ch = tid; ch < 512; ch += 128) {
            const int row = ch >> 3, part = ch & 7;
            uint4 u = *reinterpret_cast<const uint4*>(
                q + (size_t)(b * SEQ + q0 + row) * HID + hh * HDIM + part * 8);
            __half2* hp = reinterpret_cast<__half2*>(&u);
            hp[0] = __hmul2(hp[0], s125); hp[1] = __hmul2(hp[1], s125);
            hp[2] = __hmul2(hp[2], s125); hp[3] = __hmul2(hp[3], s125);
            *reinterpret_cast<uint4*>(&Qs[row * ASTR + part * 8]) = u;
        }
    }
    __syncthreads();

    uint32_t qf[4][4];
    {
        const int r = 16 * w + (lane & 15);
        const int c = (lane >> 4) * 8;
        #pragma unroll
        for (int kk = 0; kk < 4; kk++)
            ldsm_x4(qf[kk], (uint32_t)__cvta_generic_to_shared(&Qs[r * ASTR + kk * 16 + c]));
    }

    float o[8][4];
    #pragma unroll
    for (int i = 0; i < 8; i++)
        #pragma unroll
        for (int j = 0; j < 4; j++) o[i][j] = 0.f;
    float mi0 = -1e30f, mi1 = -1e30f, li0 = 0.f, li1 = 0.f;
    const int row0 = q0 + 16 * w + gid;
    const int row1 = row0 + 8;

    for (int kt = 0; kt <= qt; kt++) {
        __syncthreads();
        #pragma unroll
        for (int ch = tid; ch < 512; ch += 128) {
            const int row = ch >> 3, part = ch & 7;
            const size_t go = (size_t)(b * SEQ + kt * 64 + row) * HID + hh * HDIM + part * 8;
            *reinterpret_cast<uint4*>(&Ks[row * ASTR + part * 8]) =
                *reinterpret_cast<const uint4*>(k + go);
            *reinterpret_cast<uint4*>(&Vs[row * ASTR + part * 8]) =
                *reinterpret_cast<const uint4*>(v + go);
        }
        if (tid < 64) msk[tid] = amask[b * SEQ + kt * 64 + tid];
        __syncthreads();

        float s[8][4];
        #pragma unroll
        for (int j = 0; j < 8; j++) {
            s[j][0] = s[j][1] = s[j][2] = s[j][3] = 0.f;
            uint32_t kb[8];
            const uint32_t base = (uint32_t)__cvta_generic_to_shared(
                &Ks[(8 * j + (lane & 7)) * ASTR + (lane >> 3) * 8]);
            ldsm_x4(kb, base);
            ldsm_x4(kb + 4, base + 64);
            mma_f16(s[j], qf[0], kb);
            mma_f16(s[j], qf[1], kb + 2);
            mma_f16(s[j], qf[2], kb + 4);
            mma_f16(s[j], qf[3], kb + 6);
        }

        const bool diag = (kt == qt);
        #pragma unroll
        for (int j = 0; j < 8; j++) {
            const int c0i = kt * 64 + 8 * j + 2 * tig;
            if (msk[8 * j + 2 * tig] == 0)     { s[j][0] = -1e9f; s[j][2] = -1e9f; }
            if (msk[8 * j + 2 * tig + 1] == 0) { s[j][1] = -1e9f; s[j][3] = -1e9f; }
            if (diag) {
                if (c0i > row0)     s[j][0] = -1e9f;
                if (c0i + 1 > row0) s[j][1] = -1e9f;
                if (c0i > row1)     s[j][2] = -1e9f;
                if (c0i + 1 > row1) s[j][3] = -1e9f;
            }
        }

        float m0 = -1e30f, m1 = -1e30f;
        #pragma unroll
        for (int j = 0; j < 8; j++) {
            m0 = fmaxf(m0, fmaxf(s[j][0], s[j][1]));
            m1 = fmaxf(m1, fmaxf(s[j][2], s[j][3]));
        }
        m0 = fmaxf(m0, __shfl_xor_sync(0xffffffffu, m0, 1));
        m0 = fmaxf(m0, __shfl_xor_sync(0xffffffffu, m0, 2));
        m1 = fmaxf(m1, __shfl_xor_sync(0xffffffffu, m1, 1));
        m1 = fmaxf(m1, __shfl_xor_sync(0xffffffffu, m1, 2));
        const float mn0 = fmaxf(mi0, m0);
        const float mn1 = fmaxf(mi1, m1);
        const float sc0 = __expf(mi0 - mn0);
        const float sc1 = __expf(mi1 - mn1);

        uint32_t ph[8][2];
        float ls0 = 0.f, ls1 = 0.f;
        #pragma unroll
        for (int j = 0; j < 8; j++) {
            const float p0 = __expf(s[j][0] - mn0);
            const float p1 = __expf(s[j][1] - mn0);
            const float p2 = __expf(s[j][2] - mn1);
            const float p3 = __expf(s[j][3] - mn1);
            ls0 += p0 + p1; ls1 += p2 + p3;
            __half2 h01 = __floats2half2_rn(p0, p1);
            __half2 h23 = __floats2half2_rn(p2, p3);
            ph[j][0] = *reinterpret_cast<uint32_t*>(&h01);
            ph[j][1] = *reinterpret_cast<uint32_t*>(&h23);
        }
        li0 = li0 * sc0 + ls0;
        li1 = li1 * sc1 + ls1;
        mi0 = mn0; mi1 = mn1;
        #pragma unroll
        for (int dn = 0; dn < 8; dn++) {
            o[dn][0] *= sc0; o[dn][1] *= sc0;
            o[dn][2] *= sc1; o[dn][3] *= sc1;
        }

        #pragma unroll
        for (int kj = 0; kj < 4; kj++) {
            const uint32_t a[4] = {ph[2 * kj][0], ph[2 * kj][1],
                                   ph[2 * kj + 1][0], ph[2 * kj + 1][1]};
            #pragma unroll
            for (int dnp = 0; dnp < 4; dnp++) {
                uint32_t vb[4];
                const uint32_t addr = (uint32_t)__cvta_generic_to_shared(
                    &Vs[(16 * kj + (lane & 7) + ((lane >> 3) & 1) * 8) * ASTR
                        + 16 * dnp + (lane >> 4) * 8]);
                ldsm_x4_t(vb, addr);
                mma_f16(o[2 * dnp], a, vb);
                mma_f16(o[2 * dnp + 1], a, vb + 2);
            }
        }
    }

    li0 += __shfl_xor_sync(0xffffffffu, li0, 1);
    li0 += __shfl_xor_sync(0xffffffffu, li0, 2);
    li1 += __shfl_xor_sync(0xffffffffu, li1, 1);
    li1 += __shfl_xor_sync(0xffffffffu, li1, 2);
    const float inv0 = 1.0f / li0;
    const float inv1 = 1.0f / li1;
    #pragma unroll
    for (int dn = 0; dn < 8; dn++) {
        const int cb = hh * HDIM + 8 * dn + 2 * tig;
        __half2 h0 = __floats2half2_rn(o[dn][0] * inv0, o[dn][1] * inv0);
        __half2 h1 = __floats2half2_rn(o[dn][2] * inv1, o[dn][3] * inv1);
        *reinterpret_cast<__half2*>(&out[(size_t)(b * SEQ + row0) * HID + cb]) = h0;
        *reinterpret_cast<__half2*>(&out[(size_t)(b * SEQ + row1) * HID + cb]) = h1;
    }
}

// ---------------- launcher ----------------
extern "C" void kernel_launch(void* const* d_in, const int* in_sizes, int n_in,
                              void* d_out, int out_size) {
    const int*   input_ids = (const int*)d_in[0];
    const int*   attn_mask = (const int*)d_in[1];
    const float* tok_emb   = (const float*)d_in[2];
    const float* pos_emb   = (const float*)d_in[3];
    const float* ln1_w     = (const float*)d_in[4];
    const float* ln1_b     = (const float*)d_in[5];
    const float* qw        = (const float*)d_in[6];
    const float* kw        = (const float*)d_in[7];
    const float* vw        = (const float*)d_in[8];
    const float* ow        = (const float*)d_in[9];
    const float* ob        = (const float*)d_in[10];
    const float* ln2_w     = (const float*)d_in[11];
    const float* ln2_b     = (const float*)d_in[12];
    const float* w1        = (const float*)d_in[13];
    const float* b1        = (const float*)d_in[14];
    const float* w2        = (const float*)d_in[15];
    const float* b2        = (const float*)d_in[16];
    const float* lnf_w     = (const float*)d_in[17];
    const float* lnf_b     = (const float*)d_in[18];
    const float* lm_w      = (const float*)d_in[19];
    float* out = (float*)d_out;

    float *x;
    __half *h, *q, *k, *v, *a, *ff, *wq, *wk, *wv, *wo, *cw1, *cw2, *wlm;
    cudaGetSymbolAddress((void**)&x,  g_x);
    cudaGetSymbolAddress((void**)&h,  g_h);
    cudaGetSymbolAddress((void**)&q,  g_q);
    cudaGetSymbolAddress((void**)&k,  g_k);
    cudaGetSymbolAddress((void**)&v,  g_v);
    cudaGetSymbolAddress((void**)&a,  g_a);
    cudaGetSymbolAddress((void**)&ff, g_ff);
    cudaGetSymbolAddress((void**)&wq, g_wq);
    cudaGetSymbolAddress((void**)&wk, g_wk);
    cudaGetSymbolAddress((void**)&wv, g_wv);
    cudaGetSymbolAddress((void**)&wo, g_wo);
    cudaGetSymbolAddress((void**)&cw1, g_w1);
    cudaGetSymbolAddress((void**)&cw2, g_w2);
    cudaGetSymbolAddress((void**)&wlm, g_wlm);

    cudaFuncSetAttribute((const void*)gemm_f16_k<128, false, false>,
                         cudaFuncAttributeMaxDynamicSharedMemorySize, GEMM_SMEM_128);
    cudaFuncSetAttribute((const void*)gemm_f16_k<128, true, true>,
                         cudaFuncAttributeMaxDynamicSharedMemorySize, GEMM_SMEM_128);
    cudaFuncSetAttribute((const void*)gemm_f16_k<64, false, false>,
                         cudaFuncAttributeMaxDynamicSharedMemorySize, GEMM_SMEM_64);
    cudaFuncSetAttribute((const void*)gemm_f16_qkv_k,
                         cudaFuncAttributeMaxDynamicSharedMemorySize, GEMM_SMEM_128);

    // one-time-per-launch fp16 weight conversion (4 float4 / thread)
    {
        const int nqk = NLAYER * HID * HID / 4;
        cvt_half_k<<<(nqk + 1023) / 1024, 256>>>(qw, wq, nqk);
        cvt_half_k<<<(nqk + 1023) / 1024, 256>>>(kw, wk, nqk);
        cvt_half_k<<<(nqk + 1023) / 1024, 256>>>(vw, wv, nqk);
        cvt_half_k<<<(nqk + 1023) / 1024, 256>>>(ow, wo, nqk);
        const int nff = NLAYER * FFI * HID / 4;
        cvt_half_k<<<(nff + 1023) / 1024, 256>>>(w1, cw1, nff);
        cvt_half_k<<<(nff + 1023) / 1024, 256>>>(w2, cw2, nff);
        const int nlm = VOCAB * HID / 4;
        cvt_half_k<<<(nlm + 1023) / 1024, 256>>>(lm_w, wlm, nlm);
    }

    {
        int n = T_TOK * HID;
        embed_kernel<<<(n + 255) / 256, 256>>>(input_ids, tok_emb, pos_emb, x);
    }

    dim3 gqkv(HID / 128, T_TOK / 128, 3);
    dim3 gproj(HID / 128, T_TOK / 64);
    dim3 gff1(FFI / 128, T_TOK / 128);
    dim3 gff2(HID / 128, T_TOK / 64);
    dim3 gattn(SEQ / 64, NHEAD, BATCH);
    dim3 glm((VOCAB + 127) / 128, T_TOK / 128);

    for (int l = 0; l < NLAYER; l++) {
        const float* l1w = ln1_w + (size_t)l * HID;
        const float* l1b = ln1_b + (size_t)l * HID;
        const __half* qwl = wq + (size_t)l * HID * HID;
        const __half* kwl = wk + (size_t)l * HID * HID;
        const __half* vwl = wv + (size_t)l * HID * HID;
        const __half* owl = wo + (size_t)l * HID * HID;
        const float* obl = ob + (size_t)l * HID;
        const float* l2w = ln2_w + (size_t)l * HID;
        const float* l2b = ln2_b + (size_t)l * HID;
        const __half* w1l = cw1 + (size_t)l * FFI * HID;
        const float* b1l = b1 + (size_t)l * FFI;
        const __half* w2l = cw2 + (size_t)l * HID * FFI;
        const float* b2l = b2 + (size_t)l * HID;

        layernorm_kernel<<<T_TOK / 8, 256>>>(x, l1w, l1b, h);
        gemm_f16_qkv_k<<<gqkv, 256, GEMM_SMEM_128>>>(h, qwl, kwl, vwl, q, k, v, T_TOK, HID, HID);
        flash_attn_f16_kernel<<<gattn, 128>>>(q, k, v, attn_mask, a);
        gemm_f16_k<64, false, false><<<gproj, 256, GEMM_SMEM_64>>>(a, owl, obl, x, (void*)x, T_TOK, HID, HID);

        layernorm_kernel<<<T_TOK / 8, 256>>>(x, l2w, l2b, h);
        gemm_f16_k<128, true, true><<<gff1, 256, GEMM_SMEM_128>>>(h, w1l, b1l, nullptr, (void*)ff, T_TOK, FFI, HID);
        gemm_f16_k<64, false, false><<<gff2, 256, GEMM_SMEM_64>>>(ff, w2l, b2l, x, (void*)x, T_TOK, HID, FFI);
    }

    layernorm_kernel<<<T_TOK / 8, 256>>>(x, lnf_w, lnf_b, h);
    gemm_f16_k<128, false, false><<<glm, 256, GEMM_SMEM_128>>>(h, wlm, nullptr, nullptr, (void*)out, T_TOK, VOCAB, HID);
}

// round 13
// speedup vs baseline: 10.8808x; 1.0479x over previous
#include <cuda_runtime.h>
#include <cuda_fp16.h>
#include <math.h>
#include <stdint.h>

#define T_TOK 2048
#define SEQ   1024
#define BATCH 2
#define HID   768
#define NHEAD 12
#define HDIM  64
#define NLAYER 12
#define FFI   3072
#define VOCAB 50257

// ---------------- scratch (device globals: allocation-free) ----------------
__device__ float  g_x[T_TOK * HID];
__device__ __half g_h[T_TOK * HID];
__device__ __half g_q[T_TOK * HID];
__device__ __half g_k[T_TOK * HID];
__device__ __half g_v[T_TOK * HID];
__device__ __half g_a[T_TOK * HID];
__device__ __half g_ff[T_TOK * FFI];
// fp16 weight copies
__device__ __half g_wq[NLAYER * HID * HID];
__device__ __half g_wk[NLAYER * HID * HID];
__device__ __half g_wv[NLAYER * HID * HID];
__device__ __half g_wo[NLAYER * HID * HID];
__device__ __half g_w1[NLAYER * FFI * HID];
__device__ __half g_w2[NLAYER * HID * FFI];
__device__ __half g_wlm[VOCAB * HID];

// ---------------- helpers ----------------
__device__ __forceinline__ float gelu1(float x) {
    return 0.5f * x * (1.0f + erff(x * 0.70710678118654752f));
}
__device__ __forceinline__ void mma_f16(float d[4], const uint32_t a[4], const uint32_t b[2]) {
    asm volatile(
        "mma.sync.aligned.m16n8k16.row.col.f32.f16.f16.f32 "
        "{%0,%1,%2,%3}, {%4,%5,%6,%7}, {%8,%9}, {%0,%1,%2,%3};\n"
        : "+f"(d[0]), "+f"(d[1]), "+f"(d[2]), "+f"(d[3])
        : "r"(a[0]), "r"(a[1]), "r"(a[2]), "r"(a[3]), "r"(b[0]), "r"(b[1]));
}
__device__ __forceinline__ void ldsm_x4(uint32_t* r, uint32_t addr) {
    asm volatile("ldmatrix.sync.aligned.m8n8.x4.shared.b16 {%0,%1,%2,%3}, [%4];"
        : "=r"(r[0]), "=r"(r[1]), "=r"(r[2]), "=r"(r[3]) : "r"(addr));
}
__device__ __forceinline__ void ldsm_x4_t(uint32_t* r, uint32_t addr) {
    asm volatile("ldmatrix.sync.aligned.m8n8.x4.trans.shared.b16 {%0,%1,%2,%3}, [%4];"
        : "=r"(r[0]), "=r"(r[1]), "=r"(r[2]), "=r"(r[3]) : "r"(addr));
}
__device__ __forceinline__ void cp_async16(uint32_t dst, const void* src, int sz) {
    asm volatile("cp.async.cg.shared.global [%0], [%1], 16, %2;\n"
                 :: "r"(dst), "l"(src), "r"(sz));
}
#define CP_COMMIT() asm volatile("cp.async.commit_group;\n" ::: "memory")
#define CP_WAIT2()  asm volatile("cp.async.wait_group 2;\n" ::: "memory")

// ---------------- embeddings ----------------
__global__ void embed_kernel(const int* __restrict__ ids,
                             const float* __restrict__ tok,
                             const float* __restrict__ pos,
                             float* __restrict__ x) {
    int idx = blockIdx.x * blockDim.x + threadIdx.x;
    if (idx >= T_TOK * HID) return;
    int t = idx / HID;
    int hh = idx - t * HID;
    int s = t % SEQ;
    int id = ids[t];
    x[idx] = tok[(size_t)id * HID + hh] + pos[(size_t)s * HID + hh];
}

// ---------------- fp16 weight copy (8 floats -> uint4 store) --------------
__global__ void cvt_half_k(const float* __restrict__ in, __half* __restrict__ outp, int n8) {
    const int i0 = blockIdx.x * 1024 + threadIdx.x;
    #pragma unroll
    for (int c = 0; c < 4; c++) {
        const int i = i0 + c * 256;
        if (i < n8) {
            float4 a = reinterpret_cast<const float4*>(in)[2 * i];
            float4 b = reinterpret_cast<const float4*>(in)[2 * i + 1];
            __half2 h0 = __floats2half2_rn(a.x, a.y);
            __half2 h1 = __floats2half2_rn(a.z, a.w);
            __half2 h2 = __floats2half2_rn(b.x, b.y);
            __half2 h3 = __floats2half2_rn(b.z, b.w);
            uint4 u;
            u.x = *reinterpret_cast<uint32_t*>(&h0);
            u.y = *reinterpret_cast<uint32_t*>(&h1);
            u.z = *reinterpret_cast<uint32_t*>(&h2);
            u.w = *reinterpret_cast<uint32_t*>(&h3);
            reinterpret_cast<uint4*>(outp)[i] = u;
        }
    }
}

// ---------------- layernorm: one warp per row, register-resident ----------
__global__ __launch_bounds__(256) void layernorm_kernel(
    const float* __restrict__ x, const float* __restrict__ w,
    const float* __restrict__ b, __half* __restrict__ out)
{
    const int warp = threadIdx.x >> 5;
    const int lane = threadIdx.x & 31;
    const int row  = blockIdx.x * 8 + warp;
    const float* xr = x + (size_t)row * HID;
    __half* orow = out + (size_t)row * HID;

    float4 vv[6];
    #pragma unroll
    for (int i = 0; i < 6; i++)
        vv[i] = *reinterpret_cast<const float4*>(&xr[(i * 32 + lane) * 4]);

    float s = 0.f;
    #pragma unroll
    for (int i = 0; i < 6; i++) s += vv[i].x + vv[i].y + vv[i].z + vv[i].w;
    #pragma unroll
    for (int o = 16; o > 0; o >>= 1) s += __shfl_xor_sync(0xffffffffu, s, o);
    const float mean = s * (1.0f / (float)HID);

    float vs = 0.f;
    #pragma unroll
    for (int i = 0; i < 6; i++) {
        float d0 = vv[i].x - mean, d1 = vv[i].y - mean;
        float d2 = vv[i].z - mean, d3 = vv[i].w - mean;
        vs += d0 * d0 + d1 * d1 + d2 * d2 + d3 * d3;
    }
    #pragma unroll
    for (int o = 16; o > 0; o >>= 1) vs += __shfl_xor_sync(0xffffffffu, vs, o);
    const float inv = rsqrtf(vs * (1.0f / (float)HID) + 1e-5f);

    #pragma unroll
    for (int i = 0; i < 6; i++) {
        const int c = (i * 32 + lane) * 4;
        float4 wv = *reinterpret_cast<const float4*>(&w[c]);
        float4 bv = *reinterpret_cast<const float4*>(&b[c]);
        float y0 = (vv[i].x - mean) * inv * wv.x + bv.x;
        float y1 = (vv[i].y - mean) * inv * wv.y + bv.y;
        float y2 = (vv[i].z - mean) * inv * wv.z + bv.z;
        float y3 = (vv[i].w - mean) * inv * wv.w + bv.w;
        __half2 h0 = __floats2half2_rn(y0, y1);
        __half2 h1 = __floats2half2_rn(y2, y3);
        uint2 u;
        u.x = *reinterpret_cast<uint32_t*>(&h0);
        u.y = *reinterpret_cast<uint32_t*>(&h1);
        *reinterpret_cast<uint2*>(&orow[c]) = u;
    }
}

// ---------------- FP16 mma GEMM, 4-stage cp.async, ldmatrix ---------------
// C[M,N] = A[M,K]*W[N,K]^T (+bias)(+res)(+gelu). BM in {64,128}, BN in {64,128}.
#define GSTAGES 4
#define HSTR 40

template<int BM, int BN, bool GELU, bool OUTHALF>
__device__ __forceinline__ void gemm_f16_dev(
    const __half* __restrict__ A, const __half* __restrict__ W,
    const float* __restrict__ bias, const float* __restrict__ res,
    void* __restrict__ Cv, int M, int N, int K)
{
    extern __shared__ __half smh[];
    constexpr int SH = (BM + BN) * HSTR;
    constexpr int MT = BM / 32;
    constexpr int NT = BN / 32;
    constexpr int WMROWS = BM / 2;
    constexpr int WNCOLS = BN / 4;

    const int tid  = threadIdx.x;
    const int warp = tid >> 5;
    const int lane = tid & 31;
    const int g    = lane >> 2;
    const int tig  = lane & 3;
    const int wm   = warp & 1;
    const int wn   = warp >> 1;

    const int m0 = blockIdx.y * BM;
    const int n0 = blockIdx.x * BN;

    // global->smem mappings
    const __half* gB;
    uint32_t dB;
    int bsz;
    if constexpr (BN == 128) {
        const int brl = tid >> 1;
        const int bk  = (tid & 1) << 4;
        const int bn  = n0 + brl;
        bsz = (bn < N) ? 16 : 0;
        gB = W + (size_t)(bn < N ? bn : 0) * K + bk;
        dB = (uint32_t)__cvta_generic_to_shared(smh + BM * HSTR + brl * HSTR + bk);
    } else {
        const int brl = tid >> 2;
        const int bk  = (tid & 3) << 3;
        const int bn  = n0 + brl;
        bsz = (bn < N) ? 16 : 0;
        gB = W + (size_t)(bn < N ? bn : 0) * K + bk;
        dB = (uint32_t)__cvta_generic_to_shared(smh + BM * HSTR + brl * HSTR + bk);
    }

    const __half* gA;
    uint32_t dA;
    if constexpr (BM == 128) {
        const int arl = tid >> 1;
        const int ak  = (tid & 1) << 4;
        gA = A + (size_t)(m0 + arl) * K + ak;
        dA = (uint32_t)__cvta_generic_to_shared(smh + arl * HSTR + ak);
    } else {
        const int arl = tid >> 2;
        const int ak  = (tid & 3) << 3;
        gA = A + (size_t)(m0 + arl) * K + ak;
        dA = (uint32_t)__cvta_generic_to_shared(smh + arl * HSTR + ak);
    }
    const uint32_t stageB = SH * 2u;

    // ldmatrix lane mappings
    const int alr = lane & 15;
    const int alc = (lane >> 4) * 8;
    const int bnr = (lane & 7) + ((lane >> 4) & 1) * 8;
    const int bkc = ((lane >> 3) & 1) * 8;

    float acc[MT][NT][4];
    #pragma unroll
    for (int i = 0; i < MT; i++)
        #pragma unroll
        for (int j = 0; j < NT; j++)
            #pragma unroll
            for (int r = 0; r < 4; r++) acc[i][j][r] = 0.f;

    const int NIT = K >> 5;

    #define FILLG(it_) do { \
        const uint32_t _o = ((it_) & 3) * stageB; \
        const int _kb = (it_) << 5; \
        if constexpr (BM == 128) { \
            cp_async16(dA + _o, gA + _kb, 16); \
        } else { \
            cp_async16(dA + _o, gA + _kb, 16); \
        } \
        if constexpr (BN == 128) { \
            cp_async16(dB + _o, gB + _kb, bsz); \
        } else { \
            cp_async16(dB + _o, gB + _kb, bsz); \
        } \
    } while (0)

    // NOTE: BM==128 / BN==128 need TWO cp16 per thread (handled below)
    #define FILLG2(it_) do { \
        const uint32_t _o = ((it_) & 3) * stageB; \
        const int _kb = (it_) << 5; \
        cp_async16(dA + _o, gA + _kb, 16); \
        if constexpr (BM == 128) cp_async16(dA + _o + 16, gA + _kb + 8, 16); \
        cp_async16(dB + _o, gB + _kb, bsz); \
        if constexpr (BN == 128) cp_async16(dB + _o + 16, gB + _kb + 8, bsz); \
    } while (0)

    #pragma unroll
    for (int s = 0; s < GSTAGES - 1; s++) {
        if (s < NIT) FILLG2(s);
        CP_COMMIT();
    }
    CP_WAIT2();
    __syncthreads();

    for (int it = 0; it < NIT; it++) {
        const int buf = it & 3;
        const __half* bufA = smh + buf * SH;
        const __half* bufB = bufA + BM * HSTR;

        #pragma unroll
        for (int s = 0; s < 2; s++) {
            uint32_t af[MT][4];
            #pragma unroll
            for (int mt = 0; mt < MT; mt++)
                ldsm_x4(af[mt], (uint32_t)__cvta_generic_to_shared(
                    &bufA[(wm * WMROWS + mt * 16 + alr) * HSTR + s * 16 + alc]));
            uint32_t bf[NT][2];
            #pragma unroll
            for (int p = 0; p < NT / 2; p++) {
                uint32_t bq[4];
                ldsm_x4(bq, (uint32_t)__cvta_generic_to_shared(
                    &bufB[(wn * WNCOLS + p * 16 + bnr) * HSTR + s * 16 + bkc]));
                bf[2 * p][0] = bq[0]; bf[2 * p][1] = bq[1];
                bf[2 * p + 1][0] = bq[2]; bf[2 * p + 1][1] = bq[3];
            }
            #pragma unroll
            for (int mt = 0; mt < MT; mt++)
                #pragma unroll
                for (int nt = 0; nt < NT; nt++)
                    mma_f16(acc[mt][nt], af[mt], bf[nt]);
        }

        const int nit = it + GSTAGES - 1;
        if (nit < NIT) FILLG2(nit);
        CP_COMMIT();
        CP_WAIT2();
        __syncthreads();
    }
    #undef FILLG
    #undef FILLG2

    float* Cf = (float*)Cv;
    __half* Ch = (__half*)Cv;
    const bool n_even = ((N & 1) == 0);
    #pragma unroll
    for (int mt = 0; mt < MT; mt++) {
        const int r0 = m0 + wm * WMROWS + mt * 16 + g;
        #pragma unroll
        for (int nt = 0; nt < NT; nt++) {
            const int c = n0 + wn * WNCOLS + nt * 8 + tig * 2;
            #pragma unroll
            for (int half_ = 0; half_ < 2; half_++) {
                const int m = r0 + half_ * 8;
                float v0 = acc[mt][nt][half_ * 2 + 0];
                float v1 = acc[mt][nt][half_ * 2 + 1];
                if (n_even && (c + 1) < N) {
                    if (bias) { float2 bv = *reinterpret_cast<const float2*>(&bias[c]); v0 += bv.x; v1 += bv.y; }
                    if (res)  { float2 rv = *reinterpret_cast<const float2*>(&res[(size_t)m * N + c]); v0 += rv.x; v1 += rv.y; }
                    if (GELU) { v0 = gelu1(v0); v1 = gelu1(v1); }
                    if (OUTHALF) {
                        *reinterpret_cast<__half2*>(&Ch[(size_t)m * N + c]) = __floats2half2_rn(v0, v1);
                    } else {
                        *reinterpret_cast<float2*>(&Cf[(size_t)m * N + c]) = make_float2(v0, v1);
                    }
                } else {
                    #pragma unroll
                    for (int q2 = 0; q2 < 2; q2++) {
                        const int n = c + q2;
                        if (n < N) {
                            float val = (q2 == 0) ? v0 : v1;
                            if (bias) val += bias[n];
                            if (res)  val += res[(size_t)m * N + n];
                            if (GELU) val = gelu1(val);
                            if (OUTHALF) Ch[(size_t)m * N + n] = __float2half_rn(val);
                            else         Cf[(size_t)m * N + n] = val;
                        }
                    }
                }
            }
        }
    }
}

template<int BM, int BN, bool GELU, bool OUTHALF>
__global__ __launch_bounds__(256, 2) void gemm_f16_k(
    const __half* __restrict__ A, const __half* __restrict__ W,
    const float* __restrict__ bias, const float* __restrict__ res,
    void* __restrict__ C, int M, int N, int K)
{
    gemm_f16_dev<BM, BN, GELU, OUTHALF>(A, W, bias, res, C, M, N, K);
}

__global__ __launch_bounds__(256, 2) void gemm_f16_qkv_k(
    const __half* __restrict__ A,
    const __half* __restrict__ w0, const __half* __restrict__ w1, const __half* __restrict__ w2,
    __half* __restrict__ o0, __half* __restrict__ o1, __half* __restrict__ o2,
    int M, int N, int K)
{
    const __half* W = (blockIdx.z == 0) ? w0 : ((blockIdx.z == 1) ? w1 : w2);
    __half* C = (blockIdx.z == 0) ? o0 : ((blockIdx.z == 1) ? o1 : o2);
    gemm_f16_dev<128, 128, false, true>(A, W, nullptr, nullptr, (void*)C, M, N, K);
}

#define GEMM_SMEM_128 (GSTAGES * (128 + 128) * HSTR * 2)
#define GEMM_SMEM_64  (GSTAGES * (64 + 64) * HSTR * 2)

// ---------------- tensor-core flash attention (unchanged) ----------------
#define ASTR 72

__global__ __launch_bounds__(128) void flash_attn_f16_kernel(
    const __half* __restrict__ q, const __half* __restrict__ k,
    const __half* __restrict__ v, const int* __restrict__ amask,
    __half* __restrict__ out)
{
    __shared__ __half Qs[64 * ASTR];
    __shared__ __half Ks[64 * ASTR];
    __shared__ __half Vs[64 * ASTR];
    __shared__ int msk[64];

    const int qt = gridDim.x - 1 - blockIdx.x;
    const int hh = blockIdx.y;
    const int b  = blockIdx.z;
    const int q0 = qt * 64;
    const int tid = threadIdx.x;
    const int lane = tid & 31;
    const int w = tid >> 5;
    const int tig = lane & 3;
    const int gid = lane >> 2;

    {
        const __half2 s125 = __float2half2_rn(0.125f);
        #pragma unroll
        for (int ch = tid; ch < 512; ch += 128) {
            const int row = ch >> 3, part = ch & 7;
            uint4 u = *reinterpret_cast<const uint4*>(
                q + (size_t)(b * SEQ + q0 + row) * HID + hh * HDIM + part * 8);
            __half2* hp = reinterpret_cast<__half2*>(&u);
            hp[0] = __hmul2(hp[0], s125); hp[1] = __hmul2(hp[1], s125);
            hp[2] = __hmul2(hp[2], s125); hp[3] = __hmul2(hp[3], s125);
            *reinterpret_cast<uint4*>(&Qs[row * ASTR + part * 8]) = u;
        }
    }
    __syncthreads();

    uint32_t qf[4][4];
    {
        const int r = 16 * w + (lane & 15);
        const int c = (lane >> 4) * 8;
        #pragma unroll
        for (int kk = 0; kk < 4; kk++)
            ldsm_x4(qf[kk], (uint32_t)__cvta_generic_to_shared(&Qs[r * ASTR + kk * 16 + c]));
    }

    float o[8][4];
    #pragma unroll
    for (int i = 0; i < 8; i++)
        #pragma unroll
        for (int j = 0; j < 4; j++) o[i][j] = 0.f;
    float mi0 = -1e30f, mi1 = -1e30f, li0 = 0.f, li1 = 0.f;
    const int row0 = q0 + 16 * w + gid;
    const int row1 = row0 + 8;

    for (int kt = 0; kt <= qt; kt++) {
        __syncthreads();
        #pragma unroll
        for (int ch = tid; ch < 512; ch += 128) {
            const int row = ch >> 3, part = ch & 7;
            const size_t go = (size_t)(b * SEQ + kt * 64 + row) * HID + hh * HDIM + part * 8;
            *reinterpret_cast<uint4*>(&Ks[row * ASTR + part * 8]) =
                *reinterpret_cast<const uint4*>(k + go);
            *reinterpret_cast<uint4*>(&Vs[row * ASTR + part * 8]) =
                *reinterpret_cast<const uint4*>(v + go);
        }
        if (tid < 64) msk[tid] = amask[b * SEQ + kt * 64 + tid];
        __syncthreads();

        float s[8][4];
        #pragma unroll
        for (int j = 0; j < 8; j++) {
            s[j][0] = s[j][1] = s[j][2] = s[j][3] = 0.f;
            uint32_t kb[8];
            const uint32_t base = (uint32_t)__cvta_generic_to_shared(
                &Ks[(8 * j + (lane & 7)) * ASTR + (lane >> 3) * 8]);
            ldsm_x4(kb, base);
            ldsm_x4(kb + 4, base + 64);
            mma_f16(s[j], qf[0], kb);
            mma_f16(s[j], qf[1], kb + 2);
            mma_f16(s[j], qf[2], kb + 4);
            mma_f16(s[j], qf[3], kb + 6);
        }

        const bool diag = (kt == qt);
        #pragma unroll
        for (int j = 0; j < 8; j++) {
            const int c0i = kt * 64 + 8 * j + 2 * tig;
            if (msk[8 * j + 2 * tig] == 0)     { s[j][0] = -1e9f; s[j][2] = -1e9f; }
            if (msk[8 * j + 2 * tig + 1] == 0) { s[j][1] = -1e9f; s[j][3] = -1e9f; }
            if (diag) {
                if (c0i > row0)     s[j][0] = -1e9f;
                if (c0i + 1 > row0) s[j][1] = -1e9f;
                if (c0i > row1)     s[j][2] = -1e9f;
                if (c0i + 1 > row1) s[j][3] = -1e9f;
            }
        }

        float m0 = -1e30f, m1 = -1e30f;
        #pragma unroll
        for (int j = 0; j < 8; j++) {
            m0 = fmaxf(m0, fmaxf(s[j][0], s[j][1]));
            m1 = fmaxf(m1, fmaxf(s[j][2], s[j][3]));
        }
        m0 = fmaxf(m0, __shfl_xor_sync(0xffffffffu, m0, 1));
        m0 = fmaxf(m0, __shfl_xor_sync(0xffffffffu, m0, 2));
        m1 = fmaxf(m1, __shfl_xor_sync(0xffffffffu, m1, 1));
        m1 = fmaxf(m1, __shfl_xor_sync(0xffffffffu, m1, 2));
        const float mn0 = fmaxf(mi0, m0);
        const float mn1 = fmaxf(mi1, m1);
        const float sc0 = __expf(mi0 - mn0);
        const float sc1 = __expf(mi1 - mn1);

        uint32_t ph[8][2];
        float ls0 = 0.f, ls1 = 0.f;
        #pragma unroll
        for (int j = 0; j < 8; j++) {
            const float p0 = __expf(s[j][0] - mn0);
            const float p1 = __expf(s[j][1] - mn0);
            const float p2 = __expf(s[j][2] - mn1);
            const float p3 = __expf(s[j][3] - mn1);
            ls0 += p0 + p1; ls1 += p2 + p3;
            __half2 h01 = __floats2half2_rn(p0, p1);
            __half2 h23 = __floats2half2_rn(p2, p3);
            ph[j][0] = *reinterpret_cast<uint32_t*>(&h01);
            ph[j][1] = *reinterpret_cast<uint32_t*>(&h23);
        }
        li0 = li0 * sc0 + ls0;
        li1 = li1 * sc1 + ls1;
        mi0 = mn0; mi1 = mn1;
        #pragma unroll
        for (int dn = 0; dn < 8; dn++) {
            o[dn][0] *= sc0; o[dn][1] *= sc0;
            o[dn][2] *= sc1; o[dn][3] *= sc1;
        }

        #pragma unroll
        for (int kj = 0; kj < 4; kj++) {
            const uint32_t a[4] = {ph[2 * kj][0], ph[2 * kj][1],
                                   ph[2 * kj + 1][0], ph[2 * kj + 1][1]};
            #pragma unroll
            for (int dnp = 0; dnp < 4; dnp++) {
                uint32_t vb[4];
                const uint32_t addr = (uint32_t)__cvta_generic_to_shared(
                    &Vs[(16 * kj + (lane & 7) + ((lane >> 3) & 1) * 8) * ASTR
                        + 16 * dnp + (lane >> 4) * 8]);
                ldsm_x4_t(vb, addr);
                mma_f16(o[2 * dnp], a, vb);
                mma_f16(o[2 * dnp + 1], a, vb + 2);
            }
        }
    }

    li0 += __shfl_xor_sync(0xffffffffu, li0, 1);
    li0 += __shfl_xor_sync(0xffffffffu, li0, 2);
    li1 += __shfl_xor_sync(0xffffffffu, li1, 1);
    li1 += __shfl_xor_sync(0xffffffffu, li1, 2);
    const float inv0 = 1.0f / li0;
    const float inv1 = 1.0f / li1;
    #pragma unroll
    for (int dn = 0; dn < 8; dn++) {
        const int cb = hh * HDIM + 8 * dn + 2 * tig;
        __half2 h0 = __floats2half2_rn(o[dn][0] * inv0, o[dn][1] * inv0);
        __half2 h1 = __floats2half2_rn(o[dn][2] * inv1, o[dn][3] * inv1);
        *reinterpret_cast<__half2*>(&out[(size_t)(b * SEQ + row0) * HID + cb]) = h0;
        *reinterpret_cast<__half2*>(&out[(size_t)(b * SEQ + row1) * HID + cb]) = h1;
    }
}

// ---------------- launcher ----------------
extern "C" void kernel_launch(void* const* d_in, const int* in_sizes, int n_in,
                              void* d_out, int out_size) {
    const int*   input_ids = (const int*)d_in[0];
    const int*   attn_mask = (const int*)d_in[1];
    const float* tok_emb   = (const float*)d_in[2];
    const float* pos_emb   = (const float*)d_in[3];
    const float* ln1_w     = (const float*)d_in[4];
    const float* ln1_b     = (const float*)d_in[5];
    const float* qw        = (const float*)d_in[6];
    const float* kw        = (const float*)d_in[7];
    const float* vw        = (const float*)d_in[8];
    const float* ow        = (const float*)d_in[9];
    const float* ob        = (const float*)d_in[10];
    const float* ln2_w     = (const float*)d_in[11];
    const float* ln2_b     = (const float*)d_in[12];
    const float* w1        = (const float*)d_in[13];
    const float* b1        = (const float*)d_in[14];
    const float* w2        = (const float*)d_in[15];
    const float* b2        = (const float*)d_in[16];
    const float* lnf_w     = (const float*)d_in[17];
    const float* lnf_b     = (const float*)d_in[18];
    const float* lm_w      = (const float*)d_in[19];
    float* out = (float*)d_out;

    float *x;
    __half *h, *q, *k, *v, *a, *ff, *wq, *wk, *wv, *wo, *cw1, *cw2, *wlm;
    cudaGetSymbolAddress((void**)&x,  g_x);
    cudaGetSymbolAddress((void**)&h,  g_h);
    cudaGetSymbolAddress((void**)&q,  g_q);
    cudaGetSymbolAddress((void**)&k,  g_k);
    cudaGetSymbolAddress((void**)&v,  g_v);
    cudaGetSymbolAddress((void**)&a,  g_a);
    cudaGetSymbolAddress((void**)&ff, g_ff);
    cudaGetSymbolAddress((void**)&wq, g_wq);
    cudaGetSymbolAddress((void**)&wk, g_wk);
    cudaGetSymbolAddress((void**)&wv, g_wv);
    cudaGetSymbolAddress((void**)&wo, g_wo);
    cudaGetSymbolAddress((void**)&cw1, g_w1);
    cudaGetSymbolAddress((void**)&cw2, g_w2);
    cudaGetSymbolAddress((void**)&wlm, g_wlm);

    cudaFuncSetAttribute((const void*)gemm_f16_k<128, 128, false, false>,
                         cudaFuncAttributeMaxDynamicSharedMemorySize, GEMM_SMEM_128);
    cudaFuncSetAttribute((const void*)gemm_f16_k<128, 128, true, true>,
                         cudaFuncAttributeMaxDynamicSharedMemorySize, GEMM_SMEM_128);
    cudaFuncSetAttribute((const void*)gemm_f16_k<64, 64, false, false>,
                         cudaFuncAttributeMaxDynamicSharedMemorySize, GEMM_SMEM_64);
    cudaFuncSetAttribute((const void*)gemm_f16_qkv_k,
                         cudaFuncAttributeMaxDynamicSharedMemorySize, GEMM_SMEM_128);

    // one-time-per-launch fp16 weight conversion (8 floats -> uint4 store)
    {
        const int nqk = NLAYER * HID * HID / 8;
        cvt_half_k<<<(nqk + 1023) / 1024, 256>>>(qw, wq, nqk);
        cvt_half_k<<<(nqk + 1023) / 1024, 256>>>(kw, wk, nqk);
        cvt_half_k<<<(nqk + 1023) / 1024, 256>>>(vw, wv, nqk);
        cvt_half_k<<<(nqk + 1023) / 1024, 256>>>(ow, wo, nqk);
        const int nff = NLAYER * FFI * HID / 8;
        cvt_half_k<<<(nff + 1023) / 1024, 256>>>(w1, cw1, nff);
        cvt_half_k<<<(nff + 1023) / 1024, 256>>>(w2, cw2, nff);
        const int nlm = VOCAB * HID / 8;
        cvt_half_k<<<(nlm + 1023) / 1024, 256>>>(lm_w, wlm, nlm);
    }

    {
        int n = T_TOK * HID;
        embed_kernel<<<(n + 255) / 256, 256>>>(input_ids, tok_emb, pos_emb, x);
    }

    dim3 gqkv(HID / 128, T_TOK / 128, 3);   // 288
    dim3 gproj(HID / 64, T_TOK / 64);       // 12 x 32 = 384
    dim3 gff1(FFI / 128, T_TOK / 128);      // 384
    dim3 gff2(HID / 64, T_TOK / 64);        // 384
    dim3 gattn(SEQ / 64, NHEAD, BATCH);
    dim3 glm((VOCAB + 127) / 128, T_TOK / 128);

    for (int l = 0; l < NLAYER; l++) {
        const float* l1w = ln1_w + (size_t)l * HID;
        const float* l1b = ln1_b + (size_t)l * HID;
        const __half* qwl = wq + (size_t)l * HID * HID;
        const __half* kwl = wk + (size_t)l * HID * HID;
        const __half* vwl = wv + (size_t)l * HID * HID;
        const __half* owl = wo + (size_t)l * HID * HID;
        const float* obl = ob + (size_t)l * HID;
        const float* l2w = ln2_w + (size_t)l * HID;
        const float* l2b = ln2_b + (size_t)l * HID;
        const __half* w1l = cw1 + (size_t)l * FFI * HID;
        const float* b1l = b1 + (size_t)l * FFI;
        const __half* w2l = cw2 + (size_t)l * HID * FFI;
        const float* b2l = b2 + (size_t)l * HID;

        layernorm_kernel<<<T_TOK / 8, 256>>>(x, l1w, l1b, h);
        gemm_f16_qkv_k<<<gqkv, 256, GEMM_SMEM_128>>>(h, qwl, kwl, vwl, q, k, v, T_TOK, HID, HID);
        flash_attn_f16_kernel<<<gattn, 128>>>(q, k, v, attn_mask, a);
        gemm_f16_k<64, 64, false, false><<<gproj, 256, GEMM_SMEM_64>>>(a, owl, obl, x, (void*)x, T_TOK, HID, HID);

        layernorm_kernel<<<T_TOK / 8, 256>>>(x, l2w, l2b, h);
        gemm_f16_k<128, 128, true, true><<<gff1, 256, GEMM_SMEM_128>>>(h, w1l, b1l, nullptr, (void*)ff, T_TOK, FFI, HID);
        gemm_f16_k<64, 64, false, false><<<gff2, 256, GEMM_SMEM_64>>>(ff, w2l, b2l, x, (void*)x, T_TOK, HID, FFI);
    }

    layernorm_kernel<<<T_TOK / 8, 256>>>(x, lnf_w, lnf_b, h);
    gemm_f16_k<128, 128, false, false><<<glm, 256, GEMM_SMEM_128>>>(h, wlm, nullptr, nullptr, (void*)out, T_TOK, VOCAB, HID);
}